// round 4
// baseline (speedup 1.0000x reference)
#include <cuda_runtime.h>
#include <cstdint>

#define B_N   65536
#define CTXD  384
#define NPR   5
#define MEMV  10
#define EPSV  1e-8f

typedef unsigned long long ull;

__device__ float g_o_vec[64];
__device__ float g_part[148];
__device__ float g_const_f[192];
__device__ float g_const_r[192];

__device__ __forceinline__ ull pack2(float lo, float hi) {
    ull r; asm("mov.b64 %0,{%1,%2};" : "=l"(r) : "f"(lo), "f"(hi)); return r;
}
__device__ __forceinline__ float2 unpack2(ull v) {
    float2 f; asm("mov.b64 {%0,%1},%2;" : "=f"(f.x), "=f"(f.y) : "l"(v)); return f;
}
__device__ __forceinline__ void fma2(ull& acc, ull a, ull b) {
    asm("fma.rn.f32x2 %0,%1,%2,%0;" : "+l"(acc) : "l"(a), "l"(b));
}
__device__ __forceinline__ float wsum(float v) {
#pragma unroll
    for (int o = 16; o; o >>= 1) v += __shfl_xor_sync(0xffffffffu, v, o);
    return v;
}
__device__ __forceinline__ float sigm(float x) { return 1.0f / (1.0f + __expf(-x)); }

// ---------------- kernel A: batch-constant MHA branch ----------------
__global__ void kA(const float* __restrict__ memory, const float* __restrict__ tw,
                   const float* __restrict__ ipw, const float* __restrict__ ipb,
                   const float* __restrict__ ow, const float* __restrict__ ob) {
    __shared__ float mt[64], vv[64];
    int d = threadIdx.x;  // 64 threads
    float a[MEMV], m = -1e30f, s = 0.f;
#pragma unroll
    for (int i = 0; i < MEMV; i++) { a[i] = tw[i]; m = fmaxf(m, a[i]); }
#pragma unroll
    for (int i = 0; i < MEMV; i++) { a[i] = __expf(a[i] - m); s += a[i]; }
    float inv = 1.f / s, acc = 0.f;
#pragma unroll
    for (int i = 0; i < MEMV; i++) acc += (a[i] * inv) * memory[i * 64 + d];
    mt[d] = acc;
    __syncthreads();
    float v = ipb[128 + d];
    for (int j = 0; j < 64; j++) v += mt[j] * ipw[(128 + d) * 64 + j];
    vv[d] = v;
    __syncthreads();
    float o = ob[d];
    for (int j = 0; j < 64; j++) o += vv[j] * ow[d * 64 + j];
    g_o_vec[d] = o;
}

// ---------------- kernel B: per-row phase 1 ----------------
#define OFF_CTXW2 0          // 32*387 ull
#define OFF_W1P   24768      // 64*67 ull
#define OFF_W2P   33344      // 32*131 ull
#define OFF_ROWU  41728      // 8*576 ull
#define OFF_IDW   50944
#define OFF_PE    51584
#define OFF_CTXB  51904
#define OFF_EB1   51968
#define OFF_EB2   52096
#define OFF_IDB   52160
#define OFF_PREV  52168
#define OFF_WPART 52232
#define SMEM_B_BYTES (52240 * 4)

__global__ __launch_bounds__(256, 1)
void kB(const float* __restrict__ theta, const float* __restrict__ context,
        const float* __restrict__ ctx_w, const float* __restrict__ ctx_b,
        const float* __restrict__ ideal_w, const float* __restrict__ ideal_b,
        const float* __restrict__ prime_embeds,
        const float* __restrict__ emo_w1, const float* __restrict__ emo_b1,
        const float* __restrict__ emo_w2, const float* __restrict__ emo_b2,
        const float* __restrict__ prev_ideal,
        const float* __restrict__ freq_w, const float* __restrict__ freq_b,
        float* __restrict__ out) {
    extern __shared__ float smem[];
    const int tid = threadIdx.x, lane = tid & 31, wrp = tid >> 5;

    ull* ctxw2 = (ull*)(smem + OFF_CTXW2);
    ull* w1p   = (ull*)(smem + OFF_W1P);
    ull* w2p   = (ull*)(smem + OFF_W2P);
    float* s_idw = smem + OFF_IDW;
    float* s_pe  = smem + OFF_PE;
    float* s_ctxb = smem + OFF_CTXB;
    float* s_eb1 = smem + OFF_EB1;
    float* s_eb2 = smem + OFF_EB2;
    float* s_idb = smem + OFF_IDB;
    float* s_prev = smem + OFF_PREV;
    float* s_part = smem + OFF_WPART;

    for (int idx = tid; idx < 32 * CTXD; idx += 256) {
        int o = idx / CTXD, j = idx - o * CTXD;
        ctxw2[o * 387 + j] = pack2(ctx_w[o * CTXD + j], ctx_w[(o + 32) * CTXD + j]);
    }
    for (int idx = tid; idx < 64 * 64; idx += 256) {
        int o = idx >> 6, j = idx & 63;
        w1p[o * 67 + j] = pack2(emo_w1[o * 64 + j], emo_w1[(o + 64) * 64 + j]);
    }
    for (int idx = tid; idx < 32 * 128; idx += 256) {
        int o = idx >> 7, j = idx & 127;
        w2p[o * 131 + j] = pack2(emo_w2[o * 128 + j], emo_w2[(o + 32) * 128 + j]);
    }
    for (int idx = tid; idx < NPR * 128; idx += 256) s_idw[idx] = ideal_w[idx];
    for (int idx = tid; idx < NPR * 64; idx += 256) s_pe[idx] = prime_embeds[idx];
    if (tid < 64) s_ctxb[tid] = ctx_b[tid];
    if (tid < 128) s_eb1[tid] = emo_b1[tid];
    if (tid < 64) s_eb2[tid] = emo_b2[tid];
    if (tid < NPR) s_idb[tid] = ideal_b[tid];
    if (tid < 64) s_prev[tid] = prev_ideal[tid];
    __syncthreads();

    const float fwv = freq_w[0], fbv = freq_b[0];
    ull* rowu = (ull*)(smem + OFF_ROWU) + wrp * 576;
    ull* ctxin = rowu;        // 384
    ull* thb   = rowu + 384;  // 64
    ull* t1b   = rowu + 448;  // 128

    float* out_e  = out + (size_t)3 * B_N * 64;
    float* out_rs = out + (size_t)4 * B_N * 64;
    float* out_om = out_rs + B_N;
    float* out_pw = out_om + B_N;

    float stress_acc = 0.f;

    for (int r = blockIdx.x * 8 + wrp; r < B_N; r += 148 * 8) {
        __syncwarp();
        const float* crow = context + (size_t)r * CTXD;
#pragma unroll
        for (int k = 0; k < 12; k++) {
            float x = crow[lane + 32 * k];
            ctxin[lane + 32 * k] = pack2(x, x);
        }
        const size_t ro = (size_t)r * 64;
        float th_lo = theta[ro + lane], th_hi = theta[ro + lane + 32];
        thb[lane] = pack2(th_lo, th_lo);
        thb[lane + 32] = pack2(th_hi, th_hi);
        __syncwarp();

        // ctx = context @ ctx_w.T + ctx_b
        ull acc = pack2(s_ctxb[lane], s_ctxb[lane + 32]);
        const ull* wr = ctxw2 + lane * 387;
#pragma unroll 8
        for (int j = 0; j < CTXD; j++) fma2(acc, wr[j], ctxin[j]);
        float2 c = unpack2(acc);

        // prime logits + softmax
        float lg[NPR];
#pragma unroll
        for (int p = 0; p < NPR; p++) {
            const float* wp = s_idw + p * 128;
            lg[p] = wp[lane] * th_lo + wp[lane + 32] * th_hi
                  + wp[lane + 64] * c.x + wp[lane + 96] * c.y;
        }
#pragma unroll
        for (int p = 0; p < NPR; p++) lg[p] = wsum(lg[p]) + s_idb[p];
        float mx = lg[0];
#pragma unroll
        for (int p = 1; p < NPR; p++) mx = fmaxf(mx, lg[p]);
        float pw[NPR], ssum = 0.f;
#pragma unroll
        for (int p = 0; p < NPR; p++) { pw[p] = __expf(lg[p] - mx); ssum += pw[p]; }
        float invs = 1.f / ssum;
#pragma unroll
        for (int p = 0; p < NPR; p++) pw[p] *= invs;
        if (lane < NPR) {
            float pwv = (lane == 0) ? pw[0] : (lane == 1) ? pw[1] : (lane == 2) ? pw[2]
                      : (lane == 3) ? pw[3] : pw[4];
            out_pw[(size_t)r * NPR + lane] = pwv;
        }

        // theta_ideal
        float ti_lo = 0.f, ti_hi = 0.f;
#pragma unroll
        for (int p = 0; p < NPR; p++) {
            ti_lo += pw[p] * s_pe[p * 64 + lane];
            ti_hi += pw[p] * s_pe[p * 64 + lane + 32];
        }

        // emotion MLP
        ull a0 = pack2(s_eb1[lane], s_eb1[lane + 64]);
        ull a1 = pack2(s_eb1[lane + 32], s_eb1[lane + 96]);
        const ull* w1a = w1p + lane * 67;
        const ull* w1b = w1p + (lane + 32) * 67;
#pragma unroll 8
        for (int j = 0; j < 64; j++) {
            ull x = thb[j];
            fma2(a0, w1a[j], x);
            fma2(a1, w1b[j], x);
        }
        float2 f0 = unpack2(a0), f1 = unpack2(a1);
        float t0 = tanhf(f0.x), t2 = tanhf(f0.y);
        float t1v = tanhf(f1.x), t3 = tanhf(f1.y);
        t1b[lane] = pack2(t0, t0);
        t1b[lane + 64] = pack2(t2, t2);
        t1b[lane + 32] = pack2(t1v, t1v);
        t1b[lane + 96] = pack2(t3, t3);
        __syncwarp();
        ull a2 = pack2(s_eb2[lane], s_eb2[lane + 32]);
        const ull* w2r = w2p + lane * 131;
#pragma unroll 8
        for (int j = 0; j < 128; j++) fma2(a2, w2r[j], t1b[j]);
        float2 fe = unpack2(a2);
        out_e[ro + lane] = fmaxf(fe.x, 0.f);
        out_e[ro + lane + 32] = fmaxf(fe.y, 0.f);

        // stress / resonance / omega
        float d0 = th_lo - ti_lo, d1 = th_hi - ti_hi;
        stress_acc += wsum(d0 * d0 + d1 * d1);
        float nth = wsum(th_lo * th_lo + th_hi * th_hi);
        float nti = wsum(ti_lo * ti_lo + ti_hi * ti_hi);
        float rdot = wsum(th_lo * ti_lo + th_hi * ti_hi);
        float p0 = ti_lo - s_prev[lane], p1 = ti_hi - s_prev[lane + 32];
        float f2s = wsum(p0 * p0 + p1 * p1);
        if (lane == 0) {
            float inv_t = 1.f / (sqrtf(nth) + EPSV);
            float inv_i = 1.f / (sqrtf(nti) + EPSV);
            float ntn = sqrtf(nth) * inv_t, ntin = sqrtf(nti) * inv_i;
            out_rs[r] = (rdot * inv_t * inv_i) / fmaxf(ntn * ntin, EPSV);
            float fr = sqrtf(f2s);
            out_om[r] = tanhf(fr * fwv + fbv) * (1.0f + 0.1f * __sinf(fr));
        }
    }
    if (lane == 0) s_part[wrp] = stress_acc;
    __syncthreads();
    if (tid == 0) {
        float s = 0.f;
        for (int w = 0; w < 8; w++) s += s_part[w];
        g_part[blockIdx.x] = s;
    }
}

// ---------------- kernel C: fold GRU batch-constant terms ----------------
__global__ void kC(const float* __restrict__ w_ih_f, const float* __restrict__ b_ih_f,
                   const float* __restrict__ w_ih_r, const float* __restrict__ b_ih_r) {
    __shared__ float ss;
    int i = threadIdx.x;  // 192 threads
    if (i == 0) {
        float s = 0.f;
        for (int b = 0; b < 148; b++) s += g_part[b];
        ss = s;
    }
    __syncthreads();
    float sc = 0.001f * ss;
    float af = b_ih_f[i], ar = b_ih_r[i], rf = 0.f, rr = 0.f;
    for (int j = 0; j < 64; j++) {
        float ov = g_o_vec[j];
        af += w_ih_f[i * 130 + j] * ov;
        ar += w_ih_r[i * 130 + j] * ov;
        rf += w_ih_f[i * 130 + 64 + j];
        rr += w_ih_r[i * 130 + 64 + j];
    }
    g_const_f[i] = af + sc * rf;
    g_const_r[i] = ar + sc * rr;
}

// ---------------- kernel D: one GRU direction ----------------
#define D_WEP  0          // 96*67 ull
#define D_WHP  12864      // 96*67 ull
#define D_RES  25728
#define D_OM   25920
#define D_CST  26112
#define D_BHH  26304
#define D_ROW  26496      // 8*128 ull
#define SMEM_D_BYTES (28544 * 4)

__global__ __launch_bounds__(256, 1)
void kD(int dir,
        const float* __restrict__ w_ih, const float* __restrict__ w_hh,
        const float* __restrict__ b_hh, const float* __restrict__ h_prev,
        const float* __restrict__ theta, float* __restrict__ out) {
    extern __shared__ float smem[];
    const int tid = threadIdx.x, lane = tid & 31, wrp = tid >> 5;

    ull* wep = (ull*)(smem + D_WEP);
    ull* whp = (ull*)(smem + D_WHP);
    float* swres = smem + D_RES;
    float* swom  = smem + D_OM;
    float* scst  = smem + D_CST;
    float* sbhh  = smem + D_BHH;

    const float* cv = dir ? g_const_r : g_const_f;
    for (int idx = tid; idx < 96 * 64; idx += 256) {
        int pr = idx >> 6, j = idx & 63;
        int g = pr >> 5, l = pr & 31;
        int row = g * 64 + l;
        wep[pr * 67 + j] = pack2(w_ih[row * 130 + 64 + j], w_ih[(row + 32) * 130 + 64 + j]);
        whp[pr * 67 + j] = pack2(w_hh[row * 64 + j], w_hh[(row + 32) * 64 + j]);
    }
    for (int i = tid; i < 192; i += 256) {
        swres[i] = w_ih[i * 130 + 128];
        swom[i]  = w_ih[i * 130 + 129];
        scst[i]  = cv[i];
        sbhh[i]  = b_hh[i];
    }
    __syncthreads();

    float stress_c;
    {
        float s = 0.f;
        for (int b = 0; b < 148; b++) s += g_part[b];
        stress_c = 0.001f * s;
    }

    const float* hp = h_prev + (size_t)dir * B_N * 64;
    float* out_theta = out;
    float* out_h = out + (size_t)(1 + dir) * B_N * 64;
    float* out_e = out + (size_t)3 * B_N * 64;
    const float* out_rs = out + (size_t)4 * B_N * 64;
    const float* out_om = out_rs + B_N;

    ull* rowx = (ull*)(smem + D_ROW) + wrp * 128;
    ull* ex = rowx;       // 64
    ull* hx = rowx + 64;  // 64

    for (int r = blockIdx.x * 8 + wrp; r < B_N; r += 148 * 8) {
        __syncwarp();
        const size_t ro = (size_t)r * 64;
        float e_lo = out_e[ro + lane], e_hi = out_e[ro + lane + 32];
        float h_lo = hp[ro + lane],    h_hi = hp[ro + lane + 32];
        ex[lane] = pack2(e_lo, e_lo);
        ex[lane + 32] = pack2(e_hi, e_hi);
        hx[lane] = pack2(h_lo, h_lo);
        hx[lane + 32] = pack2(h_hi, h_hi);
        float res = out_rs[r], om = out_om[r];
        __syncwarp();

        float2 ge[3], gh[3];
#pragma unroll
        for (int g = 0; g < 3; g++) {
            int i0 = g * 64 + lane;
            ull ae = pack2(scst[i0] + res * swres[i0] + om * swom[i0],
                           scst[i0 + 32] + res * swres[i0 + 32] + om * swom[i0 + 32]);
            ull ah = pack2(sbhh[i0], sbhh[i0 + 32]);
            const ull* we = wep + (g * 32 + lane) * 67;
            const ull* wh = whp + (g * 32 + lane) * 67;
#pragma unroll 8
            for (int j = 0; j < 64; j++) {
                fma2(ae, we[j], ex[j]);
                fma2(ah, wh[j], hx[j]);
            }
            ge[g] = unpack2(ae);
            gh[g] = unpack2(ah);
        }
        float r0 = sigm(ge[0].x + gh[0].x), r1 = sigm(ge[0].y + gh[0].y);
        float z0 = sigm(ge[1].x + gh[1].x), z1 = sigm(ge[1].y + gh[1].y);
        float n0 = tanhf(ge[2].x + r0 * gh[2].x), n1 = tanhf(ge[2].y + r1 * gh[2].y);
        float hn0 = (1.f - z0) * n0 + z0 * h_lo;
        float hn1 = (1.f - z1) * n1 + z1 * h_hi;
        out_h[ro + lane] = hn0;
        out_h[ro + lane + 32] = hn1;
        if (dir == 0) {
            out_theta[ro + lane] = 0.3f * theta[ro + lane] + 0.7f * hn0;
            out_theta[ro + lane + 32] = 0.3f * theta[ro + lane + 32] + 0.7f * hn1;
            out_e[ro + lane] = e_lo + stress_c;
            out_e[ro + lane + 32] = e_hi + stress_c;
        }
    }
}

extern "C" void kernel_launch(void* const* d_in, const int* in_sizes, int n_in,
                              void* d_out, int out_size) {
    const float* theta    = (const float*)d_in[0];
    const float* context  = (const float*)d_in[1];
    const float* h_prev   = (const float*)d_in[2];
    const float* memory   = (const float*)d_in[3];
    const float* tw       = (const float*)d_in[4];
    const float* ipw      = (const float*)d_in[5];
    const float* ipb      = (const float*)d_in[6];
    const float* ow       = (const float*)d_in[7];
    const float* ob       = (const float*)d_in[8];
    const float* emo_w1   = (const float*)d_in[9];
    const float* emo_b1   = (const float*)d_in[10];
    const float* emo_w2   = (const float*)d_in[11];
    const float* emo_b2   = (const float*)d_in[12];
    const float* pe       = (const float*)d_in[13];
    const float* ctx_w    = (const float*)d_in[14];
    const float* ctx_b    = (const float*)d_in[15];
    const float* ideal_w  = (const float*)d_in[16];
    const float* ideal_b  = (const float*)d_in[17];
    const float* wih_f    = (const float*)d_in[18];
    const float* whh_f    = (const float*)d_in[19];
    const float* bih_f    = (const float*)d_in[20];
    const float* bhh_f    = (const float*)d_in[21];
    const float* wih_r    = (const float*)d_in[22];
    const float* whh_r    = (const float*)d_in[23];
    const float* bih_r    = (const float*)d_in[24];
    const float* bhh_r    = (const float*)d_in[25];
    const float* freq_w   = (const float*)d_in[26];
    const float* freq_b   = (const float*)d_in[27];
    const float* prev_i   = (const float*)d_in[28];
    float* out = (float*)d_out;

    static bool attr_set = false;
    if (!attr_set) {
        cudaFuncSetAttribute(kB, cudaFuncAttributeMaxDynamicSharedMemorySize, SMEM_B_BYTES);
        cudaFuncSetAttribute(kD, cudaFuncAttributeMaxDynamicSharedMemorySize, SMEM_D_BYTES);
        attr_set = true;
    }

    kA<<<1, 64>>>(memory, tw, ipw, ipb, ow, ob);
    kB<<<148, 256, SMEM_B_BYTES>>>(theta, context, ctx_w, ctx_b, ideal_w, ideal_b,
                                   pe, emo_w1, emo_b1, emo_w2, emo_b2,
                                   prev_i, freq_w, freq_b, out);
    kC<<<1, 192>>>(wih_f, bih_f, wih_r, bih_r);
    kD<<<148, 256, SMEM_D_BYTES>>>(1, wih_r, whh_r, bhh_r, h_prev, theta, out);
    kD<<<148, 256, SMEM_D_BYTES>>>(0, wih_f, whh_f, bhh_f, h_prev, theta, out);
}

// round 5
// speedup vs baseline: 1.1803x; 1.1803x over previous
#include <cuda_runtime.h>
#include <cstdint>

#define B_N   65536
#define CTXD  384
#define NPR   5
#define MEMV  10
#define EPSV  1e-8f
#define GRD   128

typedef unsigned long long ull;

__device__ float g_o_vec[64];
__device__ float g_part[GRD];
__device__ float g_const_f[192];
__device__ float g_const_r[192];

__device__ __forceinline__ ull pack2(float lo, float hi) {
    ull r; asm("mov.b64 %0,{%1,%2};" : "=l"(r) : "f"(lo), "f"(hi)); return r;
}
__device__ __forceinline__ float2 unpack2(ull v) {
    float2 f; asm("mov.b64 {%0,%1},%2;" : "=f"(f.x), "=f"(f.y) : "l"(v)); return f;
}
__device__ __forceinline__ void fma2(ull& acc, ull a, ull b) {
    asm("fma.rn.f32x2 %0,%1,%2,%0;" : "+l"(acc) : "l"(a), "l"(b));
}
__device__ __forceinline__ float hadd2(ull v) { float2 f = unpack2(v); return f.x + f.y; }
__device__ __forceinline__ float wsum(float v) {
#pragma unroll
    for (int o = 16; o; o >>= 1) v += __shfl_xor_sync(0xffffffffu, v, o);
    return v;
}
__device__ __forceinline__ float sigm(float x) { return 1.0f / (1.0f + __expf(-x)); }
__device__ __forceinline__ float ftanh(float x) {
    return 1.0f - 2.0f / (1.0f + __expf(2.0f * x));
}

// ---------------- kernel A: batch-constant MHA branch ----------------
__global__ void kA(const float* __restrict__ memory, const float* __restrict__ tw,
                   const float* __restrict__ ipw, const float* __restrict__ ipb,
                   const float* __restrict__ ow, const float* __restrict__ ob) {
    __shared__ float mt[64], vv[64];
    int d = threadIdx.x;  // 64 threads
    float a[MEMV], m = -1e30f, s = 0.f;
#pragma unroll
    for (int i = 0; i < MEMV; i++) { a[i] = tw[i]; m = fmaxf(m, a[i]); }
#pragma unroll
    for (int i = 0; i < MEMV; i++) { a[i] = __expf(a[i] - m); s += a[i]; }
    float inv = 1.f / s, acc = 0.f;
#pragma unroll
    for (int i = 0; i < MEMV; i++) acc += (a[i] * inv) * memory[i * 64 + d];
    mt[d] = acc;
    __syncthreads();
    float v = ipb[128 + d];
    for (int j = 0; j < 64; j++) v += mt[j] * ipw[(128 + d) * 64 + j];
    vv[d] = v;
    __syncthreads();
    float o = ob[d];
    for (int j = 0; j < 64; j++) o += vv[j] * ow[d * 64 + j];
    g_o_vec[d] = o;
}

// ---------------- kernel B: per-row phase 1 (lane = batch row) ----------------
// smem float offsets
#define B_WCTX  0        // 12288 ull
#define B_W1P   24576    // 4096 ull
#define B_W2P   32768    // 4096 ull
#define B_IDWT  40960    // 160 ull
#define B_IDWC  41280    // 160 ull
#define B_PE    41600    // 320 f
#define B_PREV  41920    // 64
#define B_B1    41984    // 128
#define B_B2    42112    // 64
#define B_CTXB  42176    // 64
#define B_IDB   42240    // 8
#define B_SPART 42248    // 8
#define SMEM_B_BYTES (42256 * 4)

__global__ __launch_bounds__(256, 1)
void kB(const float* __restrict__ theta, const float* __restrict__ context,
        const float* __restrict__ ctx_w, const float* __restrict__ ctx_b,
        const float* __restrict__ ideal_w, const float* __restrict__ ideal_b,
        const float* __restrict__ prime_embeds,
        const float* __restrict__ emo_w1, const float* __restrict__ emo_b1,
        const float* __restrict__ emo_w2, const float* __restrict__ emo_b2,
        const float* __restrict__ prev_ideal,
        const float* __restrict__ freq_w, const float* __restrict__ freq_b,
        float* __restrict__ out) {
    extern __shared__ float smem[];
    const int tid = threadIdx.x, lane = tid & 31, wrp = tid >> 5;

    ull* wctx = (ull*)(smem + B_WCTX);
    ull* w1p  = (ull*)(smem + B_W1P);
    ull* w2p  = (ull*)(smem + B_W2P);
    ull* idwt = (ull*)(smem + B_IDWT);
    ull* idwc = (ull*)(smem + B_IDWC);
    float* s_pe   = smem + B_PE;
    float* s_prev = smem + B_PREV;
    float* s_b1   = smem + B_B1;
    float* s_b2   = smem + B_B2;
    float* s_ctxb = smem + B_CTXB;
    float* s_idb  = smem + B_IDB;
    float* s_part = smem + B_SPART;

    // ---- cooperative weight fill (all packed along K as (j, j+half)) ----
    for (int idx = tid; idx < 64 * 192; idx += 256) {
        int d = idx / 192, t = idx - d * 192;   // t = ck*32 + j
        int ck = t >> 5, j = t & 31;
        wctx[idx] = pack2(ctx_w[d * 384 + ck * 64 + j], ctx_w[d * 384 + ck * 64 + j + 32]);
    }
    for (int idx = tid; idx < 128 * 32; idx += 256) {
        int o = idx >> 5, j = idx & 31;
        w1p[idx] = pack2(emo_w1[o * 64 + j], emo_w1[o * 64 + j + 32]);
    }
    for (int idx = tid; idx < 64 * 64; idx += 256) {
        int d = idx >> 6, t = idx & 63;         // t = q*16 + j
        int q = t >> 4, j = t & 15;
        w2p[idx] = pack2(emo_w2[d * 128 + q * 32 + j], emo_w2[d * 128 + q * 32 + j + 16]);
    }
    for (int idx = tid; idx < 5 * 32; idx += 256) {
        int p = idx >> 5, j = idx & 31;
        idwt[idx] = pack2(ideal_w[p * 128 + j], ideal_w[p * 128 + j + 32]);
        idwc[idx] = pack2(ideal_w[p * 128 + 64 + j], ideal_w[p * 128 + 96 + j]);
    }
    for (int idx = tid; idx < NPR * 64; idx += 256) s_pe[idx] = prime_embeds[idx];
    if (tid < 64) s_prev[tid] = prev_ideal[tid];
    if (tid < 128) s_b1[tid] = emo_b1[tid];
    if (tid < 64) s_b2[tid] = emo_b2[tid];
    if (tid < 64) s_ctxb[tid] = ctx_b[tid];
    if (tid < NPR) s_idb[tid] = ideal_b[tid];
    __syncthreads();

    const float fwv = freq_w[0], fbv = freq_b[0];
    float* out_e  = out + (size_t)3 * B_N * 64;
    float* out_rs = out + (size_t)4 * B_N * 64;
    float* out_om = out_rs + B_N;
    float* out_pw = out_om + B_N;

    float stress_acc = 0.f;

    for (int it = 0; it < 2; it++) {
        const int r = ((blockIdx.x * 16) + wrp * 2 + it) * 32 + lane;
        const size_t ro = (size_t)r * 64;

        // ================= ctx = context @ ctx_w.T + ctx_b =================
        float c_arr[64];
#pragma unroll
        for (int d = 0; d < 64; d++) c_arr[d] = s_ctxb[d];
        const float4* cp = (const float4*)(context + (size_t)r * CTXD);
#pragma unroll 1
        for (int ck = 0; ck < 6; ck++) {
            ull x_p[32];
#pragma unroll
            for (int k = 0; k < 8; k++) {
                float4 a = cp[ck * 16 + k], b = cp[ck * 16 + k + 8];
                x_p[k * 4 + 0] = pack2(a.x, b.x);
                x_p[k * 4 + 1] = pack2(a.y, b.y);
                x_p[k * 4 + 2] = pack2(a.z, b.z);
                x_p[k * 4 + 3] = pack2(a.w, b.w);
            }
            const ull* w = wctx + ck * 32;
#pragma unroll
            for (int d = 0; d < 64; d += 4) {
                ull a0 = 0, a1 = 0, a2 = 0, a3 = 0;
#pragma unroll
                for (int j = 0; j < 32; j++) {
                    ull x = x_p[j];
                    fma2(a0, w[(d + 0) * 192 + j], x);
                    fma2(a1, w[(d + 1) * 192 + j], x);
                    fma2(a2, w[(d + 2) * 192 + j], x);
                    fma2(a3, w[(d + 3) * 192 + j], x);
                }
                c_arr[d + 0] += hadd2(a0);
                c_arr[d + 1] += hadd2(a1);
                c_arr[d + 2] += hadd2(a2);
                c_arr[d + 3] += hadd2(a3);
            }
        }
        ull c_p[32];
#pragma unroll
        for (int j = 0; j < 32; j++) c_p[j] = pack2(c_arr[j], c_arr[j + 32]);

        // ================= load theta row (packed (j, j+32)) =================
        ull th_p[32];
        {
            const float4* tp = (const float4*)(theta + ro);
#pragma unroll
            for (int k = 0; k < 8; k++) {
                float4 a = tp[k], b = tp[k + 8];
                th_p[k * 4 + 0] = pack2(a.x, b.x);
                th_p[k * 4 + 1] = pack2(a.y, b.y);
                th_p[k * 4 + 2] = pack2(a.z, b.z);
                th_p[k * 4 + 3] = pack2(a.w, b.w);
            }
        }

        // ================= prime logits + softmax =================
        float pw[NPR];
        {
            float lg[NPR];
#pragma unroll
            for (int p = 0; p < NPR; p++) {
                ull a = 0, b = 0;
#pragma unroll
                for (int j = 0; j < 32; j++) {
                    fma2(a, idwt[p * 32 + j], th_p[j]);
                    fma2(b, idwc[p * 32 + j], c_p[j]);
                }
                lg[p] = hadd2(a) + hadd2(b) + s_idb[p];
            }
            float mx = lg[0];
#pragma unroll
            for (int p = 1; p < NPR; p++) mx = fmaxf(mx, lg[p]);
            float ssum = 0.f;
#pragma unroll
            for (int p = 0; p < NPR; p++) { pw[p] = __expf(lg[p] - mx); ssum += pw[p]; }
            float invs = 1.f / ssum;
#pragma unroll
            for (int p = 0; p < NPR; p++) {
                pw[p] *= invs;
                out_pw[(size_t)r * NPR + p] = pw[p];
            }
        }

        // ================= theta_ideal scalars: stress/res/omega =================
        {
            float str = 0.f, nth = 0.f, nti = 0.f, rdot = 0.f, f2 = 0.f;
#pragma unroll
            for (int j = 0; j < 32; j++) {
                float2 t = unpack2(th_p[j]);
                float ti0 = 0.f, ti1 = 0.f;
#pragma unroll
                for (int p = 0; p < NPR; p++) {
                    ti0 += pw[p] * s_pe[p * 64 + j];
                    ti1 += pw[p] * s_pe[p * 64 + j + 32];
                }
                float d0 = t.x - ti0, d1 = t.y - ti1;
                str += d0 * d0 + d1 * d1;
                nth += t.x * t.x + t.y * t.y;
                nti += ti0 * ti0 + ti1 * ti1;
                rdot += t.x * ti0 + t.y * ti1;
                float p0 = ti0 - s_prev[j], p1 = ti1 - s_prev[j + 32];
                f2 += p0 * p0 + p1 * p1;
            }
            stress_acc += str;
            float inv_t = 1.f / (sqrtf(nth) + EPSV);
            float inv_i = 1.f / (sqrtf(nti) + EPSV);
            float ntn = sqrtf(nth) * inv_t, ntin = sqrtf(nti) * inv_i;
            out_rs[r] = (rdot * inv_t * inv_i) / fmaxf(ntn * ntin, EPSV);
            float fr = sqrtf(f2);
            out_om[r] = ftanh(fr * fwv + fbv) * (1.0f + 0.1f * __sinf(fr));
        }

        // ================= emotion MLP =================
        {
            float e_acc[64];
#pragma unroll
            for (int d = 0; d < 64; d++) e_acc[d] = s_b2[d];
#pragma unroll 1
            for (int q = 0; q < 4; q++) {
                ull t1q[16];
#pragma unroll
                for (int j2 = 0; j2 < 16; j2++) {
                    int o0 = q * 32 + j2, o1 = o0 + 16;
                    ull a = 0, b = 0;
#pragma unroll
                    for (int j = 0; j < 32; j++) {
                        ull t = th_p[j];
                        fma2(a, w1p[o0 * 32 + j], t);
                        fma2(b, w1p[o1 * 32 + j], t);
                    }
                    t1q[j2] = pack2(ftanh(hadd2(a) + s_b1[o0]),
                                    ftanh(hadd2(b) + s_b1[o1]));
                }
#pragma unroll
                for (int d = 0; d < 64; d += 4) {
                    ull a0 = 0, a1 = 0, a2 = 0, a3 = 0;
#pragma unroll
                    for (int j = 0; j < 16; j++) {
                        ull t = t1q[j];
                        fma2(a0, w2p[(d + 0) * 64 + q * 16 + j], t);
                        fma2(a1, w2p[(d + 1) * 64 + q * 16 + j], t);
                        fma2(a2, w2p[(d + 2) * 64 + q * 16 + j], t);
                        fma2(a3, w2p[(d + 3) * 64 + q * 16 + j], t);
                    }
                    e_acc[d + 0] += hadd2(a0);
                    e_acc[d + 1] += hadd2(a1);
                    e_acc[d + 2] += hadd2(a2);
                    e_acc[d + 3] += hadd2(a3);
                }
            }
            float4* ep = (float4*)(out_e + ro);
#pragma unroll
            for (int k = 0; k < 16; k++) {
                ep[k] = make_float4(fmaxf(e_acc[k * 4 + 0], 0.f),
                                    fmaxf(e_acc[k * 4 + 1], 0.f),
                                    fmaxf(e_acc[k * 4 + 2], 0.f),
                                    fmaxf(e_acc[k * 4 + 3], 0.f));
            }
        }
    }

    // deterministic stress reduction: lane-sum -> warp -> block -> g_part
    float ws = wsum(stress_acc);
    if (lane == 0) s_part[wrp] = ws;
    __syncthreads();
    if (tid == 0) {
        float s = 0.f;
        for (int w = 0; w < 8; w++) s += s_part[w];
        g_part[blockIdx.x] = s;
    }
}

// ---------------- kernel C: fold GRU batch-constant terms ----------------
__global__ void kC(const float* __restrict__ w_ih_f, const float* __restrict__ b_ih_f,
                   const float* __restrict__ w_ih_r, const float* __restrict__ b_ih_r) {
    __shared__ float ss;
    int i = threadIdx.x;  // 192 threads
    if (i == 0) {
        float s = 0.f;
        for (int b = 0; b < GRD; b++) s += g_part[b];
        ss = s;
    }
    __syncthreads();
    float sc = 0.001f * ss;
    float af = b_ih_f[i], ar = b_ih_r[i], rf = 0.f, rr = 0.f;
    for (int j = 0; j < 64; j++) {
        float ov = g_o_vec[j];
        af += w_ih_f[i * 130 + j] * ov;
        ar += w_ih_r[i * 130 + j] * ov;
        rf += w_ih_f[i * 130 + 64 + j];
        rr += w_ih_r[i * 130 + 64 + j];
    }
    g_const_f[i] = af + sc * rf;
    g_const_r[i] = ar + sc * rr;
}

// ---------------- kernel D: both GRU directions (lane = batch row) ----------------
#define D_WE   0        // 2*192*32 ull = 12288 ull
#define D_WH   24576    // 12288 ull
#define D_CST  49152    // 384
#define D_RES  49536    // 384
#define D_OM   49920    // 384
#define D_BHH  50304    // 384
#define D_STC  50688    // 1
#define SMEM_D_BYTES (50692 * 4)

__global__ __launch_bounds__(256, 1)
void kD(const float* __restrict__ wih_f, const float* __restrict__ whh_f,
        const float* __restrict__ bhh_f,
        const float* __restrict__ wih_r, const float* __restrict__ whh_r,
        const float* __restrict__ bhh_r,
        const float* __restrict__ h_prev, const float* __restrict__ theta,
        float* __restrict__ out) {
    extern __shared__ float smem[];
    const int tid = threadIdx.x, lane = tid & 31, wrp = tid >> 5;

    ull* wE = (ull*)(smem + D_WE);
    ull* wH = (ull*)(smem + D_WH);
    float* scst = smem + D_CST;
    float* sres = smem + D_RES;
    float* som  = smem + D_OM;
    float* sbhh = smem + D_BHH;
    float* s_stc = smem + D_STC;

    for (int idx = tid; idx < 6144; idx += 256) {
        int i = idx >> 5, j = idx & 31;
        wE[idx]        = pack2(wih_f[i * 130 + 64 + j], wih_f[i * 130 + 96 + j]);
        wE[6144 + idx] = pack2(wih_r[i * 130 + 64 + j], wih_r[i * 130 + 96 + j]);
        wH[idx]        = pack2(whh_f[(i << 6) + j], whh_f[(i << 6) + 32 + j]);
        wH[6144 + idx] = pack2(whh_r[(i << 6) + j], whh_r[(i << 6) + 32 + j]);
    }
    for (int i = tid; i < 192; i += 256) {
        scst[i] = g_const_f[i];        scst[192 + i] = g_const_r[i];
        sres[i] = wih_f[i * 130 + 128]; sres[192 + i] = wih_r[i * 130 + 128];
        som[i]  = wih_f[i * 130 + 129]; som[192 + i]  = wih_r[i * 130 + 129];
        sbhh[i] = bhh_f[i];            sbhh[192 + i] = bhh_r[i];
    }
    if (tid == 0) {
        float s = 0.f;
        for (int b = 0; b < GRD; b++) s += g_part[b];
        s_stc[0] = 0.001f * s;
    }
    __syncthreads();

    const float stc = s_stc[0];
    float* out_t  = out;
    float* out_e  = out + (size_t)3 * B_N * 64;
    const float* out_rs = out + (size_t)4 * B_N * 64;
    const float* out_om = out_rs + B_N;

    for (int it = 0; it < 2; it++) {
        const int r = ((blockIdx.x * 16) + wrp * 2 + it) * 32 + lane;
        const size_t ro = (size_t)r * 64;

        ull e_p[32];
        {
            const float4* ep = (const float4*)(out_e + ro);
#pragma unroll
            for (int k = 0; k < 8; k++) {
                float4 a = ep[k], b = ep[k + 8];
                e_p[k * 4 + 0] = pack2(a.x, b.x);
                e_p[k * 4 + 1] = pack2(a.y, b.y);
                e_p[k * 4 + 2] = pack2(a.z, b.z);
                e_p[k * 4 + 3] = pack2(a.w, b.w);
            }
        }
        const float res = out_rs[r], om = out_om[r];

#pragma unroll 1
        for (int dir = 0; dir < 2; dir++) {
            ull h_p[32];
            {
                const float4* hp = (const float4*)(h_prev + (size_t)dir * B_N * 64 + ro);
#pragma unroll
                for (int k = 0; k < 8; k++) {
                    float4 a = hp[k], b = hp[k + 8];
                    h_p[k * 4 + 0] = pack2(a.x, b.x);
                    h_p[k * 4 + 1] = pack2(a.y, b.y);
                    h_p[k * 4 + 2] = pack2(a.z, b.z);
                    h_p[k * 4 + 3] = pack2(a.w, b.w);
                }
            }
            const ull* wEd = wE + dir * 6144;
            const ull* wHd = wH + dir * 6144;
            const int c0 = dir * 192;
            float* oh = out_t + (size_t)(1 + dir) * B_N * 64 + ro;

#pragma unroll 1
            for (int d = 0; d < 32; d++) {
                // outputs d and d+32 for gates r(z=+0), z(+64), n(+128)
                const ull* e0 = wEd + (d) * 32;
                const ull* e1 = wEd + (d + 32) * 32;
                const ull* e2 = wEd + (64 + d) * 32;
                const ull* e3 = wEd + (96 + d) * 32;
                const ull* e4 = wEd + (128 + d) * 32;
                const ull* e5 = wEd + (160 + d) * 32;
                const ull* h0 = wHd + (d) * 32;
                const ull* h1 = wHd + (d + 32) * 32;
                const ull* h2 = wHd + (64 + d) * 32;
                const ull* h3 = wHd + (96 + d) * 32;
                const ull* h4 = wHd + (128 + d) * 32;
                const ull* h5 = wHd + (160 + d) * 32;
                ull A0 = 0, A1 = 0, A2 = 0, A3 = 0, A4 = 0, A5 = 0;
                ull B0 = 0, B1 = 0, B2 = 0, B3 = 0, B4 = 0, B5 = 0;
#pragma unroll
                for (int j = 0; j < 32; j++) {
                    ull e = e_p[j], h = h_p[j];
                    fma2(A0, e0[j], e); fma2(A1, e1[j], e); fma2(A2, e2[j], e);
                    fma2(A3, e3[j], e); fma2(A4, e4[j], e); fma2(A5, e5[j], e);
                    fma2(B0, h0[j], h); fma2(B1, h1[j], h); fma2(B2, h2[j], h);
                    fma2(B3, h3[j], h); fma2(B4, h4[j], h); fma2(B5, h5[j], h);
                }
                float ir0 = hadd2(A0) + scst[c0 + d]       + res * sres[c0 + d]       + om * som[c0 + d];
                float ir1 = hadd2(A1) + scst[c0 + d + 32]  + res * sres[c0 + d + 32]  + om * som[c0 + d + 32];
                float iz0 = hadd2(A2) + scst[c0 + 64 + d]  + res * sres[c0 + 64 + d]  + om * som[c0 + 64 + d];
                float iz1 = hadd2(A3) + scst[c0 + 96 + d]  + res * sres[c0 + 96 + d]  + om * som[c0 + 96 + d];
                float in0 = hadd2(A4) + scst[c0 + 128 + d] + res * sres[c0 + 128 + d] + om * som[c0 + 128 + d];
                float in1 = hadd2(A5) + scst[c0 + 160 + d] + res * sres[c0 + 160 + d] + om * som[c0 + 160 + d];
                float hr0 = hadd2(B0) + sbhh[c0 + d];
                float hr1 = hadd2(B1) + sbhh[c0 + d + 32];
                float hz0 = hadd2(B2) + sbhh[c0 + 64 + d];
                float hz1 = hadd2(B3) + sbhh[c0 + 96 + d];
                float hn0 = hadd2(B4) + sbhh[c0 + 128 + d];
                float hn1 = hadd2(B5) + sbhh[c0 + 160 + d];

                float2 hv = unpack2(h_p[d]);
                float rg0 = sigm(ir0 + hr0), rg1 = sigm(ir1 + hr1);
                float zg0 = sigm(iz0 + hz0), zg1 = sigm(iz1 + hz1);
                float ng0 = ftanh(in0 + rg0 * hn0), ng1 = ftanh(in1 + rg1 * hn1);
                float o0 = (1.f - zg0) * ng0 + zg0 * hv.x;
                float o1 = (1.f - zg1) * ng1 + zg1 * hv.y;
                oh[d] = o0;
                oh[d + 32] = o1;
                if (dir == 0) {
                    float2 ev = unpack2(e_p[d]);
                    out_e[ro + d] = ev.x + stc;
                    out_e[ro + d + 32] = ev.y + stc;
                    out_t[ro + d] = 0.3f * __ldg(theta + ro + d) + 0.7f * o0;
                    out_t[ro + d + 32] = 0.3f * __ldg(theta + ro + d + 32) + 0.7f * o1;
                }
            }
        }
    }
}

extern "C" void kernel_launch(void* const* d_in, const int* in_sizes, int n_in,
                              void* d_out, int out_size) {
    const float* theta   = (const float*)d_in[0];
    const float* context = (const float*)d_in[1];
    const float* h_prev  = (const float*)d_in[2];
    const float* memory  = (const float*)d_in[3];
    const float* tw      = (const float*)d_in[4];
    const float* ipw     = (const float*)d_in[5];
    const float* ipb     = (const float*)d_in[6];
    const float* ow      = (const float*)d_in[7];
    const float* ob      = (const float*)d_in[8];
    const float* emo_w1  = (const float*)d_in[9];
    const float* emo_b1  = (const float*)d_in[10];
    const float* emo_w2  = (const float*)d_in[11];
    const float* emo_b2  = (const float*)d_in[12];
    const float* pe      = (const float*)d_in[13];
    const float* ctx_w   = (const float*)d_in[14];
    const float* ctx_b   = (const float*)d_in[15];
    const float* ideal_w = (const float*)d_in[16];
    const float* ideal_b = (const float*)d_in[17];
    const float* wih_f   = (const float*)d_in[18];
    const float* whh_f   = (const float*)d_in[19];
    const float* bih_f   = (const float*)d_in[20];
    const float* bhh_f   = (const float*)d_in[21];
    const float* wih_r   = (const float*)d_in[22];
    const float* whh_r   = (const float*)d_in[23];
    const float* bih_r   = (const float*)d_in[24];
    const float* bhh_r   = (const float*)d_in[25];
    const float* freq_w  = (const float*)d_in[26];
    const float* freq_b  = (const float*)d_in[27];
    const float* prev_i  = (const float*)d_in[28];
    float* out = (float*)d_out;

    static bool attr_set = false;
    if (!attr_set) {
        cudaFuncSetAttribute(kB, cudaFuncAttributeMaxDynamicSharedMemorySize, SMEM_B_BYTES);
        cudaFuncSetAttribute(kD, cudaFuncAttributeMaxDynamicSharedMemorySize, SMEM_D_BYTES);
        attr_set = true;
    }

    kA<<<1, 64>>>(memory, tw, ipw, ipb, ow, ob);
    kB<<<GRD, 256, SMEM_B_BYTES>>>(theta, context, ctx_w, ctx_b, ideal_w, ideal_b,
                                   pe, emo_w1, emo_b1, emo_w2, emo_b2,
                                   prev_i, freq_w, freq_b, out);
    kC<<<1, 192>>>(wih_f, bih_f, wih_r, bih_r);
    kD<<<GRD, 256, SMEM_D_BYTES>>>(wih_f, whh_f, bhh_f, wih_r, whh_r, bhh_r,
                                   h_prev, theta, out);
}

// round 6
// speedup vs baseline: 1.3034x; 1.1043x over previous
#include <cuda_runtime.h>
#include <cstdint>

#define B_N   65536
#define CTXD  384
#define NPR   5
#define MEMV  10
#define EPSV  1e-8f
#define GRD   128

typedef unsigned long long ull;

__device__ float g_o_vec[64];
__device__ float g_part[GRD];
__device__ float g_const_f[192];
__device__ float g_const_r[192];

__device__ __forceinline__ ull pack2(float lo, float hi) {
    ull r; asm("mov.b64 %0,{%1,%2};" : "=l"(r) : "f"(lo), "f"(hi)); return r;
}
__device__ __forceinline__ float2 unpack2(ull v) {
    float2 f; asm("mov.b64 {%0,%1},%2;" : "=f"(f.x), "=f"(f.y) : "l"(v)); return f;
}
__device__ __forceinline__ void fma2(ull& acc, ull a, ull b) {
    asm("fma.rn.f32x2 %0,%1,%2,%0;" : "+l"(acc) : "l"(a), "l"(b));
}
__device__ __forceinline__ float hadd2(ull v) { float2 f = unpack2(v); return f.x + f.y; }
__device__ __forceinline__ float wsum(float v) {
#pragma unroll
    for (int o = 16; o; o >>= 1) v += __shfl_xor_sync(0xffffffffu, v, o);
    return v;
}
__device__ __forceinline__ float sigm(float x) {
    return __fdividef(1.0f, 1.0f + __expf(-x));
}
__device__ __forceinline__ float ftanh(float x) {
    return 1.0f - __fdividef(2.0f, 1.0f + __expf(2.0f * x));
}

// ---------------- kernel A: batch-constant MHA branch ----------------
__global__ void kA(const float* __restrict__ memory, const float* __restrict__ tw,
                   const float* __restrict__ ipw, const float* __restrict__ ipb,
                   const float* __restrict__ ow, const float* __restrict__ ob) {
    __shared__ float mt[64], vv[64];
    int d = threadIdx.x;  // 64 threads
    float a[MEMV], m = -1e30f, s = 0.f;
#pragma unroll
    for (int i = 0; i < MEMV; i++) { a[i] = tw[i]; m = fmaxf(m, a[i]); }
#pragma unroll
    for (int i = 0; i < MEMV; i++) { a[i] = __expf(a[i] - m); s += a[i]; }
    float inv = 1.f / s, acc = 0.f;
#pragma unroll
    for (int i = 0; i < MEMV; i++) acc += (a[i] * inv) * memory[i * 64 + d];
    mt[d] = acc;
    __syncthreads();
    float v = ipb[128 + d];
    for (int j = 0; j < 64; j++) v += mt[j] * ipw[(128 + d) * 64 + j];
    vv[d] = v;
    __syncthreads();
    float o = ob[d];
    for (int j = 0; j < 64; j++) o += vv[j] * ow[d * 64 + j];
    g_o_vec[d] = o;
}

// ---------------- kernel B: per-row phase 1 (lane = batch row) ----------------
// smem float offsets
#define B_WCTX  0        // 12288 ull (interleaved groups of 8 outputs)
#define B_W1P   24576    // 4096 ull  (interleaved groups of 8 outputs, K-paired (j,j+32))
#define B_W2P   32768    // 4096 ull  (output-paired (d,d+32), per hidden k)
#define B_IDWT  40960    // 160 ull
#define B_IDWC  41280    // 160 ull
#define B_PE    41600    // 320 f
#define B_PREV  41920    // 64
#define B_B1    41984    // 128
#define B_B2    42112    // 64
#define B_CTXB  42176    // 64
#define B_IDB   42240    // 8
#define B_SPART 42248    // 8
#define SMEM_B_BYTES (42256 * 4)

__global__ __launch_bounds__(256, 1)
void kB(const float* __restrict__ theta, const float* __restrict__ context,
        const float* __restrict__ ctx_w, const float* __restrict__ ctx_b,
        const float* __restrict__ ideal_w, const float* __restrict__ ideal_b,
        const float* __restrict__ prime_embeds,
        const float* __restrict__ emo_w1, const float* __restrict__ emo_b1,
        const float* __restrict__ emo_w2, const float* __restrict__ emo_b2,
        const float* __restrict__ prev_ideal,
        const float* __restrict__ freq_w, const float* __restrict__ freq_b,
        float* __restrict__ out) {
    extern __shared__ float smem[];
    const int tid = threadIdx.x, lane = tid & 31, wrp = tid >> 5;

    ull* wctx = (ull*)(smem + B_WCTX);
    ull* w1i  = (ull*)(smem + B_W1P);
    ull* w2i  = (ull*)(smem + B_W2P);
    ull* idwt = (ull*)(smem + B_IDWT);
    ull* idwc = (ull*)(smem + B_IDWC);
    float* s_pe   = smem + B_PE;
    float* s_prev = smem + B_PREV;
    float* s_b1   = smem + B_B1;
    float* s_b2   = smem + B_B2;
    float* s_ctxb = smem + B_CTXB;
    float* s_idb  = smem + B_IDB;
    float* s_part = smem + B_SPART;

    // ---- cooperative weight fill ----
    // ctx: [(dg*6+ck)*32 + j]*8 + di ; output d = dg*8+di ; K-pair (j, j+32) in ck chunk
    for (int idx = tid; idx < 12288; idx += 256) {
        int di = idx & 7, j = (idx >> 3) & 31, ck = (idx >> 8) % 6, dg = idx / 1536;
        int d = dg * 8 + di;
        wctx[idx] = pack2(ctx_w[d * 384 + ck * 64 + j], ctx_w[d * 384 + ck * 64 + j + 32]);
    }
    // emo1: [og*32 + j]*8 + oi ; o = og*8+oi ; K-pair (j, j+32)
    for (int idx = tid; idx < 4096; idx += 256) {
        int oi = idx & 7, j = (idx >> 3) & 31, og = idx >> 8;
        int o = og * 8 + oi;
        w1i[idx] = pack2(emo_w1[o * 64 + j], emo_w1[o * 64 + j + 32]);
    }
    // emo2: [kh*32 + di] ; output-pair (di, di+32) at hidden col kh
    for (int idx = tid; idx < 4096; idx += 256) {
        int di = idx & 31, kh = idx >> 5;
        w2i[idx] = pack2(emo_w2[di * 128 + kh], emo_w2[(di + 32) * 128 + kh]);
    }
    for (int idx = tid; idx < NPR * 32; idx += 256) {
        int p = idx >> 5, j = idx & 31;
        idwt[idx] = pack2(ideal_w[p * 128 + j], ideal_w[p * 128 + j + 32]);
        idwc[idx] = pack2(ideal_w[p * 128 + 64 + j], ideal_w[p * 128 + 96 + j]);
    }
    for (int idx = tid; idx < NPR * 64; idx += 256) s_pe[idx] = prime_embeds[idx];
    if (tid < 64) s_prev[tid] = prev_ideal[tid];
    if (tid < 128) s_b1[tid] = emo_b1[tid];
    if (tid < 64) s_b2[tid] = emo_b2[tid];
    if (tid < 64) s_ctxb[tid] = ctx_b[tid];
    if (tid < NPR) s_idb[tid] = ideal_b[tid];
    __syncthreads();

    const float fwv = freq_w[0], fbv = freq_b[0];
    float* out_e  = out + (size_t)3 * B_N * 64;
    float* out_rs = out + (size_t)4 * B_N * 64;
    float* out_om = out_rs + B_N;
    float* out_pw = out_om + B_N;

    float stress_acc = 0.f;

#pragma unroll 1
    for (int it = 0; it < 2; it++) {
        const int r = ((blockIdx.x * 16) + wrp * 2 + it) * 32 + lane;
        const size_t ro = (size_t)r * 64;

        // ================= ctx = context @ ctx_w.T + ctx_b =================
        float c_arr[64];
#pragma unroll
        for (int d = 0; d < 64; d++) c_arr[d] = s_ctxb[d];
        const float4* cp = (const float4*)(context + (size_t)r * CTXD);
#pragma unroll 1
        for (int ck = 0; ck < 6; ck++) {
            ull x_p[32];
#pragma unroll
            for (int k = 0; k < 8; k++) {
                float4 a = cp[ck * 16 + k], b = cp[ck * 16 + k + 8];
                x_p[k * 4 + 0] = pack2(a.x, b.x);
                x_p[k * 4 + 1] = pack2(a.y, b.y);
                x_p[k * 4 + 2] = pack2(a.z, b.z);
                x_p[k * 4 + 3] = pack2(a.w, b.w);
            }
#pragma unroll
            for (int dg = 0; dg < 8; dg++) {
                const ulonglong2* w = (const ulonglong2*)(wctx + (dg * 6 + ck) * 256);
                ull a0 = 0, a1 = 0, a2 = 0, a3 = 0, a4 = 0, a5 = 0, a6 = 0, a7 = 0;
#pragma unroll
                for (int j = 0; j < 32; j++) {
                    ulonglong2 p0 = w[j * 4 + 0], p1 = w[j * 4 + 1];
                    ulonglong2 p2 = w[j * 4 + 2], p3 = w[j * 4 + 3];
                    ull x = x_p[j];
                    fma2(a0, p0.x, x); fma2(a1, p0.y, x);
                    fma2(a2, p1.x, x); fma2(a3, p1.y, x);
                    fma2(a4, p2.x, x); fma2(a5, p2.y, x);
                    fma2(a6, p3.x, x); fma2(a7, p3.y, x);
                }
                c_arr[dg * 8 + 0] += hadd2(a0);
                c_arr[dg * 8 + 1] += hadd2(a1);
                c_arr[dg * 8 + 2] += hadd2(a2);
                c_arr[dg * 8 + 3] += hadd2(a3);
                c_arr[dg * 8 + 4] += hadd2(a4);
                c_arr[dg * 8 + 5] += hadd2(a5);
                c_arr[dg * 8 + 6] += hadd2(a6);
                c_arr[dg * 8 + 7] += hadd2(a7);
            }
        }

        // ================= theta row (packed (j, j+32)) =================
        ull th_p[32];
        {
            const float4* tp = (const float4*)(theta + ro);
#pragma unroll
            for (int k = 0; k < 8; k++) {
                float4 a = tp[k], b = tp[k + 8];
                th_p[k * 4 + 0] = pack2(a.x, b.x);
                th_p[k * 4 + 1] = pack2(a.y, b.y);
                th_p[k * 4 + 2] = pack2(a.z, b.z);
                th_p[k * 4 + 3] = pack2(a.w, b.w);
            }
        }

        // ================= prime logits + softmax =================
        float pw[NPR];
        {
            ull c_p[32];
#pragma unroll
            for (int j = 0; j < 32; j++) c_p[j] = pack2(c_arr[j], c_arr[j + 32]);
            float lg[NPR];
#pragma unroll
            for (int p = 0; p < NPR; p++) {
                ull a = 0, b = 0;
#pragma unroll
                for (int j = 0; j < 32; j++) {
                    fma2(a, idwt[p * 32 + j], th_p[j]);
                    fma2(b, idwc[p * 32 + j], c_p[j]);
                }
                lg[p] = hadd2(a) + hadd2(b) + s_idb[p];
            }
            float mx = lg[0];
#pragma unroll
            for (int p = 1; p < NPR; p++) mx = fmaxf(mx, lg[p]);
            float ssum = 0.f;
#pragma unroll
            for (int p = 0; p < NPR; p++) { pw[p] = __expf(lg[p] - mx); ssum += pw[p]; }
            float invs = __fdividef(1.f, ssum);
#pragma unroll
            for (int p = 0; p < NPR; p++) {
                pw[p] *= invs;
                out_pw[(size_t)r * NPR + p] = pw[p];
            }
        }

        // ================= theta_ideal scalars: stress/res/omega =================
        {
            float str = 0.f, nth = 0.f, nti = 0.f, rdot = 0.f, f2 = 0.f;
#pragma unroll
            for (int j = 0; j < 32; j++) {
                float2 t = unpack2(th_p[j]);
                float ti0 = 0.f, ti1 = 0.f;
#pragma unroll
                for (int p = 0; p < NPR; p++) {
                    ti0 += pw[p] * s_pe[p * 64 + j];
                    ti1 += pw[p] * s_pe[p * 64 + j + 32];
                }
                float d0 = t.x - ti0, d1 = t.y - ti1;
                str += d0 * d0 + d1 * d1;
                nth += t.x * t.x + t.y * t.y;
                nti += ti0 * ti0 + ti1 * ti1;
                rdot += t.x * ti0 + t.y * ti1;
                float p0 = ti0 - s_prev[j], p1 = ti1 - s_prev[j + 32];
                f2 += p0 * p0 + p1 * p1;
            }
            stress_acc += str;
            float inv_t = __fdividef(1.f, sqrtf(nth) + EPSV);
            float inv_i = __fdividef(1.f, sqrtf(nti) + EPSV);
            float ntn = sqrtf(nth) * inv_t, ntin = sqrtf(nti) * inv_i;
            out_rs[r] = __fdividef(rdot * inv_t * inv_i, fmaxf(ntn * ntin, EPSV));
            float fr = sqrtf(f2);
            out_om[r] = ftanh(fr * fwv + fbv) * (1.0f + 0.1f * __sinf(fr));
        }

        // ================= emotion MLP (fused hidden chunks of 8) =================
        {
            ull e_acc[32];
#pragma unroll
            for (int di = 0; di < 32; di++) e_acc[di] = pack2(s_b2[di], s_b2[di + 32]);
#pragma unroll 1
            for (int og = 0; og < 16; og++) {
                const ulonglong2* w1v = (const ulonglong2*)(w1i + og * 256);
                ull a0 = 0, a1 = 0, a2 = 0, a3 = 0, a4 = 0, a5 = 0, a6 = 0, a7 = 0;
#pragma unroll
                for (int j = 0; j < 32; j++) {
                    ulonglong2 p0 = w1v[j * 4 + 0], p1 = w1v[j * 4 + 1];
                    ulonglong2 p2 = w1v[j * 4 + 2], p3 = w1v[j * 4 + 3];
                    ull t = th_p[j];
                    fma2(a0, p0.x, t); fma2(a1, p0.y, t);
                    fma2(a2, p1.x, t); fma2(a3, p1.y, t);
                    fma2(a4, p2.x, t); fma2(a5, p2.y, t);
                    fma2(a6, p3.x, t); fma2(a7, p3.y, t);
                }
                float t8[8];
                t8[0] = ftanh(hadd2(a0) + s_b1[og * 8 + 0]);
                t8[1] = ftanh(hadd2(a1) + s_b1[og * 8 + 1]);
                t8[2] = ftanh(hadd2(a2) + s_b1[og * 8 + 2]);
                t8[3] = ftanh(hadd2(a3) + s_b1[og * 8 + 3]);
                t8[4] = ftanh(hadd2(a4) + s_b1[og * 8 + 4]);
                t8[5] = ftanh(hadd2(a5) + s_b1[og * 8 + 5]);
                t8[6] = ftanh(hadd2(a6) + s_b1[og * 8 + 6]);
                t8[7] = ftanh(hadd2(a7) + s_b1[og * 8 + 7]);
#pragma unroll
                for (int k = 0; k < 8; k++) {
                    ull tt = pack2(t8[k], t8[k]);
                    const ulonglong2* w2v = (const ulonglong2*)(w2i + (og * 8 + k) * 32);
#pragma unroll
                    for (int di2 = 0; di2 < 16; di2++) {
                        ulonglong2 q = w2v[di2];
                        fma2(e_acc[di2 * 2 + 0], q.x, tt);
                        fma2(e_acc[di2 * 2 + 1], q.y, tt);
                    }
                }
            }
            float4* ep = (float4*)(out_e + ro);
#pragma unroll
            for (int k = 0; k < 8; k++) {
                float2 v0 = unpack2(e_acc[k * 4 + 0]);
                float2 v1 = unpack2(e_acc[k * 4 + 1]);
                float2 v2 = unpack2(e_acc[k * 4 + 2]);
                float2 v3 = unpack2(e_acc[k * 4 + 3]);
                ep[k]     = make_float4(fmaxf(v0.x, 0.f), fmaxf(v1.x, 0.f),
                                        fmaxf(v2.x, 0.f), fmaxf(v3.x, 0.f));
                ep[8 + k] = make_float4(fmaxf(v0.y, 0.f), fmaxf(v1.y, 0.f),
                                        fmaxf(v2.y, 0.f), fmaxf(v3.y, 0.f));
            }
        }
    }

    // deterministic stress reduction
    float ws = wsum(stress_acc);
    if (lane == 0) s_part[wrp] = ws;
    __syncthreads();
    if (tid == 0) {
        float s = 0.f;
        for (int w = 0; w < 8; w++) s += s_part[w];
        g_part[blockIdx.x] = s;
    }
}

// ---------------- kernel C: fold GRU batch-constant terms ----------------
__global__ void kC(const float* __restrict__ w_ih_f, const float* __restrict__ b_ih_f,
                   const float* __restrict__ w_ih_r, const float* __restrict__ b_ih_r) {
    __shared__ float ss;
    int i = threadIdx.x;  // 192 threads
    if (i == 0) {
        float s = 0.f;
        for (int b = 0; b < GRD; b++) s += g_part[b];
        ss = s;
    }
    __syncthreads();
    float sc = 0.001f * ss;
    float af = b_ih_f[i], ar = b_ih_r[i], rf = 0.f, rr = 0.f;
    for (int j = 0; j < 64; j++) {
        float ov = g_o_vec[j];
        af += w_ih_f[i * 130 + j] * ov;
        ar += w_ih_r[i * 130 + j] * ov;
        rf += w_ih_f[i * 130 + 64 + j];
        rr += w_ih_r[i * 130 + 64 + j];
    }
    g_const_f[i] = af + sc * rf;
    g_const_r[i] = ar + sc * rr;
}

// ---------------- kernel D: both GRU directions (lane = batch row) ----------------
// wInt interleaved: [((dir*32 + d)*32 + j)*12 + s]
//   s 0..5 : E-weights (r lo, r hi, z lo, z hi, n lo, n hi), K-pair (j, j+32)
//   s 6..11: H-weights, same order
#define D_WINT 0         // 24576 ull = 49152 f
#define D_CST  49152     // 384
#define D_RES  49536     // 384
#define D_OM   49920     // 384
#define D_BHH  50304     // 384
#define D_STC  50688     // 1
#define SMEM_D_BYTES (50692 * 4)

__global__ __launch_bounds__(256, 1)
void kD(const float* __restrict__ wih_f, const float* __restrict__ whh_f,
        const float* __restrict__ bhh_f,
        const float* __restrict__ wih_r, const float* __restrict__ whh_r,
        const float* __restrict__ bhh_r,
        const float* __restrict__ h_prev, const float* __restrict__ theta,
        float* __restrict__ out) {
    extern __shared__ float smem[];
    const int tid = threadIdx.x, lane = tid & 31, wrp = tid >> 5;

    ull* wInt = (ull*)(smem + D_WINT);
    float* scst = smem + D_CST;
    float* sres = smem + D_RES;
    float* som  = smem + D_OM;
    float* sbhh = smem + D_BHH;
    float* s_stc = smem + D_STC;

    for (int idx = tid; idx < 24576; idx += 256) {
        int s = idx % 12;
        int j = (idx / 12) & 31;
        int d = (idx / 384) & 31;
        int dir = idx / 12288;
        int sg = s % 6;
        int o = (sg >> 1) * 64 + (sg & 1) * 32 + d;
        const float* wih = dir ? wih_r : wih_f;
        const float* whh = dir ? whh_r : whh_f;
        wInt[idx] = (s < 6) ? pack2(wih[o * 130 + 64 + j], wih[o * 130 + 96 + j])
                            : pack2(whh[o * 64 + j], whh[o * 64 + 32 + j]);
    }
    for (int i = tid; i < 192; i += 256) {
        scst[i] = g_const_f[i];         scst[192 + i] = g_const_r[i];
        sres[i] = wih_f[i * 130 + 128]; sres[192 + i] = wih_r[i * 130 + 128];
        som[i]  = wih_f[i * 130 + 129]; som[192 + i]  = wih_r[i * 130 + 129];
        sbhh[i] = bhh_f[i];             sbhh[192 + i] = bhh_r[i];
    }
    if (tid == 0) {
        float s = 0.f;
        for (int b = 0; b < GRD; b++) s += g_part[b];
        s_stc[0] = 0.001f * s;
    }
    __syncthreads();

    const float stc = s_stc[0];
    float* out_t  = out;
    float* out_e  = out + (size_t)3 * B_N * 64;
    const float* out_rs = out + (size_t)4 * B_N * 64;
    const float* out_om = out_rs + B_N;

#pragma unroll 1
    for (int it = 0; it < 2; it++) {
        const int r = ((blockIdx.x * 16) + wrp * 2 + it) * 32 + lane;
        const size_t ro = (size_t)r * 64;

        ull e_p[32];
        {
            const float4* ep = (const float4*)(out_e + ro);
#pragma unroll
            for (int k = 0; k < 8; k++) {
                float4 a = ep[k], b = ep[k + 8];
                e_p[k * 4 + 0] = pack2(a.x, b.x);
                e_p[k * 4 + 1] = pack2(a.y, b.y);
                e_p[k * 4 + 2] = pack2(a.z, b.z);
                e_p[k * 4 + 3] = pack2(a.w, b.w);
            }
        }
        const float res = out_rs[r], om = out_om[r];

#pragma unroll 1
        for (int dir = 0; dir < 2; dir++) {
            const float* hpd = h_prev + (size_t)dir * B_N * 64;
            ull h_p[32];
            {
                const float4* hp = (const float4*)(hpd + ro);
#pragma unroll
                for (int k = 0; k < 8; k++) {
                    float4 a = hp[k], b = hp[k + 8];
                    h_p[k * 4 + 0] = pack2(a.x, b.x);
                    h_p[k * 4 + 1] = pack2(a.y, b.y);
                    h_p[k * 4 + 2] = pack2(a.z, b.z);
                    h_p[k * 4 + 3] = pack2(a.w, b.w);
                }
            }
            const int c0 = dir * 192;
            float* oh = out_t + (size_t)(1 + dir) * B_N * 64 + ro;

#pragma unroll 1
            for (int d = 0; d < 32; d++) {
                const ulonglong2* w = (const ulonglong2*)(wInt + (size_t)(dir * 32 + d) * 384);
                ull A0 = 0, A1 = 0, A2 = 0, A3 = 0, A4 = 0, A5 = 0;
                ull B0 = 0, B1 = 0, B2 = 0, B3 = 0, B4 = 0, B5 = 0;
#pragma unroll
                for (int j = 0; j < 32; j++) {
                    ulonglong2 p0 = w[j * 6 + 0], p1 = w[j * 6 + 1], p2 = w[j * 6 + 2];
                    ulonglong2 p3 = w[j * 6 + 3], p4 = w[j * 6 + 4], p5 = w[j * 6 + 5];
                    ull e = e_p[j], h = h_p[j];
                    fma2(A0, p0.x, e); fma2(A1, p0.y, e);
                    fma2(A2, p1.x, e); fma2(A3, p1.y, e);
                    fma2(A4, p2.x, e); fma2(A5, p2.y, e);
                    fma2(B0, p3.x, h); fma2(B1, p3.y, h);
                    fma2(B2, p4.x, h); fma2(B3, p4.y, h);
                    fma2(B4, p5.x, h); fma2(B5, p5.y, h);
                }
                float ir0 = hadd2(A0) + scst[c0 + d]       + res * sres[c0 + d]       + om * som[c0 + d];
                float ir1 = hadd2(A1) + scst[c0 + d + 32]  + res * sres[c0 + d + 32]  + om * som[c0 + d + 32];
                float iz0 = hadd2(A2) + scst[c0 + 64 + d]  + res * sres[c0 + 64 + d]  + om * som[c0 + 64 + d];
                float iz1 = hadd2(A3) + scst[c0 + 96 + d]  + res * sres[c0 + 96 + d]  + om * som[c0 + 96 + d];
                float in0 = hadd2(A4) + scst[c0 + 128 + d] + res * sres[c0 + 128 + d] + om * som[c0 + 128 + d];
                float in1 = hadd2(A5) + scst[c0 + 160 + d] + res * sres[c0 + 160 + d] + om * som[c0 + 160 + d];
                float hr0 = hadd2(B0) + sbhh[c0 + d];
                float hr1 = hadd2(B1) + sbhh[c0 + d + 32];
                float hz0 = hadd2(B2) + sbhh[c0 + 64 + d];
                float hz1 = hadd2(B3) + sbhh[c0 + 96 + d];
                float hn0 = hadd2(B4) + sbhh[c0 + 128 + d];
                float hn1 = hadd2(B5) + sbhh[c0 + 160 + d];

                // reload scalars from gmem (L1-hit) — avoids dynamic reg-array indexing
                float hv0 = hpd[ro + d], hv1 = hpd[ro + d + 32];
                float rg0 = sigm(ir0 + hr0), rg1 = sigm(ir1 + hr1);
                float zg0 = sigm(iz0 + hz0), zg1 = sigm(iz1 + hz1);
                float ng0 = ftanh(in0 + rg0 * hn0), ng1 = ftanh(in1 + rg1 * hn1);
                float o0 = (1.f - zg0) * ng0 + zg0 * hv0;
                float o1 = (1.f - zg1) * ng1 + zg1 * hv1;
                oh[d] = o0;
                oh[d + 32] = o1;
                if (dir == 0) {
                    out_e[ro + d]      += stc;
                    out_e[ro + d + 32] += stc;
                    out_t[ro + d]      = 0.3f * theta[ro + d] + 0.7f * o0;
                    out_t[ro + d + 32] = 0.3f * theta[ro + d + 32] + 0.7f * o1;
                }
            }
        }
    }
}

extern "C" void kernel_launch(void* const* d_in, const int* in_sizes, int n_in,
                              void* d_out, int out_size) {
    const float* theta   = (const float*)d_in[0];
    const float* context = (const float*)d_in[1];
    const float* h_prev  = (const float*)d_in[2];
    const float* memory  = (const float*)d_in[3];
    const float* tw      = (const float*)d_in[4];
    const float* ipw     = (const float*)d_in[5];
    const float* ipb     = (const float*)d_in[6];
    const float* ow      = (const float*)d_in[7];
    const float* ob      = (const float*)d_in[8];
    const float* emo_w1  = (const float*)d_in[9];
    const float* emo_b1  = (const float*)d_in[10];
    const float* emo_w2  = (const float*)d_in[11];
    const float* emo_b2  = (const float*)d_in[12];
    const float* pe      = (const float*)d_in[13];
    const float* ctx_w   = (const float*)d_in[14];
    const float* ctx_b   = (const float*)d_in[15];
    const float* ideal_w = (const float*)d_in[16];
    const float* ideal_b = (const float*)d_in[17];
    const float* wih_f   = (const float*)d_in[18];
    const float* whh_f   = (const float*)d_in[19];
    const float* bih_f   = (const float*)d_in[20];
    const float* bhh_f   = (const float*)d_in[21];
    const float* wih_r   = (const float*)d_in[22];
    const float* whh_r   = (const float*)d_in[23];
    const float* bih_r   = (const float*)d_in[24];
    const float* bhh_r   = (const float*)d_in[25];
    const float* freq_w  = (const float*)d_in[26];
    const float* freq_b  = (const float*)d_in[27];
    const float* prev_i  = (const float*)d_in[28];
    float* out = (float*)d_out;

    static bool attr_set = false;
    if (!attr_set) {
        cudaFuncSetAttribute(kB, cudaFuncAttributeMaxDynamicSharedMemorySize, SMEM_B_BYTES);
        cudaFuncSetAttribute(kD, cudaFuncAttributeMaxDynamicSharedMemorySize, SMEM_D_BYTES);
        attr_set = true;
    }

    kA<<<1, 64>>>(memory, tw, ipw, ipb, ow, ob);
    kB<<<GRD, 256, SMEM_B_BYTES>>>(theta, context, ctx_w, ctx_b, ideal_w, ideal_b,
                                   pe, emo_w1, emo_b1, emo_w2, emo_b2,
                                   prev_i, freq_w, freq_b, out);
    kC<<<1, 192>>>(wih_f, bih_f, wih_r, bih_r);
    kD<<<GRD, 256, SMEM_D_BYTES>>>(wih_f, whh_f, bhh_f, wih_r, whh_r, bhh_r,
                                   h_prev, theta, out);
}

// round 7
// speedup vs baseline: 1.4195x; 1.0891x over previous
#include <cuda_runtime.h>
#include <cstdint>

#define B_N   65536
#define CTXD  384
#define NPR   5
#define MEMV  10
#define EPSV  1e-8f
#define NPART 256

typedef unsigned long long ull;

__device__ float g_o_vec[64];
__device__ float g_part[NPART];
__device__ float g_const_f[192];
__device__ float g_const_r[192];
__device__ float g_ge[2u * 192u * B_N];   // GRU e-part pre-GEMM scratch

__device__ __forceinline__ ull pack2(float lo, float hi) {
    ull r; asm("mov.b64 %0,{%1,%2};" : "=l"(r) : "f"(lo), "f"(hi)); return r;
}
__device__ __forceinline__ float2 unpack2(ull v) {
    float2 f; asm("mov.b64 {%0,%1},%2;" : "=f"(f.x), "=f"(f.y) : "l"(v)); return f;
}
__device__ __forceinline__ void fma2(ull& acc, ull a, ull b) {
    asm("fma.rn.f32x2 %0,%1,%2,%0;" : "+l"(acc) : "l"(a), "l"(b));
}
__device__ __forceinline__ float hadd2(ull v) { float2 f = unpack2(v); return f.x + f.y; }
__device__ __forceinline__ float wsum(float v) {
#pragma unroll
    for (int o = 16; o; o >>= 1) v += __shfl_xor_sync(0xffffffffu, v, o);
    return v;
}
__device__ __forceinline__ float sigm(float x) { return __fdividef(1.0f, 1.0f + __expf(-x)); }
__device__ __forceinline__ float ftanh(float x) { return 1.0f - __fdividef(2.0f, 1.0f + __expf(2.0f * x)); }

// load a 64-float row as 32 (j, j+32) packed pairs
__device__ __forceinline__ void load_row_pairs(const float* p, ull* dst) {
    const float4* v = (const float4*)p;
#pragma unroll
    for (int k = 0; k < 8; k++) {
        float4 a = v[k], b = v[k + 8];
        dst[k * 4 + 0] = pack2(a.x, b.x);
        dst[k * 4 + 1] = pack2(a.y, b.y);
        dst[k * 4 + 2] = pack2(a.z, b.z);
        dst[k * 4 + 3] = pack2(a.w, b.w);
    }
}

// ---------------- kernel A: batch-constant MHA branch ----------------
__global__ void kA(const float* __restrict__ memory, const float* __restrict__ tw,
                   const float* __restrict__ ipw, const float* __restrict__ ipb,
                   const float* __restrict__ ow, const float* __restrict__ ob) {
    __shared__ float mt[64], vv[64];
    int d = threadIdx.x;  // 64 threads
    float a[MEMV], m = -1e30f, s = 0.f;
#pragma unroll
    for (int i = 0; i < MEMV; i++) { a[i] = tw[i]; m = fmaxf(m, a[i]); }
#pragma unroll
    for (int i = 0; i < MEMV; i++) { a[i] = __expf(a[i] - m); s += a[i]; }
    float inv = 1.f / s, acc = 0.f;
#pragma unroll
    for (int i = 0; i < MEMV; i++) acc += (a[i] * inv) * memory[i * 64 + d];
    mt[d] = acc;
    __syncthreads();
    float v = ipb[128 + d];
    for (int j = 0; j < 64; j++) v += mt[j] * ipw[(128 + d) * 64 + j];
    vv[d] = v;
    __syncthreads();
    float o = ob[d];
    for (int j = 0; j < 64; j++) o += vv[j] * ow[d * 64 + j];
    g_o_vec[d] = o;
}

// ---------------- kB1: ctx GEMM + prime softmax + scalars (2 rows/lane) ----------------
// smem float offsets
#define B1_WCTX 0        // 12288 ull = 24576 f  : [(p*384 + k)*16 + dpi] pair (d, d+32), d = p*16+dpi
#define B1_IDWT 24576    // 160 ull
#define B1_IDWC 24896    // 160 ull
#define B1_PE   25216    // 160 ull
#define B1_PREV 25536    // 32 ull
#define B1_CTXB 25600    // 64 f
#define B1_IDB  25664    // 8
#define B1_PART 25672    // 4
#define SMEM_B1_BYTES (25680 * 4)

__global__ __launch_bounds__(128, 2)
void kB1(const float* __restrict__ theta, const float* __restrict__ context,
         const float* __restrict__ ctx_w, const float* __restrict__ ctx_b,
         const float* __restrict__ ideal_w, const float* __restrict__ ideal_b,
         const float* __restrict__ prime_embeds, const float* __restrict__ prev_ideal,
         const float* __restrict__ freq_w, const float* __restrict__ freq_b,
         float* __restrict__ out) {
    extern __shared__ float smem[];
    const int tid = threadIdx.x, lane = tid & 31, wrp = tid >> 5;

    ull* wctx = (ull*)(smem + B1_WCTX);
    ull* idwt = (ull*)(smem + B1_IDWT);
    ull* idwc = (ull*)(smem + B1_IDWC);
    ull* pe_s = (ull*)(smem + B1_PE);
    ull* prev_s = (ull*)(smem + B1_PREV);
    float* s_ctxb = smem + B1_CTXB;
    float* s_idb  = smem + B1_IDB;
    float* s_part = smem + B1_PART;

    for (int idx = tid; idx < 12288; idx += 128) {
        int dpi = idx & 15, k = (idx >> 4) % 384, p = idx / 6144;
        int d = p * 16 + dpi;
        wctx[idx] = pack2(ctx_w[d * 384 + k], ctx_w[(d + 32) * 384 + k]);
    }
    for (int idx = tid; idx < 160; idx += 128) {
        int p = idx >> 5, j = idx & 31;
        idwt[idx] = pack2(ideal_w[p * 128 + j], ideal_w[p * 128 + j + 32]);
        idwc[idx] = pack2(ideal_w[p * 128 + 64 + j], ideal_w[p * 128 + 96 + j]);
        pe_s[idx] = pack2(prime_embeds[p * 64 + j], prime_embeds[p * 64 + j + 32]);
    }
    if (tid < 32) prev_s[tid] = pack2(prev_ideal[tid], prev_ideal[tid + 32]);
    if (tid < 64) s_ctxb[tid] = ctx_b[tid];
    if (tid < NPR) s_idb[tid] = ideal_b[tid];
    __syncthreads();

    const float fwv = freq_w[0], fbv = freq_b[0];
    float* out_rs = out + (size_t)4 * B_N * 64;
    float* out_om = out_rs + B_N;
    float* out_pw = out_om + B_N;

    const int base = (blockIdx.x * 4 + wrp) * 64;
    const int r0 = base + lane, r1 = r0 + 32;

    // ---- logit accumulators (pairs, hadd at end): lgu[p*2+ri] ----
    ull lgu[10];
#pragma unroll
    for (int i = 0; i < 10; i++) lgu[i] = 0;

    // ---- ctx GEMM in two dp-half passes; fold c directly into lgu ----
    const float4* x0v = (const float4*)(context + (size_t)r0 * CTXD);
    const float4* x1v = (const float4*)(context + (size_t)r1 * CTXD);
#pragma unroll 1
    for (int p = 0; p < 2; p++) {
        ull cp[32];
#pragma unroll
        for (int dpi = 0; dpi < 16; dpi++) {
            ull b = pack2(s_ctxb[p * 16 + dpi], s_ctxb[p * 16 + dpi + 32]);
            cp[dpi * 2 + 0] = b;
            cp[dpi * 2 + 1] = b;
        }
#pragma unroll 1
        for (int k4 = 0; k4 < 96; k4++) {
            float4 a0 = x0v[k4], a1 = x1v[k4];
            float xs0[4] = {a0.x, a0.y, a0.z, a0.w};
            float xs1[4] = {a1.x, a1.y, a1.z, a1.w};
#pragma unroll
            for (int e = 0; e < 4; e++) {
                ull xx0 = pack2(xs0[e], xs0[e]);
                ull xx1 = pack2(xs1[e], xs1[e]);
                const ulonglong2* w = (const ulonglong2*)(wctx + (p * 384 + k4 * 4 + e) * 16);
#pragma unroll
                for (int q = 0; q < 8; q++) {
                    ulonglong2 ww = w[q];
                    fma2(cp[(2 * q) * 2 + 0], ww.x, xx0);
                    fma2(cp[(2 * q) * 2 + 1], ww.x, xx1);
                    fma2(cp[(2 * q + 1) * 2 + 0], ww.y, xx0);
                    fma2(cp[(2 * q + 1) * 2 + 1], ww.y, xx1);
                }
            }
        }
        // fold this half of c into the logits (c = pairs (d, d+32), d = p*16+dpi)
#pragma unroll
        for (int p5 = 0; p5 < NPR; p5++)
#pragma unroll
            for (int dpi = 0; dpi < 16; dpi++) {
                ull w = idwc[p5 * 32 + p * 16 + dpi];
                fma2(lgu[p5 * 2 + 0], w, cp[dpi * 2 + 0]);
                fma2(lgu[p5 * 2 + 1], w, cp[dpi * 2 + 1]);
            }
    }

    // ---- theta part of logits (chunked th pairs) ----
    const float4* t0v = (const float4*)(theta + (size_t)r0 * 64);
    const float4* t1v = (const float4*)(theta + (size_t)r1 * 64);
#pragma unroll 1
    for (int cc = 0; cc < 2; cc++) {
        ull thc0[16], thc1[16];
#pragma unroll
        for (int k2 = 0; k2 < 4; k2++) {
            float4 a = t0v[cc * 4 + k2], b = t0v[cc * 4 + 8 + k2];
            thc0[k2 * 4 + 0] = pack2(a.x, b.x); thc0[k2 * 4 + 1] = pack2(a.y, b.y);
            thc0[k2 * 4 + 2] = pack2(a.z, b.z); thc0[k2 * 4 + 3] = pack2(a.w, b.w);
            float4 c = t1v[cc * 4 + k2], d = t1v[cc * 4 + 8 + k2];
            thc1[k2 * 4 + 0] = pack2(c.x, d.x); thc1[k2 * 4 + 1] = pack2(c.y, d.y);
            thc1[k2 * 4 + 2] = pack2(c.z, d.z); thc1[k2 * 4 + 3] = pack2(c.w, d.w);
        }
#pragma unroll
        for (int p5 = 0; p5 < NPR; p5++)
#pragma unroll
            for (int jj = 0; jj < 16; jj++) {
                ull w = idwt[p5 * 32 + cc * 16 + jj];
                fma2(lgu[p5 * 2 + 0], w, thc0[jj]);
                fma2(lgu[p5 * 2 + 1], w, thc1[jj]);
            }
    }

    // ---- softmax (both rows) ----
    float pw0[NPR], pw1[NPR];
    {
        float lg0[NPR], lg1[NPR];
#pragma unroll
        for (int p = 0; p < NPR; p++) {
            lg0[p] = hadd2(lgu[p * 2 + 0]) + s_idb[p];
            lg1[p] = hadd2(lgu[p * 2 + 1]) + s_idb[p];
        }
        float m0 = lg0[0], m1 = lg1[0];
#pragma unroll
        for (int p = 1; p < NPR; p++) { m0 = fmaxf(m0, lg0[p]); m1 = fmaxf(m1, lg1[p]); }
        float s0 = 0.f, s1 = 0.f;
#pragma unroll
        for (int p = 0; p < NPR; p++) {
            pw0[p] = __expf(lg0[p] - m0); s0 += pw0[p];
            pw1[p] = __expf(lg1[p] - m1); s1 += pw1[p];
        }
        float i0 = __fdividef(1.f, s0), i1 = __fdividef(1.f, s1);
#pragma unroll
        for (int p = 0; p < NPR; p++) {
            pw0[p] *= i0; pw1[p] *= i1;
            out_pw[(size_t)r0 * NPR + p] = pw0[p];
            out_pw[(size_t)r1 * NPR + p] = pw1[p];
        }
    }

    // ---- scalar pass: stress / res / omega per row ----
    float str0 = 0.f, nth0 = 0.f, nti0 = 0.f, rd0 = 0.f, f20 = 0.f;
    float str1 = 0.f, nth1 = 0.f, nti1 = 0.f, rd1 = 0.f, f21 = 0.f;
#pragma unroll 1
    for (int cc = 0; cc < 2; cc++) {
        ull thc0[16], thc1[16];
#pragma unroll
        for (int k2 = 0; k2 < 4; k2++) {
            float4 a = t0v[cc * 4 + k2], b = t0v[cc * 4 + 8 + k2];
            thc0[k2 * 4 + 0] = pack2(a.x, b.x); thc0[k2 * 4 + 1] = pack2(a.y, b.y);
            thc0[k2 * 4 + 2] = pack2(a.z, b.z); thc0[k2 * 4 + 3] = pack2(a.w, b.w);
            float4 c = t1v[cc * 4 + k2], d = t1v[cc * 4 + 8 + k2];
            thc1[k2 * 4 + 0] = pack2(c.x, d.x); thc1[k2 * 4 + 1] = pack2(c.y, d.y);
            thc1[k2 * 4 + 2] = pack2(c.z, d.z); thc1[k2 * 4 + 3] = pack2(c.w, d.w);
        }
#pragma unroll
        for (int jj = 0; jj < 16; jj++) {
            int j = cc * 16 + jj;
            float2 pv = unpack2(prev_s[j]);
            float2 pe0 = unpack2(pe_s[0 * 32 + j]);
            float2 pe1 = unpack2(pe_s[1 * 32 + j]);
            float2 pe2 = unpack2(pe_s[2 * 32 + j]);
            float2 pe3 = unpack2(pe_s[3 * 32 + j]);
            float2 pe4 = unpack2(pe_s[4 * 32 + j]);
            // row 0
            {
                float tix = pw0[0] * pe0.x + pw0[1] * pe1.x + pw0[2] * pe2.x
                          + pw0[3] * pe3.x + pw0[4] * pe4.x;
                float tiy = pw0[0] * pe0.y + pw0[1] * pe1.y + pw0[2] * pe2.y
                          + pw0[3] * pe3.y + pw0[4] * pe4.y;
                float2 t = unpack2(thc0[jj]);
                float dx = t.x - tix, dy = t.y - tiy;
                str0 += dx * dx + dy * dy;
                nth0 += t.x * t.x + t.y * t.y;
                nti0 += tix * tix + tiy * tiy;
                rd0  += t.x * tix + t.y * tiy;
                float px = tix - pv.x, py = tiy - pv.y;
                f20 += px * px + py * py;
            }
            // row 1
            {
                float tix = pw1[0] * pe0.x + pw1[1] * pe1.x + pw1[2] * pe2.x
                          + pw1[3] * pe3.x + pw1[4] * pe4.x;
                float tiy = pw1[0] * pe0.y + pw1[1] * pe1.y + pw1[2] * pe2.y
                          + pw1[3] * pe3.y + pw1[4] * pe4.y;
                float2 t = unpack2(thc1[jj]);
                float dx = t.x - tix, dy = t.y - tiy;
                str1 += dx * dx + dy * dy;
                nth1 += t.x * t.x + t.y * t.y;
                nti1 += tix * tix + tiy * tiy;
                rd1  += t.x * tix + t.y * tiy;
                float px = tix - pv.x, py = tiy - pv.y;
                f21 += px * px + py * py;
            }
        }
    }
    {
        float it0 = __fdividef(1.f, sqrtf(nth0) + EPSV);
        float ii0 = __fdividef(1.f, sqrtf(nti0) + EPSV);
        out_rs[r0] = __fdividef(rd0 * it0 * ii0,
                                fmaxf(sqrtf(nth0) * it0 * sqrtf(nti0) * ii0, EPSV));
        float fr0 = sqrtf(f20);
        out_om[r0] = ftanh(fr0 * fwv + fbv) * (1.0f + 0.1f * __sinf(fr0));
        float it1 = __fdividef(1.f, sqrtf(nth1) + EPSV);
        float ii1 = __fdividef(1.f, sqrtf(nti1) + EPSV);
        out_rs[r1] = __fdividef(rd1 * it1 * ii1,
                                fmaxf(sqrtf(nth1) * it1 * sqrtf(nti1) * ii1, EPSV));
        float fr1 = sqrtf(f21);
        out_om[r1] = ftanh(fr1 * fwv + fbv) * (1.0f + 0.1f * __sinf(fr1));
    }

    // deterministic stress partial
    float ws = wsum(str0 + str1);
    if (lane == 0) s_part[wrp] = ws;
    __syncthreads();
    if (tid == 0) {
        g_part[blockIdx.x] = (s_part[0] + s_part[1]) + (s_part[2] + s_part[3]);
    }
}

// ---------------- kB2a: emotion MLP (raw e -> out_e) ----------------
#define B2A_W1  0        // 4096 ull = 8192 f
#define B2A_W2  8192     // 4096 ull = 8192 f
#define B2A_B1  16384    // 128
#define B2A_B2  16512    // 64
#define SMEM_B2A_BYTES (16576 * 4)

__global__ __launch_bounds__(128, 3)
void kB2a(const float* __restrict__ theta,
          const float* __restrict__ emo_w1, const float* __restrict__ emo_b1,
          const float* __restrict__ emo_w2, const float* __restrict__ emo_b2,
          float* __restrict__ out) {
    extern __shared__ float smem[];
    const int tid = threadIdx.x, lane = tid & 31, wrp = tid >> 5;
    ull* w1i = (ull*)(smem + B2A_W1);
    ull* w2i = (ull*)(smem + B2A_W2);
    float* s_b1 = smem + B2A_B1;
    float* s_b2 = smem + B2A_B2;

    for (int idx = tid; idx < 4096; idx += 128) {
        int oi = idx & 7, j = (idx >> 3) & 31, og = idx >> 8;
        int o = og * 8 + oi;
        w1i[idx] = pack2(emo_w1[o * 64 + j], emo_w1[o * 64 + j + 32]);
    }
    for (int idx = tid; idx < 4096; idx += 128) {
        int di = idx & 31, kh = idx >> 5;
        w2i[idx] = pack2(emo_w2[di * 128 + kh], emo_w2[(di + 32) * 128 + kh]);
    }
    if (tid < 128) s_b1[tid] = emo_b1[tid];
    if (tid < 64) s_b2[tid] = emo_b2[tid];
    __syncthreads();

    float* out_e = out + (size_t)3 * B_N * 64;
    const int r = (blockIdx.x * 4 + wrp) * 32 + lane;
    const size_t ro = (size_t)r * 64;

    ull th_p[32];
    load_row_pairs(theta + ro, th_p);

    ull e_acc[32];
#pragma unroll
    for (int di = 0; di < 32; di++) e_acc[di] = pack2(s_b2[di], s_b2[di + 32]);
#pragma unroll 1
    for (int og = 0; og < 16; og++) {
        const ulonglong2* w1v = (const ulonglong2*)(w1i + og * 256);
        ull a0 = 0, a1 = 0, a2 = 0, a3 = 0, a4 = 0, a5 = 0, a6 = 0, a7 = 0;
#pragma unroll
        for (int j = 0; j < 32; j++) {
            ulonglong2 p0 = w1v[j * 4 + 0], p1 = w1v[j * 4 + 1];
            ulonglong2 p2 = w1v[j * 4 + 2], p3 = w1v[j * 4 + 3];
            ull t = th_p[j];
            fma2(a0, p0.x, t); fma2(a1, p0.y, t);
            fma2(a2, p1.x, t); fma2(a3, p1.y, t);
            fma2(a4, p2.x, t); fma2(a5, p2.y, t);
            fma2(a6, p3.x, t); fma2(a7, p3.y, t);
        }
        float t8[8];
        t8[0] = ftanh(hadd2(a0) + s_b1[og * 8 + 0]);
        t8[1] = ftanh(hadd2(a1) + s_b1[og * 8 + 1]);
        t8[2] = ftanh(hadd2(a2) + s_b1[og * 8 + 2]);
        t8[3] = ftanh(hadd2(a3) + s_b1[og * 8 + 3]);
        t8[4] = ftanh(hadd2(a4) + s_b1[og * 8 + 4]);
        t8[5] = ftanh(hadd2(a5) + s_b1[og * 8 + 5]);
        t8[6] = ftanh(hadd2(a6) + s_b1[og * 8 + 6]);
        t8[7] = ftanh(hadd2(a7) + s_b1[og * 8 + 7]);
#pragma unroll
        for (int k = 0; k < 8; k++) {
            ull tt = pack2(t8[k], t8[k]);
            const ulonglong2* w2v = (const ulonglong2*)(w2i + (og * 8 + k) * 32);
#pragma unroll
            for (int di2 = 0; di2 < 16; di2++) {
                ulonglong2 q = w2v[di2];
                fma2(e_acc[di2 * 2 + 0], q.x, tt);
                fma2(e_acc[di2 * 2 + 1], q.y, tt);
            }
        }
    }
    float4* ep = (float4*)(out_e + ro);
#pragma unroll
    for (int k = 0; k < 8; k++) {
        float2 v0 = unpack2(e_acc[k * 4 + 0]);
        float2 v1 = unpack2(e_acc[k * 4 + 1]);
        float2 v2 = unpack2(e_acc[k * 4 + 2]);
        float2 v3 = unpack2(e_acc[k * 4 + 3]);
        ep[k]     = make_float4(fmaxf(v0.x, 0.f), fmaxf(v1.x, 0.f),
                                fmaxf(v2.x, 0.f), fmaxf(v3.x, 0.f));
        ep[8 + k] = make_float4(fmaxf(v0.y, 0.f), fmaxf(v1.y, 0.f),
                                fmaxf(v2.y, 0.f), fmaxf(v3.y, 0.f));
    }
}

// ---------------- kB2b: GRU e-part GEMM -> g_ge ; out_e += 0.001*stress ----------------
// wE[((dir*32 + d)*32 + j)*6 + s], s = g*2+hh -> output o = g*64+hh*32+d, pair (j, j+32)
#define B2B_WE  0        // 12288 ull = 24576 f
#define SMEM_B2B_BYTES (24580 * 4)

__global__ __launch_bounds__(128, 2)
void kB2b(const float* __restrict__ wih_f, const float* __restrict__ wih_r,
          float* __restrict__ out) {
    extern __shared__ float smem[];
    const int tid = threadIdx.x, lane = tid & 31, wrp = tid >> 5;
    ull* wE = (ull*)(smem + B2B_WE);
    float* s_stc = smem + 24576;

    for (int idx = tid; idx < 12288; idx += 128) {
        int s = idx % 6, t = idx / 6;
        int j = t & 31, d = (t >> 5) & 31, dirq = t >> 10;
        int o = (s >> 1) * 64 + (s & 1) * 32 + d;
        const float* w = dirq ? wih_r : wih_f;
        wE[idx] = pack2(w[o * 130 + 64 + j], w[o * 130 + 96 + j]);
    }
    if (tid == 0) {
        float s = 0.f;
        for (int b = 0; b < NPART; b++) s += g_part[b];
        s_stc[0] = 0.001f * s;
    }
    __syncthreads();
    const float stc = s_stc[0];

    float* out_e = out + (size_t)3 * B_N * 64;
    const int base = (blockIdx.x * 4 + wrp) * 64;
    const int r0 = base + lane, r1 = r0 + 32;

    ull e0_p[32], e1_p[32];
    load_row_pairs(out_e + (size_t)r0 * 64, e0_p);
    load_row_pairs(out_e + (size_t)r1 * 64, e1_p);

    // rewrite out_e with stress added (final e_theta)
    {
        float4* ep0 = (float4*)(out_e + (size_t)r0 * 64);
        float4* ep1 = (float4*)(out_e + (size_t)r1 * 64);
#pragma unroll
        for (int k = 0; k < 8; k++) {
            float2 a0 = unpack2(e0_p[k * 4 + 0]), a1 = unpack2(e0_p[k * 4 + 1]);
            float2 a2 = unpack2(e0_p[k * 4 + 2]), a3 = unpack2(e0_p[k * 4 + 3]);
            ep0[k]     = make_float4(a0.x + stc, a1.x + stc, a2.x + stc, a3.x + stc);
            ep0[8 + k] = make_float4(a0.y + stc, a1.y + stc, a2.y + stc, a3.y + stc);
            float2 b0 = unpack2(e1_p[k * 4 + 0]), b1 = unpack2(e1_p[k * 4 + 1]);
            float2 b2 = unpack2(e1_p[k * 4 + 2]), b3 = unpack2(e1_p[k * 4 + 3]);
            ep1[k]     = make_float4(b0.x + stc, b1.x + stc, b2.x + stc, b3.x + stc);
            ep1[8 + k] = make_float4(b0.y + stc, b1.y + stc, b2.y + stc, b3.y + stc);
        }
    }

#pragma unroll 1
    for (int d = 0; d < 32; d++) {
#pragma unroll 1
        for (int dirq = 0; dirq < 2; dirq++) {
            const ulonglong2* w = (const ulonglong2*)(wE + ((dirq * 32 + d) * 32) * 6);
            ull A0 = 0, A1 = 0, A2 = 0, A3 = 0, A4 = 0, A5 = 0;
            ull C0 = 0, C1 = 0, C2 = 0, C3 = 0, C4 = 0, C5 = 0;
#pragma unroll
            for (int j = 0; j < 32; j++) {
                ulonglong2 q0 = w[j * 3 + 0], q1 = w[j * 3 + 1], q2 = w[j * 3 + 2];
                ull e0 = e0_p[j], e1 = e1_p[j];
                fma2(A0, q0.x, e0); fma2(C0, q0.x, e1);
                fma2(A1, q0.y, e0); fma2(C1, q0.y, e1);
                fma2(A2, q1.x, e0); fma2(C2, q1.x, e1);
                fma2(A3, q1.y, e0); fma2(C3, q1.y, e1);
                fma2(A4, q2.x, e0); fma2(C4, q2.x, e1);
                fma2(A5, q2.y, e0); fma2(C5, q2.y, e1);
            }
            float* gb = g_ge + (size_t)dirq * 192 * B_N;
            gb[(size_t)(d) * B_N + r0]        = hadd2(A0);
            gb[(size_t)(32 + d) * B_N + r0]   = hadd2(A1);
            gb[(size_t)(64 + d) * B_N + r0]   = hadd2(A2);
            gb[(size_t)(96 + d) * B_N + r0]   = hadd2(A3);
            gb[(size_t)(128 + d) * B_N + r0]  = hadd2(A4);
            gb[(size_t)(160 + d) * B_N + r0]  = hadd2(A5);
            gb[(size_t)(d) * B_N + r1]        = hadd2(C0);
            gb[(size_t)(32 + d) * B_N + r1]   = hadd2(C1);
            gb[(size_t)(64 + d) * B_N + r1]   = hadd2(C2);
            gb[(size_t)(96 + d) * B_N + r1]   = hadd2(C3);
            gb[(size_t)(128 + d) * B_N + r1]  = hadd2(C4);
            gb[(size_t)(160 + d) * B_N + r1]  = hadd2(C5);
        }
    }
}

// ---------------- kC: fold GRU batch-constant terms ----------------
__global__ void kC(const float* __restrict__ w_ih_f, const float* __restrict__ b_ih_f,
                   const float* __restrict__ w_ih_r, const float* __restrict__ b_ih_r) {
    __shared__ float ss;
    int i = threadIdx.x;  // 192 threads
    if (i == 0) {
        float s = 0.f;
        for (int b = 0; b < NPART; b++) s += g_part[b];
        ss = s;
    }
    __syncthreads();
    float sc = 0.001f * ss;
    float af = b_ih_f[i], ar = b_ih_r[i], rf = 0.f, rr = 0.f;
    for (int j = 0; j < 64; j++) {
        float ov = g_o_vec[j];
        af += w_ih_f[i * 130 + j] * ov;
        ar += w_ih_r[i * 130 + j] * ov;
        rf += w_ih_f[i * 130 + 64 + j];
        rr += w_ih_r[i * 130 + 64 + j];
    }
    g_const_f[i] = af + sc * rf;
    g_const_r[i] = ar + sc * rr;
}

// ---------------- kD: GRU h-part + combine (dir split across blocks) ----------------
#define D_WH   0        // 6144 ull = 12288 f
#define D_CST  12288    // 192
#define D_RES  12480
#define D_OM   12672
#define D_BHH  12864
#define SMEM_D_BYTES (13060 * 4)

__global__ __launch_bounds__(128, 4)
void kD(const float* __restrict__ wih_f, const float* __restrict__ whh_f,
        const float* __restrict__ bhh_f,
        const float* __restrict__ wih_r, const float* __restrict__ whh_r,
        const float* __restrict__ bhh_r,
        const float* __restrict__ h_prev, const float* __restrict__ theta,
        float* __restrict__ out) {
    extern __shared__ float smem[];
    const int tid = threadIdx.x, lane = tid & 31, wrp = tid >> 5;
    const int dir = blockIdx.x >> 8, blk = blockIdx.x & 255;

    ull* wH = (ull*)(smem + D_WH);
    float* scst = smem + D_CST;
    float* sres = smem + D_RES;
    float* som  = smem + D_OM;
    float* sbhh = smem + D_BHH;

    const float* wih = dir ? wih_r : wih_f;
    const float* whh = dir ? whh_r : whh_f;
    const float* bhh = dir ? bhh_r : bhh_f;
    const float* cv  = dir ? g_const_r : g_const_f;

    for (int idx = tid; idx < 6144; idx += 128) {
        int s = idx % 6, t = idx / 6;
        int j = t & 31, d = t >> 5;
        int o = (s >> 1) * 64 + (s & 1) * 32 + d;
        wH[idx] = pack2(whh[o * 64 + j], whh[o * 64 + 32 + j]);
    }
    for (int i = tid; i < 192; i += 128) {
        scst[i] = cv[i];
        sres[i] = wih[i * 130 + 128];
        som[i]  = wih[i * 130 + 129];
        sbhh[i] = bhh[i];
    }
    __syncthreads();

    const float* hpd = h_prev + (size_t)dir * B_N * 64;
    const float* geb = g_ge + (size_t)dir * 192 * B_N;
    float* out_t = out;
    float* out_h = out + (size_t)(1 + dir) * B_N * 64;
    const float* out_rs = out + (size_t)4 * B_N * 64;
    const float* out_om = out_rs + B_N;

#pragma unroll 1
    for (int it = 0; it < 2; it++) {
        const int r = (blk * 4 + wrp) * 64 + it * 32 + lane;
        const size_t ro = (size_t)r * 64;

        ull h_p[32];
        load_row_pairs(hpd + ro, h_p);
        const float res = out_rs[r], om = out_om[r];

#pragma unroll 1
        for (int d = 0; d < 32; d++) {
            // issue ge loads early to overlap with the j-loop
            float ge0 = geb[(size_t)(d) * B_N + r];
            float ge1 = geb[(size_t)(32 + d) * B_N + r];
            float ge2 = geb[(size_t)(64 + d) * B_N + r];
            float ge3 = geb[(size_t)(96 + d) * B_N + r];
            float ge4 = geb[(size_t)(128 + d) * B_N + r];
            float ge5 = geb[(size_t)(160 + d) * B_N + r];

            const ulonglong2* w = (const ulonglong2*)(wH + (d * 32) * 6);
            ull B0 = 0, B1 = 0, B2 = 0, B3 = 0, B4 = 0, B5 = 0;
#pragma unroll
            for (int j = 0; j < 32; j++) {
                ulonglong2 q0 = w[j * 3 + 0], q1 = w[j * 3 + 1], q2 = w[j * 3 + 2];
                ull h = h_p[j];
                fma2(B0, q0.x, h); fma2(B1, q0.y, h);
                fma2(B2, q1.x, h); fma2(B3, q1.y, h);
                fma2(B4, q2.x, h); fma2(B5, q2.y, h);
            }
            float ir0 = ge0 + scst[d]       + res * sres[d]       + om * som[d];
            float ir1 = ge1 + scst[d + 32]  + res * sres[d + 32]  + om * som[d + 32];
            float iz0 = ge2 + scst[64 + d]  + res * sres[64 + d]  + om * som[64 + d];
            float iz1 = ge3 + scst[96 + d]  + res * sres[96 + d]  + om * som[96 + d];
            float in0 = ge4 + scst[128 + d] + res * sres[128 + d] + om * som[128 + d];
            float in1 = ge5 + scst[160 + d] + res * sres[160 + d] + om * som[160 + d];
            float hr0 = hadd2(B0) + sbhh[d];
            float hr1 = hadd2(B1) + sbhh[d + 32];
            float hz0 = hadd2(B2) + sbhh[64 + d];
            float hz1 = hadd2(B3) + sbhh[96 + d];
            float hn0 = hadd2(B4) + sbhh[128 + d];
            float hn1 = hadd2(B5) + sbhh[160 + d];

            float hv0 = hpd[ro + d], hv1 = hpd[ro + d + 32];
            float rg0 = sigm(ir0 + hr0), rg1 = sigm(ir1 + hr1);
            float zg0 = sigm(iz0 + hz0), zg1 = sigm(iz1 + hz1);
            float ng0 = ftanh(in0 + rg0 * hn0), ng1 = ftanh(in1 + rg1 * hn1);
            float o0 = (1.f - zg0) * ng0 + zg0 * hv0;
            float o1 = (1.f - zg1) * ng1 + zg1 * hv1;
            out_h[ro + d] = o0;
            out_h[ro + d + 32] = o1;
            if (dir == 0) {
                out_t[ro + d]      = 0.3f * theta[ro + d] + 0.7f * o0;
                out_t[ro + d + 32] = 0.3f * theta[ro + d + 32] + 0.7f * o1;
            }
        }
    }
}

extern "C" void kernel_launch(void* const* d_in, const int* in_sizes, int n_in,
                              void* d_out, int out_size) {
    const float* theta   = (const float*)d_in[0];
    const float* context = (const float*)d_in[1];
    const float* h_prev  = (const float*)d_in[2];
    const float* memory  = (const float*)d_in[3];
    const float* tw      = (const float*)d_in[4];
    const float* ipw     = (const float*)d_in[5];
    const float* ipb     = (const float*)d_in[6];
    const float* ow      = (const float*)d_in[7];
    const float* ob      = (const float*)d_in[8];
    const float* emo_w1  = (const float*)d_in[9];
    const float* emo_b1  = (const float*)d_in[10];
    const float* emo_w2  = (const float*)d_in[11];
    const float* emo_b2  = (const float*)d_in[12];
    const float* pe      = (const float*)d_in[13];
    const float* ctx_w   = (const float*)d_in[14];
    const float* ctx_b   = (const float*)d_in[15];
    const float* ideal_w = (const float*)d_in[16];
    const float* ideal_b = (const float*)d_in[17];
    const float* wih_f   = (const float*)d_in[18];
    const float* whh_f   = (const float*)d_in[19];
    const float* bhh_f   = (const float*)d_in[21];
    const float* wih_r   = (const float*)d_in[22];
    const float* whh_r   = (const float*)d_in[23];
    const float* bhh_r   = (const float*)d_in[25];
    const float* freq_w  = (const float*)d_in[26];
    const float* freq_b  = (const float*)d_in[27];
    const float* prev_i  = (const float*)d_in[28];
    const float* bih_f   = (const float*)d_in[20];
    const float* bih_r   = (const float*)d_in[24];
    float* out = (float*)d_out;

    static bool attr_set = false;
    if (!attr_set) {
        cudaFuncSetAttribute(kB1, cudaFuncAttributeMaxDynamicSharedMemorySize, SMEM_B1_BYTES);
        cudaFuncSetAttribute(kB2a, cudaFuncAttributeMaxDynamicSharedMemorySize, SMEM_B2A_BYTES);
        cudaFuncSetAttribute(kB2b, cudaFuncAttributeMaxDynamicSharedMemorySize, SMEM_B2B_BYTES);
        cudaFuncSetAttribute(kD, cudaFuncAttributeMaxDynamicSharedMemorySize, SMEM_D_BYTES);
        attr_set = true;
    }

    kA<<<1, 64>>>(memory, tw, ipw, ipb, ow, ob);
    kB1<<<256, 128, SMEM_B1_BYTES>>>(theta, context, ctx_w, ctx_b, ideal_w, ideal_b,
                                     pe, prev_i, freq_w, freq_b, out);
    kB2a<<<512, 128, SMEM_B2A_BYTES>>>(theta, emo_w1, emo_b1, emo_w2, emo_b2, out);
    kB2b<<<256, 128, SMEM_B2B_BYTES>>>(wih_f, wih_r, out);
    kC<<<1, 192>>>(wih_f, bih_f, wih_r, bih_r);
    kD<<<512, 128, SMEM_D_BYTES>>>(wih_f, whh_f, bhh_f, wih_r, whh_r, bhh_r,
                                   h_prev, theta, out);
}

// round 9
// speedup vs baseline: 1.4377x; 1.0129x over previous
#include <cuda_runtime.h>
#include <cstdint>

#define B_N   65536
#define CTXD  384
#define NPR   5
#define MEMV  10
#define EPSV  1e-8f
#define NPART 296

typedef unsigned long long ull;

__device__ float g_o_vec[64];
__device__ float g_part[NPART];
__device__ float g_const_f[192];
__device__ float g_const_r[192];
__device__ float g_ge[2u * 192u * B_N];   // GRU e-part pre-GEMM scratch

__device__ __forceinline__ ull pack2(float lo, float hi) {
    ull r; asm("mov.b64 %0,{%1,%2};" : "=l"(r) : "f"(lo), "f"(hi)); return r;
}
__device__ __forceinline__ float2 unpack2(ull v) {
    float2 f; asm("mov.b64 {%0,%1},%2;" : "=f"(f.x), "=f"(f.y) : "l"(v)); return f;
}
__device__ __forceinline__ void fma2(ull& acc, ull a, ull b) {
    asm("fma.rn.f32x2 %0,%1,%2,%0;" : "+l"(acc) : "l"(a), "l"(b));
}
__device__ __forceinline__ float hadd2(ull v) { float2 f = unpack2(v); return f.x + f.y; }
__device__ __forceinline__ float wsum(float v) {
#pragma unroll
    for (int o = 16; o; o >>= 1) v += __shfl_xor_sync(0xffffffffu, v, o);
    return v;
}
__device__ __forceinline__ float sigm(float x) { return __fdividef(1.0f, 1.0f + __expf(-x)); }
__device__ __forceinline__ float ftanh(float x) { return 1.0f - __fdividef(2.0f, 1.0f + __expf(2.0f * x)); }

// load a 64-float row as 32 (j, j+32) packed pairs
__device__ __forceinline__ void load_row_pairs(const float* p, ull* dst) {
    const float4* v = (const float4*)p;
#pragma unroll
    for (int k = 0; k < 8; k++) {
        float4 a = v[k], b = v[k + 8];
        dst[k * 4 + 0] = pack2(a.x, b.x);
        dst[k * 4 + 1] = pack2(a.y, b.y);
        dst[k * 4 + 2] = pack2(a.z, b.z);
        dst[k * 4 + 3] = pack2(a.w, b.w);
    }
}

// ---------------- kernel A: batch-constant MHA branch ----------------
__global__ void kA(const float* __restrict__ memory, const float* __restrict__ tw,
                   const float* __restrict__ ipw, const float* __restrict__ ipb,
                   const float* __restrict__ ow, const float* __restrict__ ob) {
    __shared__ float mt[64], vv[64];
    int d = threadIdx.x;  // 64 threads
    float a[MEMV], m = -1e30f, s = 0.f;
#pragma unroll
    for (int i = 0; i < MEMV; i++) { a[i] = tw[i]; m = fmaxf(m, a[i]); }
#pragma unroll
    for (int i = 0; i < MEMV; i++) { a[i] = __expf(a[i] - m); s += a[i]; }
    float inv = 1.f / s, acc = 0.f;
#pragma unroll
    for (int i = 0; i < MEMV; i++) acc += (a[i] * inv) * memory[i * 64 + d];
    mt[d] = acc;
    __syncthreads();
    float v = ipb[128 + d];
    for (int j = 0; j < 64; j++) v += mt[j] * ipw[(128 + d) * 64 + j];
    vv[d] = v;
    __syncthreads();
    float o = ob[d];
    for (int j = 0; j < 64; j++) o += vv[j] * ow[d * 64 + j];
    g_o_vec[d] = o;
}

// ---------------- kB1: ctx GEMM + prime softmax + scalars (2 rows/lane) ----------------
#define B1_WCTX 0        // 12288 ull
#define B1_IDWT 24576    // 160 ull
#define B1_IDWC 24896    // 160 ull
#define B1_PE   25216    // 160 ull
#define B1_PREV 25536    // 32 ull
#define B1_CTXB 25600    // 64 f
#define B1_IDB  25664    // 8
#define B1_PART 25672    // 4
#define SMEM_B1_BYTES (25680 * 4)

__global__ __launch_bounds__(128, 2)
void kB1(const float* __restrict__ theta, const float* __restrict__ context,
         const float* __restrict__ ctx_w, const float* __restrict__ ctx_b,
         const float* __restrict__ ideal_w, const float* __restrict__ ideal_b,
         const float* __restrict__ prime_embeds, const float* __restrict__ prev_ideal,
         const float* __restrict__ freq_w, const float* __restrict__ freq_b,
         float* __restrict__ out) {
    extern __shared__ float smem[];
    const int tid = threadIdx.x, lane = tid & 31, wrp = tid >> 5;

    ull* wctx = (ull*)(smem + B1_WCTX);
    ull* idwt = (ull*)(smem + B1_IDWT);
    ull* idwc = (ull*)(smem + B1_IDWC);
    ull* pe_s = (ull*)(smem + B1_PE);
    ull* prev_s = (ull*)(smem + B1_PREV);
    float* s_ctxb = smem + B1_CTXB;
    float* s_idb  = smem + B1_IDB;
    float* s_part = smem + B1_PART;

    for (int idx = tid; idx < 12288; idx += 128) {
        int dpi = idx & 15, k = (idx >> 4) % 384, p = idx / 6144;
        int d = p * 16 + dpi;
        wctx[idx] = pack2(ctx_w[d * 384 + k], ctx_w[(d + 32) * 384 + k]);
    }
    for (int idx = tid; idx < 160; idx += 128) {
        int p = idx >> 5, j = idx & 31;
        idwt[idx] = pack2(ideal_w[p * 128 + j], ideal_w[p * 128 + j + 32]);
        idwc[idx] = pack2(ideal_w[p * 128 + 64 + j], ideal_w[p * 128 + 96 + j]);
        pe_s[idx] = pack2(prime_embeds[p * 64 + j], prime_embeds[p * 64 + j + 32]);
    }
    if (tid < 32) prev_s[tid] = pack2(prev_ideal[tid], prev_ideal[tid + 32]);
    if (tid < 64) s_ctxb[tid] = ctx_b[tid];
    if (tid < NPR) s_idb[tid] = ideal_b[tid];
    __syncthreads();

    const float fwv = freq_w[0], fbv = freq_b[0];
    float* out_rs = out + (size_t)4 * B_N * 64;
    float* out_om = out_rs + B_N;
    float* out_pw = out_om + B_N;

    const int u = blockIdx.x * 4 + wrp;
    float stress_total = 0.f;
    if (u < 1024) {
        const int r0 = u * 64 + lane, r1 = r0 + 32;

        ull lgu[10];
#pragma unroll
        for (int i = 0; i < 10; i++) lgu[i] = 0;

        const float4* x0v = (const float4*)(context + (size_t)r0 * CTXD);
        const float4* x1v = (const float4*)(context + (size_t)r1 * CTXD);
#pragma unroll 1
        for (int p = 0; p < 2; p++) {
            ull cp[32];
#pragma unroll
            for (int dpi = 0; dpi < 16; dpi++) {
                ull b = pack2(s_ctxb[p * 16 + dpi], s_ctxb[p * 16 + dpi + 32]);
                cp[dpi * 2 + 0] = b;
                cp[dpi * 2 + 1] = b;
            }
#pragma unroll 1
            for (int k4 = 0; k4 < 96; k4++) {
                float4 a0 = x0v[k4], a1 = x1v[k4];
                float xs0[4] = {a0.x, a0.y, a0.z, a0.w};
                float xs1[4] = {a1.x, a1.y, a1.z, a1.w};
#pragma unroll
                for (int e = 0; e < 4; e++) {
                    ull xx0 = pack2(xs0[e], xs0[e]);
                    ull xx1 = pack2(xs1[e], xs1[e]);
                    const ulonglong2* w = (const ulonglong2*)(wctx + (p * 384 + k4 * 4 + e) * 16);
#pragma unroll
                    for (int q = 0; q < 8; q++) {
                        ulonglong2 ww = w[q];
                        fma2(cp[(2 * q) * 2 + 0], ww.x, xx0);
                        fma2(cp[(2 * q) * 2 + 1], ww.x, xx1);
                        fma2(cp[(2 * q + 1) * 2 + 0], ww.y, xx0);
                        fma2(cp[(2 * q + 1) * 2 + 1], ww.y, xx1);
                    }
                }
            }
#pragma unroll
            for (int p5 = 0; p5 < NPR; p5++)
#pragma unroll
                for (int dpi = 0; dpi < 16; dpi++) {
                    ull w = idwc[p5 * 32 + p * 16 + dpi];
                    fma2(lgu[p5 * 2 + 0], w, cp[dpi * 2 + 0]);
                    fma2(lgu[p5 * 2 + 1], w, cp[dpi * 2 + 1]);
                }
        }

        const float4* t0v = (const float4*)(theta + (size_t)r0 * 64);
        const float4* t1v = (const float4*)(theta + (size_t)r1 * 64);
#pragma unroll 1
        for (int cc = 0; cc < 2; cc++) {
            ull thc0[16], thc1[16];
#pragma unroll
            for (int k2 = 0; k2 < 4; k2++) {
                float4 a = t0v[cc * 4 + k2], b = t0v[cc * 4 + 8 + k2];
                thc0[k2 * 4 + 0] = pack2(a.x, b.x); thc0[k2 * 4 + 1] = pack2(a.y, b.y);
                thc0[k2 * 4 + 2] = pack2(a.z, b.z); thc0[k2 * 4 + 3] = pack2(a.w, b.w);
                float4 c = t1v[cc * 4 + k2], d = t1v[cc * 4 + 8 + k2];
                thc1[k2 * 4 + 0] = pack2(c.x, d.x); thc1[k2 * 4 + 1] = pack2(c.y, d.y);
                thc1[k2 * 4 + 2] = pack2(c.z, d.z); thc1[k2 * 4 + 3] = pack2(c.w, d.w);
            }
#pragma unroll
            for (int p5 = 0; p5 < NPR; p5++)
#pragma unroll
                for (int jj = 0; jj < 16; jj++) {
                    ull w = idwt[p5 * 32 + cc * 16 + jj];
                    fma2(lgu[p5 * 2 + 0], w, thc0[jj]);
                    fma2(lgu[p5 * 2 + 1], w, thc1[jj]);
                }
        }

        float pw0[NPR], pw1[NPR];
        {
            float lg0[NPR], lg1[NPR];
#pragma unroll
            for (int p = 0; p < NPR; p++) {
                lg0[p] = hadd2(lgu[p * 2 + 0]) + s_idb[p];
                lg1[p] = hadd2(lgu[p * 2 + 1]) + s_idb[p];
            }
            float m0 = lg0[0], m1 = lg1[0];
#pragma unroll
            for (int p = 1; p < NPR; p++) { m0 = fmaxf(m0, lg0[p]); m1 = fmaxf(m1, lg1[p]); }
            float s0 = 0.f, s1 = 0.f;
#pragma unroll
            for (int p = 0; p < NPR; p++) {
                pw0[p] = __expf(lg0[p] - m0); s0 += pw0[p];
                pw1[p] = __expf(lg1[p] - m1); s1 += pw1[p];
            }
            float i0 = __fdividef(1.f, s0), i1 = __fdividef(1.f, s1);
#pragma unroll
            for (int p = 0; p < NPR; p++) {
                pw0[p] *= i0; pw1[p] *= i1;
                out_pw[(size_t)r0 * NPR + p] = pw0[p];
                out_pw[(size_t)r1 * NPR + p] = pw1[p];
            }
        }

        float str0 = 0.f, nth0 = 0.f, nti0 = 0.f, rd0 = 0.f, f20 = 0.f;
        float str1 = 0.f, nth1 = 0.f, nti1 = 0.f, rd1 = 0.f, f21 = 0.f;
#pragma unroll 1
        for (int cc = 0; cc < 2; cc++) {
            ull thc0[16], thc1[16];
#pragma unroll
            for (int k2 = 0; k2 < 4; k2++) {
                float4 a = t0v[cc * 4 + k2], b = t0v[cc * 4 + 8 + k2];
                thc0[k2 * 4 + 0] = pack2(a.x, b.x); thc0[k2 * 4 + 1] = pack2(a.y, b.y);
                thc0[k2 * 4 + 2] = pack2(a.z, b.z); thc0[k2 * 4 + 3] = pack2(a.w, b.w);
                float4 c = t1v[cc * 4 + k2], d = t1v[cc * 4 + 8 + k2];
                thc1[k2 * 4 + 0] = pack2(c.x, d.x); thc1[k2 * 4 + 1] = pack2(c.y, d.y);
                thc1[k2 * 4 + 2] = pack2(c.z, d.z); thc1[k2 * 4 + 3] = pack2(c.w, d.w);
            }
#pragma unroll
            for (int jj = 0; jj < 16; jj++) {
                int j = cc * 16 + jj;
                float2 pv = unpack2(prev_s[j]);
                float2 pe0 = unpack2(pe_s[0 * 32 + j]);
                float2 pe1 = unpack2(pe_s[1 * 32 + j]);
                float2 pe2 = unpack2(pe_s[2 * 32 + j]);
                float2 pe3 = unpack2(pe_s[3 * 32 + j]);
                float2 pe4 = unpack2(pe_s[4 * 32 + j]);
                {
                    float tix = pw0[0] * pe0.x + pw0[1] * pe1.x + pw0[2] * pe2.x
                              + pw0[3] * pe3.x + pw0[4] * pe4.x;
                    float tiy = pw0[0] * pe0.y + pw0[1] * pe1.y + pw0[2] * pe2.y
                              + pw0[3] * pe3.y + pw0[4] * pe4.y;
                    float2 t = unpack2(thc0[jj]);
                    float dx = t.x - tix, dy = t.y - tiy;
                    str0 += dx * dx + dy * dy;
                    nth0 += t.x * t.x + t.y * t.y;
                    nti0 += tix * tix + tiy * tiy;
                    rd0  += t.x * tix + t.y * tiy;
                    float px = tix - pv.x, py = tiy - pv.y;
                    f20 += px * px + py * py;
                }
                {
                    float tix = pw1[0] * pe0.x + pw1[1] * pe1.x + pw1[2] * pe2.x
                              + pw1[3] * pe3.x + pw1[4] * pe4.x;
                    float tiy = pw1[0] * pe0.y + pw1[1] * pe1.y + pw1[2] * pe2.y
                              + pw1[3] * pe3.y + pw1[4] * pe4.y;
                    float2 t = unpack2(thc1[jj]);
                    float dx = t.x - tix, dy = t.y - tiy;
                    str1 += dx * dx + dy * dy;
                    nth1 += t.x * t.x + t.y * t.y;
                    nti1 += tix * tix + tiy * tiy;
                    rd1  += t.x * tix + t.y * tiy;
                    float px = tix - pv.x, py = tiy - pv.y;
                    f21 += px * px + py * py;
                }
            }
        }
        {
            float it0 = __fdividef(1.f, sqrtf(nth0) + EPSV);
            float ii0 = __fdividef(1.f, sqrtf(nti0) + EPSV);
            out_rs[r0] = __fdividef(rd0 * it0 * ii0,
                                    fmaxf(sqrtf(nth0) * it0 * sqrtf(nti0) * ii0, EPSV));
            float fr0 = sqrtf(f20);
            out_om[r0] = ftanh(fr0 * fwv + fbv) * (1.0f + 0.1f * __sinf(fr0));
            float it1 = __fdividef(1.f, sqrtf(nth1) + EPSV);
            float ii1 = __fdividef(1.f, sqrtf(nti1) + EPSV);
            out_rs[r1] = __fdividef(rd1 * it1 * ii1,
                                    fmaxf(sqrtf(nth1) * it1 * sqrtf(nti1) * ii1, EPSV));
            float fr1 = sqrtf(f21);
            out_om[r1] = ftanh(fr1 * fwv + fbv) * (1.0f + 0.1f * __sinf(fr1));
        }
        stress_total = str0 + str1;
    }

    float ws = wsum(stress_total);
    if (lane == 0) s_part[wrp] = ws;
    __syncthreads();
    if (tid == 0) {
        g_part[blockIdx.x] = (s_part[0] + s_part[1]) + (s_part[2] + s_part[3]);
    }
}

// ---------------- kB2a: emotion MLP (raw e -> out_e) ----------------
#define B2A_W1  0        // 4096 ull
#define B2A_W2  8192     // 4096 ull
#define B2A_B1  16384    // 128
#define B2A_B2  16512    // 64
#define SMEM_B2A_BYTES (16576 * 4)

__global__ __launch_bounds__(128, 3)
void kB2a(const float* __restrict__ theta,
          const float* __restrict__ emo_w1, const float* __restrict__ emo_b1,
          const float* __restrict__ emo_w2, const float* __restrict__ emo_b2,
          float* __restrict__ out) {
    extern __shared__ float smem[];
    const int tid = threadIdx.x, lane = tid & 31, wrp = tid >> 5;
    ull* w1i = (ull*)(smem + B2A_W1);
    ull* w2i = (ull*)(smem + B2A_W2);
    float* s_b1 = smem + B2A_B1;
    float* s_b2 = smem + B2A_B2;

    for (int idx = tid; idx < 4096; idx += 128) {
        int oi = idx & 7, j = (idx >> 3) & 31, og = idx >> 8;
        int o = og * 8 + oi;
        w1i[idx] = pack2(emo_w1[o * 64 + j], emo_w1[o * 64 + j + 32]);
    }
    for (int idx = tid; idx < 4096; idx += 128) {
        int di = idx & 31, kh = idx >> 5;
        w2i[idx] = pack2(emo_w2[di * 128 + kh], emo_w2[(di + 32) * 128 + kh]);
    }
    if (tid < 128) s_b1[tid] = emo_b1[tid];
    if (tid < 64) s_b2[tid] = emo_b2[tid];
    __syncthreads();

    float* out_e = out + (size_t)3 * B_N * 64;

#pragma unroll 1
    for (int u = blockIdx.x * 4 + wrp; u < 2048; u += 444 * 4) {
        const int r = u * 32 + lane;
        const size_t ro = (size_t)r * 64;

        ull th_p[32];
        load_row_pairs(theta + ro, th_p);

        ull e_acc[32];
#pragma unroll
        for (int di = 0; di < 32; di++) e_acc[di] = pack2(s_b2[di], s_b2[di + 32]);
#pragma unroll 1
        for (int og = 0; og < 16; og++) {
            const ulonglong2* w1v = (const ulonglong2*)(w1i + og * 256);
            ull a0 = 0, a1 = 0, a2 = 0, a3 = 0, a4 = 0, a5 = 0, a6 = 0, a7 = 0;
#pragma unroll
            for (int j = 0; j < 32; j++) {
                ulonglong2 p0 = w1v[j * 4 + 0], p1 = w1v[j * 4 + 1];
                ulonglong2 p2 = w1v[j * 4 + 2], p3 = w1v[j * 4 + 3];
                ull t = th_p[j];
                fma2(a0, p0.x, t); fma2(a1, p0.y, t);
                fma2(a2, p1.x, t); fma2(a3, p1.y, t);
                fma2(a4, p2.x, t); fma2(a5, p2.y, t);
                fma2(a6, p3.x, t); fma2(a7, p3.y, t);
            }
            float t8[8];
            t8[0] = ftanh(hadd2(a0) + s_b1[og * 8 + 0]);
            t8[1] = ftanh(hadd2(a1) + s_b1[og * 8 + 1]);
            t8[2] = ftanh(hadd2(a2) + s_b1[og * 8 + 2]);
            t8[3] = ftanh(hadd2(a3) + s_b1[og * 8 + 3]);
            t8[4] = ftanh(hadd2(a4) + s_b1[og * 8 + 4]);
            t8[5] = ftanh(hadd2(a5) + s_b1[og * 8 + 5]);
            t8[6] = ftanh(hadd2(a6) + s_b1[og * 8 + 6]);
            t8[7] = ftanh(hadd2(a7) + s_b1[og * 8 + 7]);
#pragma unroll
            for (int k = 0; k < 8; k++) {
                ull tt = pack2(t8[k], t8[k]);
                const ulonglong2* w2v = (const ulonglong2*)(w2i + (og * 8 + k) * 32);
#pragma unroll
                for (int di2 = 0; di2 < 16; di2++) {
                    ulonglong2 q = w2v[di2];
                    fma2(e_acc[di2 * 2 + 0], q.x, tt);
                    fma2(e_acc[di2 * 2 + 1], q.y, tt);
                }
            }
        }
        float4* ep = (float4*)(out_e + ro);
#pragma unroll
        for (int k = 0; k < 8; k++) {
            float2 v0 = unpack2(e_acc[k * 4 + 0]);
            float2 v1 = unpack2(e_acc[k * 4 + 1]);
            float2 v2 = unpack2(e_acc[k * 4 + 2]);
            float2 v3 = unpack2(e_acc[k * 4 + 3]);
            ep[k]     = make_float4(fmaxf(v0.x, 0.f), fmaxf(v1.x, 0.f),
                                    fmaxf(v2.x, 0.f), fmaxf(v3.x, 0.f));
            ep[8 + k] = make_float4(fmaxf(v0.y, 0.f), fmaxf(v1.y, 0.f),
                                    fmaxf(v2.y, 0.f), fmaxf(v3.y, 0.f));
        }
    }
}

// ---------------- kB2b: GRU e-part GEMM -> g_ge ; out_e += 0.001*stress ----------------
#define B2B_WE  0        // 12288 ull
#define SMEM_B2B_BYTES (24580 * 4)

__global__ __launch_bounds__(128, 2)
void kB2b(const float* __restrict__ wih_f, const float* __restrict__ wih_r,
          float* __restrict__ out) {
    extern __shared__ float smem[];
    const int tid = threadIdx.x, lane = tid & 31, wrp = tid >> 5;
    ull* wE = (ull*)(smem + B2B_WE);
    float* s_stc = smem + 24576;

    for (int idx = tid; idx < 12288; idx += 128) {
        int s = idx % 6, t = idx / 6;
        int j = t & 31, d = (t >> 5) & 31, dirq = t >> 10;
        int o = (s >> 1) * 64 + (s & 1) * 32 + d;
        const float* w = dirq ? wih_r : wih_f;
        wE[idx] = pack2(w[o * 130 + 64 + j], w[o * 130 + 96 + j]);
    }
    if (tid == 0) {
        float s = 0.f;
        for (int b = 0; b < NPART; b++) s += g_part[b];
        s_stc[0] = 0.001f * s;
    }
    __syncthreads();
    const int u = blockIdx.x * 4 + wrp;
    if (u >= 1024) return;
    const float stc = s_stc[0];

    float* out_e = out + (size_t)3 * B_N * 64;
    const int r0 = u * 64 + lane, r1 = r0 + 32;

    ull e0_p[32], e1_p[32];
    load_row_pairs(out_e + (size_t)r0 * 64, e0_p);
    load_row_pairs(out_e + (size_t)r1 * 64, e1_p);

    {
        float4* ep0 = (float4*)(out_e + (size_t)r0 * 64);
        float4* ep1 = (float4*)(out_e + (size_t)r1 * 64);
#pragma unroll
        for (int k = 0; k < 8; k++) {
            float2 a0 = unpack2(e0_p[k * 4 + 0]), a1 = unpack2(e0_p[k * 4 + 1]);
            float2 a2 = unpack2(e0_p[k * 4 + 2]), a3 = unpack2(e0_p[k * 4 + 3]);
            ep0[k]     = make_float4(a0.x + stc, a1.x + stc, a2.x + stc, a3.x + stc);
            ep0[8 + k] = make_float4(a0.y + stc, a1.y + stc, a2.y + stc, a3.y + stc);
            float2 b0 = unpack2(e1_p[k * 4 + 0]), b1 = unpack2(e1_p[k * 4 + 1]);
            float2 b2 = unpack2(e1_p[k * 4 + 2]), b3 = unpack2(e1_p[k * 4 + 3]);
            ep1[k]     = make_float4(b0.x + stc, b1.x + stc, b2.x + stc, b3.x + stc);
            ep1[8 + k] = make_float4(b0.y + stc, b1.y + stc, b2.y + stc, b3.y + stc);
        }
    }

#pragma unroll 1
    for (int d = 0; d < 32; d++) {
#pragma unroll 1
        for (int dirq = 0; dirq < 2; dirq++) {
            const ulonglong2* w = (const ulonglong2*)(wE + ((dirq * 32 + d) * 32) * 6);
            ull A0 = 0, A1 = 0, A2 = 0, A3 = 0, A4 = 0, A5 = 0;
            ull C0 = 0, C1 = 0, C2 = 0, C3 = 0, C4 = 0, C5 = 0;
#pragma unroll
            for (int j = 0; j < 32; j++) {
                ulonglong2 q0 = w[j * 3 + 0], q1 = w[j * 3 + 1], q2 = w[j * 3 + 2];
                ull e0 = e0_p[j], e1 = e1_p[j];
                fma2(A0, q0.x, e0); fma2(C0, q0.x, e1);
                fma2(A1, q0.y, e0); fma2(C1, q0.y, e1);
                fma2(A2, q1.x, e0); fma2(C2, q1.x, e1);
                fma2(A3, q1.y, e0); fma2(C3, q1.y, e1);
                fma2(A4, q2.x, e0); fma2(C4, q2.x, e1);
                fma2(A5, q2.y, e0); fma2(C5, q2.y, e1);
            }
            float* gb = g_ge + (size_t)dirq * 192 * B_N;
            gb[(size_t)(d) * B_N + r0]        = hadd2(A0);
            gb[(size_t)(32 + d) * B_N + r0]   = hadd2(A1);
            gb[(size_t)(64 + d) * B_N + r0]   = hadd2(A2);
            gb[(size_t)(96 + d) * B_N + r0]   = hadd2(A3);
            gb[(size_t)(128 + d) * B_N + r0]  = hadd2(A4);
            gb[(size_t)(160 + d) * B_N + r0]  = hadd2(A5);
            gb[(size_t)(d) * B_N + r1]        = hadd2(C0);
            gb[(size_t)(32 + d) * B_N + r1]   = hadd2(C1);
            gb[(size_t)(64 + d) * B_N + r1]   = hadd2(C2);
            gb[(size_t)(96 + d) * B_N + r1]   = hadd2(C3);
            gb[(size_t)(128 + d) * B_N + r1]  = hadd2(C4);
            gb[(size_t)(160 + d) * B_N + r1]  = hadd2(C5);
        }
    }
}

// ---------------- kC: fold GRU batch-constant terms ----------------
__global__ void kC(const float* __restrict__ w_ih_f, const float* __restrict__ b_ih_f,
                   const float* __restrict__ w_ih_r, const float* __restrict__ b_ih_r) {
    __shared__ float ss;
    int i = threadIdx.x;  // 192 threads
    if (i == 0) {
        float s = 0.f;
        for (int b = 0; b < NPART; b++) s += g_part[b];
        ss = s;
    }
    __syncthreads();
    float sc = 0.001f * ss;
    float af = b_ih_f[i], ar = b_ih_r[i], rf = 0.f, rr = 0.f;
    for (int j = 0; j < 64; j++) {
        float ov = g_o_vec[j];
        af += w_ih_f[i * 130 + j] * ov;
        ar += w_ih_r[i * 130 + j] * ov;
        rf += w_ih_f[i * 130 + 64 + j];
        rr += w_ih_r[i * 130 + 64 + j];
    }
    g_const_f[i] = af + sc * rf;
    g_const_r[i] = ar + sc * rr;
}

// ---------------- kD: GRU h-part + combine (2 rows/lane, both dirs) ----------------
// wH[((dir*32 + d)*32 + j)*6 + s]  s = g*2+hh -> output o = g*64+hh*32+d, pair (j, j+32)
#define D_WH   0        // 12288 ull = 24576 f
#define D_CST  24576    // 384
#define D_RES  24960    // 384
#define D_OM   25344    // 384
#define D_BHH  25728    // 384
#define SMEM_D_BYTES (26112 * 4)

__global__ __launch_bounds__(128, 2)
void kD(const float* __restrict__ wih_f, const float* __restrict__ whh_f,
        const float* __restrict__ bhh_f,
        const float* __restrict__ wih_r, const float* __restrict__ whh_r,
        const float* __restrict__ bhh_r,
        const float* __restrict__ h_prev, const float* __restrict__ theta,
        float* __restrict__ out) {
    extern __shared__ float smem[];
    const int tid = threadIdx.x, lane = tid & 31, wrp = tid >> 5;

    ull* wH = (ull*)(smem + D_WH);
    float* scst = smem + D_CST;
    float* sres = smem + D_RES;
    float* som  = smem + D_OM;
    float* sbhh = smem + D_BHH;

    for (int idx = tid; idx < 12288; idx += 128) {
        int s = idx % 6, t = idx / 6;
        int j = t & 31, d = (t >> 5) & 31, dir = t >> 10;
        int o = (s >> 1) * 64 + (s & 1) * 32 + d;
        const float* whh = dir ? whh_r : whh_f;
        wH[idx] = pack2(whh[o * 64 + j], whh[o * 64 + 32 + j]);
    }
    for (int i = tid; i < 192; i += 128) {
        scst[i] = g_const_f[i];         scst[192 + i] = g_const_r[i];
        sres[i] = wih_f[i * 130 + 128]; sres[192 + i] = wih_r[i * 130 + 128];
        som[i]  = wih_f[i * 130 + 129]; som[192 + i]  = wih_r[i * 130 + 129];
        sbhh[i] = bhh_f[i];             sbhh[192 + i] = bhh_r[i];
    }
    __syncthreads();

    const int u = blockIdx.x * 4 + wrp;
    if (u >= 1024) return;

    float* out_t = out;
    const float* out_rs = out + (size_t)4 * B_N * 64;
    const float* out_om = out_rs + B_N;

    const int r0 = u * 64 + lane, r1 = r0 + 32;
    const size_t ro0 = (size_t)r0 * 64, ro1 = (size_t)r1 * 64;
    const float res0 = out_rs[r0], om0 = out_om[r0];
    const float res1 = out_rs[r1], om1 = out_om[r1];

#pragma unroll 1
    for (int dir = 0; dir < 2; dir++) {
        const float* hpd = h_prev + (size_t)dir * B_N * 64;
        const float* geb = g_ge + (size_t)dir * 192 * B_N;
        float* out_h = out + (size_t)(1 + dir) * B_N * 64;
        const int c0 = dir * 192;

        ull h0_p[32], h1_p[32];
        load_row_pairs(hpd + ro0, h0_p);
        load_row_pairs(hpd + ro1, h1_p);

#pragma unroll 1
        for (int d = 0; d < 32; d++) {
            float ga0 = geb[(size_t)(d) * B_N + r0];
            float ga1 = geb[(size_t)(32 + d) * B_N + r0];
            float ga2 = geb[(size_t)(64 + d) * B_N + r0];
            float ga3 = geb[(size_t)(96 + d) * B_N + r0];
            float ga4 = geb[(size_t)(128 + d) * B_N + r0];
            float ga5 = geb[(size_t)(160 + d) * B_N + r0];
            float gc0 = geb[(size_t)(d) * B_N + r1];
            float gc1 = geb[(size_t)(32 + d) * B_N + r1];
            float gc2 = geb[(size_t)(64 + d) * B_N + r1];
            float gc3 = geb[(size_t)(96 + d) * B_N + r1];
            float gc4 = geb[(size_t)(128 + d) * B_N + r1];
            float gc5 = geb[(size_t)(160 + d) * B_N + r1];

            const ulonglong2* w = (const ulonglong2*)(wH + ((dir * 32 + d) * 32) * 6);
            ull A0 = 0, A1 = 0, A2 = 0, A3 = 0, A4 = 0, A5 = 0;
            ull C0 = 0, C1 = 0, C2 = 0, C3 = 0, C4 = 0, C5 = 0;
#pragma unroll
            for (int j = 0; j < 32; j++) {
                ulonglong2 q0 = w[j * 3 + 0], q1 = w[j * 3 + 1], q2 = w[j * 3 + 2];
                ull h0 = h0_p[j], h1 = h1_p[j];
                fma2(A0, q0.x, h0); fma2(C0, q0.x, h1);
                fma2(A1, q0.y, h0); fma2(C1, q0.y, h1);
                fma2(A2, q1.x, h0); fma2(C2, q1.x, h1);
                fma2(A3, q1.y, h0); fma2(C3, q1.y, h1);
                fma2(A4, q2.x, h0); fma2(C4, q2.x, h1);
                fma2(A5, q2.y, h0); fma2(C5, q2.y, h1);
            }
            float cr0 = scst[c0 + d]       + res0 * sres[c0 + d]       + om0 * som[c0 + d];
            float cr1 = scst[c0 + d + 32]  + res0 * sres[c0 + d + 32]  + om0 * som[c0 + d + 32];
            float cz0 = scst[c0 + 64 + d]  + res0 * sres[c0 + 64 + d]  + om0 * som[c0 + 64 + d];
            float cz1 = scst[c0 + 96 + d]  + res0 * sres[c0 + 96 + d]  + om0 * som[c0 + 96 + d];
            float cn0 = scst[c0 + 128 + d] + res0 * sres[c0 + 128 + d] + om0 * som[c0 + 128 + d];
            float cn1 = scst[c0 + 160 + d] + res0 * sres[c0 + 160 + d] + om0 * som[c0 + 160 + d];
            float dr0 = scst[c0 + d]       + res1 * sres[c0 + d]       + om1 * som[c0 + d];
            float dr1 = scst[c0 + d + 32]  + res1 * sres[c0 + d + 32]  + om1 * som[c0 + d + 32];
            float dz0 = scst[c0 + 64 + d]  + res1 * sres[c0 + 64 + d]  + om1 * som[c0 + 64 + d];
            float dz1 = scst[c0 + 96 + d]  + res1 * sres[c0 + 96 + d]  + om1 * som[c0 + 96 + d];
            float dn0 = scst[c0 + 128 + d] + res1 * sres[c0 + 128 + d] + om1 * som[c0 + 128 + d];
            float dn1 = scst[c0 + 160 + d] + res1 * sres[c0 + 160 + d] + om1 * som[c0 + 160 + d];

            // row 0
            {
                float hr0 = hadd2(A0) + sbhh[c0 + d];
                float hr1 = hadd2(A1) + sbhh[c0 + d + 32];
                float hz0 = hadd2(A2) + sbhh[c0 + 64 + d];
                float hz1 = hadd2(A3) + sbhh[c0 + 96 + d];
                float hn0 = hadd2(A4) + sbhh[c0 + 128 + d];
                float hn1 = hadd2(A5) + sbhh[c0 + 160 + d];
                float hv0 = hpd[ro0 + d], hv1 = hpd[ro0 + d + 32];
                float rg0 = sigm(ga0 + cr0 + hr0), rg1 = sigm(ga1 + cr1 + hr1);
                float zg0 = sigm(ga2 + cz0 + hz0), zg1 = sigm(ga3 + cz1 + hz1);
                float ng0 = ftanh(ga4 + cn0 + rg0 * hn0), ng1 = ftanh(ga5 + cn1 + rg1 * hn1);
                float o0 = (1.f - zg0) * ng0 + zg0 * hv0;
                float o1 = (1.f - zg1) * ng1 + zg1 * hv1;
                out_h[ro0 + d] = o0;
                out_h[ro0 + d + 32] = o1;
                if (dir == 0) {
                    out_t[ro0 + d]      = 0.3f * theta[ro0 + d] + 0.7f * o0;
                    out_t[ro0 + d + 32] = 0.3f * theta[ro0 + d + 32] + 0.7f * o1;
                }
            }
            // row 1
            {
                float hr0 = hadd2(C0) + sbhh[c0 + d];
                float hr1 = hadd2(C1) + sbhh[c0 + d + 32];
                float hz0 = hadd2(C2) + sbhh[c0 + 64 + d];
                float hz1 = hadd2(C3) + sbhh[c0 + 96 + d];
                float hn0 = hadd2(C4) + sbhh[c0 + 128 + d];
                float hn1 = hadd2(C5) + sbhh[c0 + 160 + d];
                float hv0 = hpd[ro1 + d], hv1 = hpd[ro1 + d + 32];
                float rg0 = sigm(gc0 + dr0 + hr0), rg1 = sigm(gc1 + dr1 + hr1);
                float zg0 = sigm(gc2 + dz0 + hz0), zg1 = sigm(gc3 + dz1 + hz1);
                float ng0 = ftanh(gc4 + dn0 + rg0 * hn0), ng1 = ftanh(gc5 + dn1 + rg1 * hn1);
                float o0 = (1.f - zg0) * ng0 + zg0 * hv0;
                float o1 = (1.f - zg1) * ng1 + zg1 * hv1;
                out_h[ro1 + d] = o0;
                out_h[ro1 + d + 32] = o1;
                if (dir == 0) {
                    out_t[ro1 + d]      = 0.3f * theta[ro1 + d] + 0.7f * o0;
                    out_t[ro1 + d + 32] = 0.3f * theta[ro1 + d + 32] + 0.7f * o1;
                }
            }
        }
    }
}

extern "C" void kernel_launch(void* const* d_in, const int* in_sizes, int n_in,
                              void* d_out, int out_size) {
    const float* theta   = (const float*)d_in[0];
    const float* context = (const float*)d_in[1];
    const float* h_prev  = (const float*)d_in[2];
    const float* memory  = (const float*)d_in[3];
    const float* tw      = (const float*)d_in[4];
    const float* ipw     = (const float*)d_in[5];
    const float* ipb     = (const float*)d_in[6];
    const float* ow      = (const float*)d_in[7];
    const float* ob      = (const float*)d_in[8];
    const float* emo_w1  = (const float*)d_in[9];
    const float* emo_b1  = (const float*)d_in[10];
    const float* emo_w2  = (const float*)d_in[11];
    const float* emo_b2  = (const float*)d_in[12];
    const float* pe      = (const float*)d_in[13];
    const float* ctx_w   = (const float*)d_in[14];
    const float* ctx_b   = (const float*)d_in[15];
    const float* ideal_w = (const float*)d_in[16];
    const float* ideal_b = (const float*)d_in[17];
    const float* wih_f   = (const float*)d_in[18];
    const float* whh_f   = (const float*)d_in[19];
    const float* bih_f   = (const float*)d_in[20];
    const float* bhh_f   = (const float*)d_in[21];
    const float* wih_r   = (const float*)d_in[22];
    const float* whh_r   = (const float*)d_in[23];
    const float* bih_r   = (const float*)d_in[24];
    const float* bhh_r   = (const float*)d_in[25];
    const float* freq_w  = (const float*)d_in[26];
    const float* freq_b  = (const float*)d_in[27];
    const float* prev_i  = (const float*)d_in[28];
    float* out = (float*)d_out;

    static bool attr_set = false;
    if (!attr_set) {
        cudaFuncSetAttribute(kB1, cudaFuncAttributeMaxDynamicSharedMemorySize, SMEM_B1_BYTES);
        cudaFuncSetAttribute(kB2a, cudaFuncAttributeMaxDynamicSharedMemorySize, SMEM_B2A_BYTES);
        cudaFuncSetAttribute(kB2b, cudaFuncAttributeMaxDynamicSharedMemorySize, SMEM_B2B_BYTES);
        cudaFuncSetAttribute(kD, cudaFuncAttributeMaxDynamicSharedMemorySize, SMEM_D_BYTES);
        attr_set = true;
    }

    kA<<<1, 64>>>(memory, tw, ipw, ipb, ow, ob);
    kB1<<<296, 128, SMEM_B1_BYTES>>>(theta, context, ctx_w, ctx_b, ideal_w, ideal_b,
                                     pe, prev_i, freq_w, freq_b, out);
    kB2a<<<444, 128, SMEM_B2A_BYTES>>>(theta, emo_w1, emo_b1, emo_w2, emo_b2, out);
    kB2b<<<296, 128, SMEM_B2B_BYTES>>>(wih_f, wih_r, out);
    kC<<<1, 192>>>(wih_f, bih_f, wih_r, bih_r);
    kD<<<296, 128, SMEM_D_BYTES>>>(wih_f, whh_f, bhh_f, wih_r, whh_r, bhh_r,
                                   h_prev, theta, out);
}

// round 11
// speedup vs baseline: 1.5529x; 1.0801x over previous
#include <cuda_runtime.h>
#include <cstdint>

#define B_N   65536
#define CTXD  384
#define NPR   5
#define MEMV  10
#define EPSV  1e-8f
#define NPART 296

typedef unsigned long long ull;

__device__ float g_part[NPART];
__device__ float g_const_f[192];
__device__ float g_const_r[192];

__device__ __forceinline__ ull pack2(float lo, float hi) {
    ull r; asm("mov.b64 %0,{%1,%2};" : "=l"(r) : "f"(lo), "f"(hi)); return r;
}
__device__ __forceinline__ float2 unpack2(ull v) {
    float2 f; asm("mov.b64 {%0,%1},%2;" : "=f"(f.x), "=f"(f.y) : "l"(v)); return f;
}
__device__ __forceinline__ void fma2(ull& acc, ull a, ull b) {
    asm("fma.rn.f32x2 %0,%1,%2,%0;" : "+l"(acc) : "l"(a), "l"(b));
}
__device__ __forceinline__ float hadd2(ull v) { float2 f = unpack2(v); return f.x + f.y; }
__device__ __forceinline__ float wsum(float v) {
#pragma unroll
    for (int o = 16; o; o >>= 1) v += __shfl_xor_sync(0xffffffffu, v, o);
    return v;
}
__device__ __forceinline__ float sigm(float x) { return __fdividef(1.0f, 1.0f + __expf(-x)); }
__device__ __forceinline__ float ftanh(float x) { return 1.0f - __fdividef(2.0f, 1.0f + __expf(2.0f * x)); }

// load a 64-float row as 32 (j, j+32) packed pairs
__device__ __forceinline__ void load_row_pairs(const float* p, ull* dst) {
    const float4* v = (const float4*)p;
#pragma unroll
    for (int k = 0; k < 8; k++) {
        float4 a = v[k], b = v[k + 8];
        dst[k * 4 + 0] = pack2(a.x, b.x);
        dst[k * 4 + 1] = pack2(a.y, b.y);
        dst[k * 4 + 2] = pack2(a.z, b.z);
        dst[k * 4 + 3] = pack2(a.w, b.w);
    }
}

// load HALF a row (K-pairs kh*16 .. kh*16+15) as 16 packed pairs
__device__ __forceinline__ void load_half_pairs(const float* p, int kh, ull* dst) {
    const float4* v = (const float4*)p;
#pragma unroll
    for (int q = 0; q < 4; q++) {
        float4 a = v[kh * 4 + q], b = v[kh * 4 + 8 + q];
        dst[q * 4 + 0] = pack2(a.x, b.x);
        dst[q * 4 + 1] = pack2(a.y, b.y);
        dst[q * 4 + 2] = pack2(a.z, b.z);
        dst[q * 4 + 3] = pack2(a.w, b.w);
    }
}

// ---------------- kA: batch-constant MHA branch + GRU constant fold ----------------
__global__ void kA(const float* __restrict__ memory, const float* __restrict__ tw,
                   const float* __restrict__ ipw, const float* __restrict__ ipb,
                   const float* __restrict__ ow, const float* __restrict__ ob,
                   const float* __restrict__ wih_f, const float* __restrict__ bih_f,
                   const float* __restrict__ wih_r, const float* __restrict__ bih_r) {
    __shared__ float mt[64], vv[64], ov[64];
    int t = threadIdx.x;  // 192 threads
    if (t < 64) {
        float a[MEMV], m = -1e30f, s = 0.f;
#pragma unroll
        for (int i = 0; i < MEMV; i++) { a[i] = tw[i]; m = fmaxf(m, a[i]); }
#pragma unroll
        for (int i = 0; i < MEMV; i++) { a[i] = __expf(a[i] - m); s += a[i]; }
        float inv = 1.f / s, acc = 0.f;
#pragma unroll
        for (int i = 0; i < MEMV; i++) acc += (a[i] * inv) * memory[i * 64 + t];
        mt[t] = acc;
    }
    __syncthreads();
    if (t < 64) {
        float v = ipb[128 + t];
        for (int j = 0; j < 64; j++) v += mt[j] * ipw[(128 + t) * 64 + j];
        vv[t] = v;
    }
    __syncthreads();
    if (t < 64) {
        float o = ob[t];
        for (int j = 0; j < 64; j++) o += vv[j] * ow[t * 64 + j];
        ov[t] = o;
    }
    __syncthreads();
    // fold: g_const = b_ih + W_ih[:, :64] @ o_vec
    float af = bih_f[t], ar = bih_r[t];
    for (int j = 0; j < 64; j++) {
        float o = ov[j];
        af += wih_f[t * 130 + j] * o;
        ar += wih_r[t * 130 + j] * o;
    }
    g_const_f[t] = af;
    g_const_r[t] = ar;
}

// ---------------- kB1: ctx GEMM + prime softmax + scalars (2 rows/lane) ----------------
#define B1_WCTX 0        // 12288 ull
#define B1_IDWT 24576    // 160 ull
#define B1_IDWC 24896    // 160 ull
#define B1_PE   25216    // 160 ull
#define B1_PREV 25536    // 32 ull
#define B1_CTXB 25600    // 64 f
#define B1_IDB  25664    // 8
#define B1_PART 25672    // 4
#define SMEM_B1_BYTES (25680 * 4)

__global__ __launch_bounds__(128, 2)
void kB1(const float* __restrict__ theta, const float* __restrict__ context,
         const float* __restrict__ ctx_w, const float* __restrict__ ctx_b,
         const float* __restrict__ ideal_w, const float* __restrict__ ideal_b,
         const float* __restrict__ prime_embeds, const float* __restrict__ prev_ideal,
         const float* __restrict__ freq_w, const float* __restrict__ freq_b,
         float* __restrict__ out) {
    extern __shared__ float smem[];
    const int tid = threadIdx.x, lane = tid & 31, wrp = tid >> 5;

    ull* wctx = (ull*)(smem + B1_WCTX);
    ull* idwt = (ull*)(smem + B1_IDWT);
    ull* idwc = (ull*)(smem + B1_IDWC);
    ull* pe_s = (ull*)(smem + B1_PE);
    ull* prev_s = (ull*)(smem + B1_PREV);
    float* s_ctxb = smem + B1_CTXB;
    float* s_idb  = smem + B1_IDB;
    float* s_part = smem + B1_PART;

    for (int idx = tid; idx < 12288; idx += 128) {
        int dpi = idx & 15, k = (idx >> 4) % 384, p = idx / 6144;
        int d = p * 16 + dpi;
        wctx[idx] = pack2(ctx_w[d * 384 + k], ctx_w[(d + 32) * 384 + k]);
    }
    for (int idx = tid; idx < 160; idx += 128) {
        int p = idx >> 5, j = idx & 31;
        idwt[idx] = pack2(ideal_w[p * 128 + j], ideal_w[p * 128 + j + 32]);
        idwc[idx] = pack2(ideal_w[p * 128 + 64 + j], ideal_w[p * 128 + 96 + j]);
        pe_s[idx] = pack2(prime_embeds[p * 64 + j], prime_embeds[p * 64 + j + 32]);
    }
    if (tid < 32) prev_s[tid] = pack2(prev_ideal[tid], prev_ideal[tid + 32]);
    if (tid < 64) s_ctxb[tid] = ctx_b[tid];
    if (tid < NPR) s_idb[tid] = ideal_b[tid];
    __syncthreads();

    const float fwv = freq_w[0], fbv = freq_b[0];
    float* out_rs = out + (size_t)4 * B_N * 64;
    float* out_om = out_rs + B_N;
    float* out_pw = out_om + B_N;

    const int u = blockIdx.x * 4 + wrp;
    float stress_total = 0.f;
    if (u < 1024) {
        const int r0 = u * 64 + lane, r1 = r0 + 32;

        ull lgu[10];
#pragma unroll
        for (int i = 0; i < 10; i++) lgu[i] = 0;

        const float4* x0v = (const float4*)(context + (size_t)r0 * CTXD);
        const float4* x1v = (const float4*)(context + (size_t)r1 * CTXD);
#pragma unroll 1
        for (int p = 0; p < 2; p++) {
            ull cp[32];
#pragma unroll
            for (int dpi = 0; dpi < 16; dpi++) {
                ull b = pack2(s_ctxb[p * 16 + dpi], s_ctxb[p * 16 + dpi + 32]);
                cp[dpi * 2 + 0] = b;
                cp[dpi * 2 + 1] = b;
            }
#pragma unroll 1
            for (int k4 = 0; k4 < 96; k4++) {
                float4 a0 = x0v[k4], a1 = x1v[k4];
                float xs0[4] = {a0.x, a0.y, a0.z, a0.w};
                float xs1[4] = {a1.x, a1.y, a1.z, a1.w};
#pragma unroll
                for (int e = 0; e < 4; e++) {
                    ull xx0 = pack2(xs0[e], xs0[e]);
                    ull xx1 = pack2(xs1[e], xs1[e]);
                    const ulonglong2* w = (const ulonglong2*)(wctx + (p * 384 + k4 * 4 + e) * 16);
#pragma unroll
                    for (int q = 0; q < 8; q++) {
                        ulonglong2 ww = w[q];
                        fma2(cp[(2 * q) * 2 + 0], ww.x, xx0);
                        fma2(cp[(2 * q) * 2 + 1], ww.x, xx1);
                        fma2(cp[(2 * q + 1) * 2 + 0], ww.y, xx0);
                        fma2(cp[(2 * q + 1) * 2 + 1], ww.y, xx1);
                    }
                }
            }
#pragma unroll
            for (int p5 = 0; p5 < NPR; p5++)
#pragma unroll
                for (int dpi = 0; dpi < 16; dpi++) {
                    ull w = idwc[p5 * 32 + p * 16 + dpi];
                    fma2(lgu[p5 * 2 + 0], w, cp[dpi * 2 + 0]);
                    fma2(lgu[p5 * 2 + 1], w, cp[dpi * 2 + 1]);
                }
        }

        ull th0[32], th1[32];
        load_row_pairs(theta + (size_t)r0 * 64, th0);
        load_row_pairs(theta + (size_t)r1 * 64, th1);
#pragma unroll
        for (int p5 = 0; p5 < NPR; p5++)
#pragma unroll
            for (int j = 0; j < 32; j++) {
                ull w = idwt[p5 * 32 + j];
                fma2(lgu[p5 * 2 + 0], w, th0[j]);
                fma2(lgu[p5 * 2 + 1], w, th1[j]);
            }

        float pw0[NPR], pw1[NPR];
        {
            float lg0[NPR], lg1[NPR];
#pragma unroll
            for (int p = 0; p < NPR; p++) {
                lg0[p] = hadd2(lgu[p * 2 + 0]) + s_idb[p];
                lg1[p] = hadd2(lgu[p * 2 + 1]) + s_idb[p];
            }
            float m0 = lg0[0], m1 = lg1[0];
#pragma unroll
            for (int p = 1; p < NPR; p++) { m0 = fmaxf(m0, lg0[p]); m1 = fmaxf(m1, lg1[p]); }
            float s0 = 0.f, s1 = 0.f;
#pragma unroll
            for (int p = 0; p < NPR; p++) {
                pw0[p] = __expf(lg0[p] - m0); s0 += pw0[p];
                pw1[p] = __expf(lg1[p] - m1); s1 += pw1[p];
            }
            float i0 = __fdividef(1.f, s0), i1 = __fdividef(1.f, s1);
#pragma unroll
            for (int p = 0; p < NPR; p++) {
                pw0[p] *= i0; pw1[p] *= i1;
                out_pw[(size_t)r0 * NPR + p] = pw0[p];
                out_pw[(size_t)r1 * NPR + p] = pw1[p];
            }
        }

        float str0 = 0.f, nth0 = 0.f, nti0 = 0.f, rd0 = 0.f, f20 = 0.f;
        float str1 = 0.f, nth1 = 0.f, nti1 = 0.f, rd1 = 0.f, f21 = 0.f;
#pragma unroll
        for (int j = 0; j < 32; j++) {
            float2 pv = unpack2(prev_s[j]);
            float2 pe0 = unpack2(pe_s[0 * 32 + j]);
            float2 pe1 = unpack2(pe_s[1 * 32 + j]);
            float2 pe2 = unpack2(pe_s[2 * 32 + j]);
            float2 pe3 = unpack2(pe_s[3 * 32 + j]);
            float2 pe4 = unpack2(pe_s[4 * 32 + j]);
            {
                float tix = pw0[0] * pe0.x + pw0[1] * pe1.x + pw0[2] * pe2.x
                          + pw0[3] * pe3.x + pw0[4] * pe4.x;
                float tiy = pw0[0] * pe0.y + pw0[1] * pe1.y + pw0[2] * pe2.y
                          + pw0[3] * pe3.y + pw0[4] * pe4.y;
                float2 t = unpack2(th0[j]);
                float dx = t.x - tix, dy = t.y - tiy;
                str0 += dx * dx + dy * dy;
                nth0 += t.x * t.x + t.y * t.y;
                nti0 += tix * tix + tiy * tiy;
                rd0  += t.x * tix + t.y * tiy;
                float px = tix - pv.x, py = tiy - pv.y;
                f20 += px * px + py * py;
            }
            {
                float tix = pw1[0] * pe0.x + pw1[1] * pe1.x + pw1[2] * pe2.x
                          + pw1[3] * pe3.x + pw1[4] * pe4.x;
                float tiy = pw1[0] * pe0.y + pw1[1] * pe1.y + pw1[2] * pe2.y
                          + pw1[3] * pe3.y + pw1[4] * pe4.y;
                float2 t = unpack2(th1[j]);
                float dx = t.x - tix, dy = t.y - tiy;
                str1 += dx * dx + dy * dy;
                nth1 += t.x * t.x + t.y * t.y;
                nti1 += tix * tix + tiy * tiy;
                rd1  += t.x * tix + t.y * tiy;
                float px = tix - pv.x, py = tiy - pv.y;
                f21 += px * px + py * py;
            }
        }
        {
            float it0 = __fdividef(1.f, sqrtf(nth0) + EPSV);
            float ii0 = __fdividef(1.f, sqrtf(nti0) + EPSV);
            out_rs[r0] = __fdividef(rd0 * it0 * ii0,
                                    fmaxf(sqrtf(nth0) * it0 * sqrtf(nti0) * ii0, EPSV));
            float fr0 = sqrtf(f20);
            out_om[r0] = ftanh(fr0 * fwv + fbv) * (1.0f + 0.1f * __sinf(fr0));
            float it1 = __fdividef(1.f, sqrtf(nth1) + EPSV);
            float ii1 = __fdividef(1.f, sqrtf(nti1) + EPSV);
            out_rs[r1] = __fdividef(rd1 * it1 * ii1,
                                    fmaxf(sqrtf(nth1) * it1 * sqrtf(nti1) * ii1, EPSV));
            float fr1 = sqrtf(f21);
            out_om[r1] = ftanh(fr1 * fwv + fbv) * (1.0f + 0.1f * __sinf(fr1));
        }
        stress_total = str0 + str1;
    }

    float ws = wsum(stress_total);
    if (lane == 0) s_part[wrp] = ws;
    __syncthreads();
    if (tid == 0) {
        g_part[blockIdx.x] = (s_part[0] + s_part[1]) + (s_part[2] + s_part[3]);
    }
}

// ---------------- kB2a: emotion MLP -> out_e = relu(..) + 0.001*stress (FINAL e_theta) ----------------
#define B2A_W1  0        // 4096 ull
#define B2A_W2  8192     // 4096 ull
#define B2A_B1  16384    // 128
#define B2A_B2  16512    // 64
#define B2A_STC 16576    // 1
#define SMEM_B2A_BYTES (16580 * 4)

__global__ __launch_bounds__(128, 3)
void kB2a(const float* __restrict__ theta,
          const float* __restrict__ emo_w1, const float* __restrict__ emo_b1,
          const float* __restrict__ emo_w2, const float* __restrict__ emo_b2,
          float* __restrict__ out) {
    extern __shared__ float smem[];
    const int tid = threadIdx.x, lane = tid & 31, wrp = tid >> 5;
    ull* w1i = (ull*)(smem + B2A_W1);
    ull* w2i = (ull*)(smem + B2A_W2);
    float* s_b1 = smem + B2A_B1;
    float* s_b2 = smem + B2A_B2;
    float* s_stc = smem + B2A_STC;

    for (int idx = tid; idx < 4096; idx += 128) {
        int oi = idx & 7, j = (idx >> 3) & 31, og = idx >> 8;
        int o = og * 8 + oi;
        w1i[idx] = pack2(emo_w1[o * 64 + j], emo_w1[o * 64 + j + 32]);
    }
    for (int idx = tid; idx < 4096; idx += 128) {
        int di = idx & 31, kh = idx >> 5;
        w2i[idx] = pack2(emo_w2[di * 128 + kh], emo_w2[(di + 32) * 128 + kh]);
    }
    if (tid < 128) s_b1[tid] = emo_b1[tid];
    if (tid < 64) s_b2[tid] = emo_b2[tid];
    if (tid == 0) {
        float s = 0.f;
        for (int b = 0; b < NPART; b++) s += g_part[b];
        s_stc[0] = 0.001f * s;
    }
    __syncthreads();
    const float stc = s_stc[0];

    float* out_e = out + (size_t)3 * B_N * 64;

#pragma unroll 1
    for (int u = blockIdx.x * 4 + wrp; u < 2048; u += 444 * 4) {
        const int r = u * 32 + lane;
        const size_t ro = (size_t)r * 64;

        ull th_p[32];
        load_row_pairs(theta + ro, th_p);

        ull e_acc[32];
#pragma unroll
        for (int di = 0; di < 32; di++) e_acc[di] = pack2(s_b2[di], s_b2[di + 32]);
#pragma unroll 1
        for (int og = 0; og < 16; og++) {
            const ulonglong2* w1v = (const ulonglong2*)(w1i + og * 256);
            ull a0 = 0, a1 = 0, a2 = 0, a3 = 0, a4 = 0, a5 = 0, a6 = 0, a7 = 0;
#pragma unroll
            for (int j = 0; j < 32; j++) {
                ulonglong2 p0 = w1v[j * 4 + 0], p1 = w1v[j * 4 + 1];
                ulonglong2 p2 = w1v[j * 4 + 2], p3 = w1v[j * 4 + 3];
                ull t = th_p[j];
                fma2(a0, p0.x, t); fma2(a1, p0.y, t);
                fma2(a2, p1.x, t); fma2(a3, p1.y, t);
                fma2(a4, p2.x, t); fma2(a5, p2.y, t);
                fma2(a6, p3.x, t); fma2(a7, p3.y, t);
            }
            float t8[8];
            t8[0] = ftanh(hadd2(a0) + s_b1[og * 8 + 0]);
            t8[1] = ftanh(hadd2(a1) + s_b1[og * 8 + 1]);
            t8[2] = ftanh(hadd2(a2) + s_b1[og * 8 + 2]);
            t8[3] = ftanh(hadd2(a3) + s_b1[og * 8 + 3]);
            t8[4] = ftanh(hadd2(a4) + s_b1[og * 8 + 4]);
            t8[5] = ftanh(hadd2(a5) + s_b1[og * 8 + 5]);
            t8[6] = ftanh(hadd2(a6) + s_b1[og * 8 + 6]);
            t8[7] = ftanh(hadd2(a7) + s_b1[og * 8 + 7]);
#pragma unroll
            for (int k = 0; k < 8; k++) {
                ull tt = pack2(t8[k], t8[k]);
                const ulonglong2* w2v = (const ulonglong2*)(w2i + (og * 8 + k) * 32);
#pragma unroll
                for (int di2 = 0; di2 < 16; di2++) {
                    ulonglong2 q = w2v[di2];
                    fma2(e_acc[di2 * 2 + 0], q.x, tt);
                    fma2(e_acc[di2 * 2 + 1], q.y, tt);
                }
            }
        }
        float4* ep = (float4*)(out_e + ro);
#pragma unroll
        for (int k = 0; k < 8; k++) {
            float2 v0 = unpack2(e_acc[k * 4 + 0]);
            float2 v1 = unpack2(e_acc[k * 4 + 1]);
            float2 v2 = unpack2(e_acc[k * 4 + 2]);
            float2 v3 = unpack2(e_acc[k * 4 + 3]);
            ep[k]     = make_float4(fmaxf(v0.x, 0.f) + stc, fmaxf(v1.x, 0.f) + stc,
                                    fmaxf(v2.x, 0.f) + stc, fmaxf(v3.x, 0.f) + stc);
            ep[8 + k] = make_float4(fmaxf(v0.y, 0.f) + stc, fmaxf(v1.y, 0.f) + stc,
                                    fmaxf(v2.y, 0.f) + stc, fmaxf(v3.y, 0.f) + stc);
        }
    }
}

// ---------------- kDF: fused GRU (e-GEMM + h-GEMM + gates), half-warp K-split ----------------
// wEH[((d*32 + j)*12 + s]: s 0..5 e-weights (r lo, r hi, z lo, z hi, n lo, n hi),
//                          s 6..11 h-weights. K-pair (j, j+32). One dir per block.
#define DF_W   0         // 12288 ull = 24576 f
#define DF_CST 24576     // 192
#define DF_RES 24768     // 192
#define DF_OM  24960     // 192
#define DF_BHH 25152     // 192
#define SMEM_DF_BYTES (25344 * 4)

__global__ __launch_bounds__(256, 2)
void kDF(const float* __restrict__ wih_f, const float* __restrict__ whh_f,
         const float* __restrict__ bhh_f,
         const float* __restrict__ wih_r, const float* __restrict__ whh_r,
         const float* __restrict__ bhh_r,
         const float* __restrict__ h_prev, const float* __restrict__ theta,
         float* __restrict__ out) {
    extern __shared__ float smem[];
    const int tid = threadIdx.x, lane = tid & 31, wrp = tid >> 5;
    const int dir = blockIdx.x & 1, ublk = blockIdx.x >> 1;
    const int kh = lane >> 4, ln = lane & 15;

    ull* wEH = (ull*)(smem + DF_W);
    float* scst = smem + DF_CST;
    float* sres = smem + DF_RES;
    float* som  = smem + DF_OM;
    float* sbhh = smem + DF_BHH;

    const float* wih = dir ? wih_r : wih_f;
    const float* whh = dir ? whh_r : whh_f;
    const float* bhh = dir ? bhh_r : bhh_f;

    for (int idx = tid; idx < 12288; idx += 256) {
        int s = idx % 12, t = idx / 12;
        int j = t & 31, d = t >> 5;
        int g = (s >= 6) ? s - 6 : s;
        int o = (g >> 1) * 64 + (g & 1) * 32 + d;
        wEH[idx] = (s < 6) ? pack2(wih[o * 130 + 64 + j], wih[o * 130 + 96 + j])
                           : pack2(whh[o * 64 + j], whh[o * 64 + 32 + j]);
    }
    for (int i = tid; i < 192; i += 256) {
        scst[i] = dir ? g_const_r[i] : g_const_f[i];
        sres[i] = wih[i * 130 + 128];
        som[i]  = wih[i * 130 + 129];
        sbhh[i] = bhh[i];
    }
    __syncthreads();

    const float* hpd = h_prev + (size_t)dir * B_N * 64;
    const float* out_e = out + (size_t)3 * B_N * 64;
    const float* out_rs = out + (size_t)4 * B_N * 64;
    const float* out_om = out_rs + B_N;
    float* out_t = out;
    float* out_h = out + (size_t)(1 + dir) * B_N * 64;

#pragma unroll 1
    for (int u = ublk; u < 512; u += 296) {
        const int r = u * 128 + wrp * 16 + ln;
        const size_t ro = (size_t)r * 64;

        ull e_p[16], h_p[16];
        load_half_pairs(out_e + ro, kh, e_p);
        load_half_pairs(hpd + ro, kh, h_p);
        const float res = out_rs[r], om = out_om[r];

#pragma unroll 1
        for (int d = 0; d < 32; d++) {
            const ulonglong2* w = (const ulonglong2*)(wEH + (size_t)(d * 32 + kh * 16) * 12);
            ull A0 = 0, A1 = 0, A2 = 0, A3 = 0, A4 = 0, A5 = 0;
            ull B0 = 0, B1 = 0, B2 = 0, B3 = 0, B4 = 0, B5 = 0;
#pragma unroll
            for (int jj = 0; jj < 16; jj++) {
                ulonglong2 q0 = w[jj * 6 + 0], q1 = w[jj * 6 + 1], q2 = w[jj * 6 + 2];
                ulonglong2 q3 = w[jj * 6 + 3], q4 = w[jj * 6 + 4], q5 = w[jj * 6 + 5];
                ull e = e_p[jj], h = h_p[jj];
                fma2(A0, q0.x, e); fma2(A1, q0.y, e);
                fma2(A2, q1.x, e); fma2(A3, q1.y, e);
                fma2(A4, q2.x, e); fma2(A5, q2.y, e);
                fma2(B0, q3.x, h); fma2(B1, q3.y, h);
                fma2(B2, q4.x, h); fma2(B3, q4.y, h);
                fma2(B4, q5.x, h); fma2(B5, q5.y, h);
            }
            // cross-half combine
            float a0 = hadd2(A0); a0 += __shfl_xor_sync(0xffffffffu, a0, 16);
            float a1 = hadd2(A1); a1 += __shfl_xor_sync(0xffffffffu, a1, 16);
            float a2 = hadd2(A2); a2 += __shfl_xor_sync(0xffffffffu, a2, 16);
            float a3 = hadd2(A3); a3 += __shfl_xor_sync(0xffffffffu, a3, 16);
            float a4 = hadd2(A4); a4 += __shfl_xor_sync(0xffffffffu, a4, 16);
            float a5 = hadd2(A5); a5 += __shfl_xor_sync(0xffffffffu, a5, 16);
            float b0 = hadd2(B0); b0 += __shfl_xor_sync(0xffffffffu, b0, 16);
            float b1 = hadd2(B1); b1 += __shfl_xor_sync(0xffffffffu, b1, 16);
            float b2 = hadd2(B2); b2 += __shfl_xor_sync(0xffffffffu, b2, 16);
            float b3 = hadd2(B3); b3 += __shfl_xor_sync(0xffffffffu, b3, 16);
            float b4 = hadd2(B4); b4 += __shfl_xor_sync(0xffffffffu, b4, 16);
            float b5 = hadd2(B5); b5 += __shfl_xor_sync(0xffffffffu, b5, 16);

            if (kh == 0) {
                float ir0 = a0 + scst[d]       + res * sres[d]       + om * som[d];
                float ir1 = a1 + scst[d + 32]  + res * sres[d + 32]  + om * som[d + 32];
                float iz0 = a2 + scst[64 + d]  + res * sres[64 + d]  + om * som[64 + d];
                float iz1 = a3 + scst[96 + d]  + res * sres[96 + d]  + om * som[96 + d];
                float in0 = a4 + scst[128 + d] + res * sres[128 + d] + om * som[128 + d];
                float in1 = a5 + scst[160 + d] + res * sres[160 + d] + om * som[160 + d];
                float hr0 = b0 + sbhh[d];
                float hr1 = b1 + sbhh[d + 32];
                float hz0 = b2 + sbhh[64 + d];
                float hz1 = b3 + sbhh[96 + d];
                float hn0 = b4 + sbhh[128 + d];
                float hn1 = b5 + sbhh[160 + d];

                float hv0 = hpd[ro + d], hv1 = hpd[ro + d + 32];
                float rg0 = sigm(ir0 + hr0), rg1 = sigm(ir1 + hr1);
                float zg0 = sigm(iz0 + hz0), zg1 = sigm(iz1 + hz1);
                float ng0 = ftanh(in0 + rg0 * hn0), ng1 = ftanh(in1 + rg1 * hn1);
                float o0 = (1.f - zg0) * ng0 + zg0 * hv0;
                float o1 = (1.f - zg1) * ng1 + zg1 * hv1;
                out_h[ro + d] = o0;
                out_h[ro + d + 32] = o1;
                if (dir == 0) {
                    out_t[ro + d]      = 0.3f * theta[ro + d] + 0.7f * o0;
                    out_t[ro + d + 32] = 0.3f * theta[ro + d + 32] + 0.7f * o1;
                }
            }
        }
    }
}

extern "C" void kernel_launch(void* const* d_in, const int* in_sizes, int n_in,
                              void* d_out, int out_size) {
    const float* theta   = (const float*)d_in[0];
    const float* context = (const float*)d_in[1];
    const float* h_prev  = (const float*)d_in[2];
    const float* memory  = (const float*)d_in[3];
    const float* tw      = (const float*)d_in[4];
    const float* ipw     = (const float*)d_in[5];
    const float* ipb     = (const float*)d_in[6];
    const float* ow      = (const float*)d_in[7];
    const float* ob      = (const float*)d_in[8];
    const float* emo_w1  = (const float*)d_in[9];
    const float* emo_b1  = (const float*)d_in[10];
    const float* emo_w2  = (const float*)d_in[11];
    const float* emo_b2  = (const float*)d_in[12];
    const float* pe      = (const float*)d_in[13];
    const float* ctx_w   = (const float*)d_in[14];
    const float* ctx_b   = (const float*)d_in[15];
    const float* ideal_w = (const float*)d_in[16];
    const float* ideal_b = (const float*)d_in[17];
    const float* wih_f   = (const float*)d_in[18];
    const float* whh_f   = (const float*)d_in[19];
    const float* bih_f   = (const float*)d_in[20];
    const float* bhh_f   = (const float*)d_in[21];
    const float* wih_r   = (const float*)d_in[22];
    const float* whh_r   = (const float*)d_in[23];
    const float* bih_r   = (const float*)d_in[24];
    const float* bhh_r   = (const float*)d_in[25];
    const float* freq_w  = (const float*)d_in[26];
    const float* freq_b  = (const float*)d_in[27];
    const float* prev_i  = (const float*)d_in[28];
    float* out = (float*)d_out;

    static bool attr_set = false;
    if (!attr_set) {
        cudaFuncSetAttribute(kB1, cudaFuncAttributeMaxDynamicSharedMemorySize, SMEM_B1_BYTES);
        cudaFuncSetAttribute(kB2a, cudaFuncAttributeMaxDynamicSharedMemorySize, SMEM_B2A_BYTES);
        cudaFuncSetAttribute(kDF, cudaFuncAttributeMaxDynamicSharedMemorySize, SMEM_DF_BYTES);
        attr_set = true;
    }

    kA<<<1, 192>>>(memory, tw, ipw, ipb, ow, ob, wih_f, bih_f, wih_r, bih_r);
    kB1<<<296, 128, SMEM_B1_BYTES>>>(theta, context, ctx_w, ctx_b, ideal_w, ideal_b,
                                     pe, prev_i, freq_w, freq_b, out);
    kB2a<<<444, 128, SMEM_B2A_BYTES>>>(theta, emo_w1, emo_b1, emo_w2, emo_b2, out);
    kDF<<<592, 256, SMEM_DF_BYTES>>>(wih_f, whh_f, bhh_f, wih_r, whh_r, bhh_r,
                                     h_prev, theta, out);
}

// round 12
// speedup vs baseline: 1.9259x; 1.2402x over previous
#include <cuda_runtime.h>
#include <cstdint>

#define B_N   65536
#define CTXD  384
#define NPR   5
#define MEMV  10
#define EPSV  1e-8f
#define NPART 296

typedef unsigned long long ull;

__device__ float g_part[NPART];
__device__ float g_const_f[192];
__device__ float g_const_r[192];
__device__ float g_M[NPR * CTXD];
__device__ float g_lb[NPR];

__device__ __forceinline__ ull pack2(float lo, float hi) {
    ull r; asm("mov.b64 %0,{%1,%2};" : "=l"(r) : "f"(lo), "f"(hi)); return r;
}
__device__ __forceinline__ float2 unpack2(ull v) {
    float2 f; asm("mov.b64 {%0,%1},%2;" : "=f"(f.x), "=f"(f.y) : "l"(v)); return f;
}
__device__ __forceinline__ void fma2(ull& acc, ull a, ull b) {
    asm("fma.rn.f32x2 %0,%1,%2,%0;" : "+l"(acc) : "l"(a), "l"(b));
}
__device__ __forceinline__ float hadd2(ull v) { float2 f = unpack2(v); return f.x + f.y; }
__device__ __forceinline__ float wsum(float v) {
#pragma unroll
    for (int o = 16; o; o >>= 1) v += __shfl_xor_sync(0xffffffffu, v, o);
    return v;
}
__device__ __forceinline__ float sigm(float x) { return __fdividef(1.0f, 1.0f + __expf(-x)); }
__device__ __forceinline__ float ftanh(float x) { return 1.0f - __fdividef(2.0f, 1.0f + __expf(2.0f * x)); }

__device__ __forceinline__ void load_row_pairs(const float* p, ull* dst) {
    const float4* v = (const float4*)p;
#pragma unroll
    for (int k = 0; k < 8; k++) {
        float4 a = v[k], b = v[k + 8];
        dst[k * 4 + 0] = pack2(a.x, b.x);
        dst[k * 4 + 1] = pack2(a.y, b.y);
        dst[k * 4 + 2] = pack2(a.z, b.z);
        dst[k * 4 + 3] = pack2(a.w, b.w);
    }
}

__device__ __forceinline__ void load_half_pairs(const float* p, int kh, ull* dst) {
    const float4* v = (const float4*)p;
#pragma unroll
    for (int q = 0; q < 4; q++) {
        float4 a = v[kh * 4 + q], b = v[kh * 4 + 8 + q];
        dst[q * 4 + 0] = pack2(a.x, b.x);
        dst[q * 4 + 1] = pack2(a.y, b.y);
        dst[q * 4 + 2] = pack2(a.z, b.z);
        dst[q * 4 + 3] = pack2(a.w, b.w);
    }
}

// ---------------- kA: batch-constant MHA branch + GRU constant fold ----------------
__global__ void kA(const float* __restrict__ memory, const float* __restrict__ tw,
                   const float* __restrict__ ipw, const float* __restrict__ ipb,
                   const float* __restrict__ ow, const float* __restrict__ ob,
                   const float* __restrict__ wih_f, const float* __restrict__ bih_f,
                   const float* __restrict__ wih_r, const float* __restrict__ bih_r) {
    __shared__ float mt[64], vv[64], ov[64];
    int t = threadIdx.x;  // 192 threads
    if (t < 64) {
        float a[MEMV], m = -1e30f, s = 0.f;
#pragma unroll
        for (int i = 0; i < MEMV; i++) { a[i] = tw[i]; m = fmaxf(m, a[i]); }
#pragma unroll
        for (int i = 0; i < MEMV; i++) { a[i] = __expf(a[i] - m); s += a[i]; }
        float inv = 1.f / s, acc = 0.f;
#pragma unroll
        for (int i = 0; i < MEMV; i++) acc += (a[i] * inv) * memory[i * 64 + t];
        mt[t] = acc;
    }
    __syncthreads();
    if (t < 64) {
        float v = ipb[128 + t];
        for (int j = 0; j < 64; j++) v += mt[j] * ipw[(128 + t) * 64 + j];
        vv[t] = v;
    }
    __syncthreads();
    if (t < 64) {
        float o = ob[t];
        for (int j = 0; j < 64; j++) o += vv[j] * ow[t * 64 + j];
        ov[t] = o;
    }
    __syncthreads();
    float af = bih_f[t], ar = bih_r[t];
    for (int j = 0; j < 64; j++) {
        float o = ov[j];
        af += wih_f[t * 130 + j] * o;
        ar += wih_r[t * 130 + j] * o;
    }
    g_const_f[t] = af;
    g_const_r[t] = ar;
}

// ---------------- kM: fold ctx GEMM into logit matrix M = idw_c @ ctx_w ----------------
__global__ void kM(const float* __restrict__ ideal_w, const float* __restrict__ ideal_b,
                   const float* __restrict__ ctx_w, const float* __restrict__ ctx_b) {
    int idx = blockIdx.x * 128 + threadIdx.x;
    if (idx < NPR * CTXD) {
        int p = idx / CTXD, k = idx - p * CTXD;
        float s = 0.f;
        for (int d = 0; d < 64; d++)
            s += ideal_w[p * 128 + 64 + d] * ctx_w[d * CTXD + k];
        g_M[idx] = s;
    }
    if (idx < NPR) {
        float s = ideal_b[idx];
        for (int d = 0; d < 64; d++)
            s += ideal_w[idx * 128 + 64 + d] * ctx_b[d];
        g_lb[idx] = s;
    }
}

// ---------------- kB1: prime logits (via M) + softmax + scalars (2 rows/lane) ----------------
#define B1_M    0        // 1920 f
#define B1_IDWT 1920     // 160 ull = 320 f
#define B1_PE   2240     // 160 ull
#define B1_PREV 2560     // 32 ull
#define B1_LB   2624     // 8
#define B1_PART 2632     // 4
#define SMEM_B1_BYTES (2640 * 4)

__global__ __launch_bounds__(128, 2)
void kB1(const float* __restrict__ theta, const float* __restrict__ context,
         const float* __restrict__ ideal_w,
         const float* __restrict__ prime_embeds, const float* __restrict__ prev_ideal,
         const float* __restrict__ freq_w, const float* __restrict__ freq_b,
         float* __restrict__ out) {
    extern __shared__ float smem[];
    const int tid = threadIdx.x, lane = tid & 31, wrp = tid >> 5;

    float* Ms = smem + B1_M;
    ull* idwt = (ull*)(smem + B1_IDWT);
    ull* pe_s = (ull*)(smem + B1_PE);
    ull* prev_s = (ull*)(smem + B1_PREV);
    float* s_lb = smem + B1_LB;
    float* s_part = smem + B1_PART;

    for (int idx = tid; idx < NPR * CTXD; idx += 128) Ms[idx] = g_M[idx];
    for (int idx = tid; idx < 160; idx += 128) {
        int p = idx >> 5, j = idx & 31;
        idwt[idx] = pack2(ideal_w[p * 128 + j], ideal_w[p * 128 + j + 32]);
        pe_s[idx] = pack2(prime_embeds[p * 64 + j], prime_embeds[p * 64 + j + 32]);
    }
    if (tid < 32) prev_s[tid] = pack2(prev_ideal[tid], prev_ideal[tid + 32]);
    if (tid < NPR) s_lb[tid] = g_lb[tid];
    __syncthreads();

    const float fwv = freq_w[0], fbv = freq_b[0];
    float* out_rs = out + (size_t)4 * B_N * 64;
    float* out_om = out_rs + B_N;
    float* out_pw = out_om + B_N;

    const int u = blockIdx.x * 4 + wrp;
    float stress_total = 0.f;
    if (u < 1024) {
        const int r0 = u * 64 + lane, r1 = r0 + 32;

        // ---- logits: ctx part via M (exactly folded) ----
        float lg0[NPR], lg1[NPR];
#pragma unroll
        for (int p = 0; p < NPR; p++) { lg0[p] = s_lb[p]; lg1[p] = s_lb[p]; }
        const float4* x0v = (const float4*)(context + (size_t)r0 * CTXD);
        const float4* x1v = (const float4*)(context + (size_t)r1 * CTXD);
#pragma unroll 4
        for (int k4 = 0; k4 < 96; k4++) {
            float4 a0 = x0v[k4], a1 = x1v[k4];
#pragma unroll
            for (int p = 0; p < NPR; p++) {
                float4 m = ((const float4*)(Ms + p * CTXD))[k4];
                lg0[p] += m.x * a0.x + m.y * a0.y + m.z * a0.z + m.w * a0.w;
                lg1[p] += m.x * a1.x + m.y * a1.y + m.z * a1.z + m.w * a1.w;
            }
        }

        // ---- theta part ----
        ull th0[32], th1[32];
        load_row_pairs(theta + (size_t)r0 * 64, th0);
        load_row_pairs(theta + (size_t)r1 * 64, th1);
#pragma unroll
        for (int p5 = 0; p5 < NPR; p5++) {
            ull a = 0, b = 0;
#pragma unroll
            for (int j = 0; j < 32; j++) {
                ull w = idwt[p5 * 32 + j];
                fma2(a, w, th0[j]);
                fma2(b, w, th1[j]);
            }
            lg0[p5] += hadd2(a);
            lg1[p5] += hadd2(b);
        }

        // ---- softmax ----
        float pw0[NPR], pw1[NPR];
        {
            float m0 = lg0[0], m1 = lg1[0];
#pragma unroll
            for (int p = 1; p < NPR; p++) { m0 = fmaxf(m0, lg0[p]); m1 = fmaxf(m1, lg1[p]); }
            float s0 = 0.f, s1 = 0.f;
#pragma unroll
            for (int p = 0; p < NPR; p++) {
                pw0[p] = __expf(lg0[p] - m0); s0 += pw0[p];
                pw1[p] = __expf(lg1[p] - m1); s1 += pw1[p];
            }
            float i0 = __fdividef(1.f, s0), i1 = __fdividef(1.f, s1);
#pragma unroll
            for (int p = 0; p < NPR; p++) {
                pw0[p] *= i0; pw1[p] *= i1;
                out_pw[(size_t)r0 * NPR + p] = pw0[p];
                out_pw[(size_t)r1 * NPR + p] = pw1[p];
            }
        }

        // ---- scalar pass: stress / res / omega ----
        float str0 = 0.f, nth0 = 0.f, nti0 = 0.f, rd0 = 0.f, f20 = 0.f;
        float str1 = 0.f, nth1 = 0.f, nti1 = 0.f, rd1 = 0.f, f21 = 0.f;
#pragma unroll
        for (int j = 0; j < 32; j++) {
            float2 pv = unpack2(prev_s[j]);
            float2 pe0 = unpack2(pe_s[0 * 32 + j]);
            float2 pe1 = unpack2(pe_s[1 * 32 + j]);
            float2 pe2 = unpack2(pe_s[2 * 32 + j]);
            float2 pe3 = unpack2(pe_s[3 * 32 + j]);
            float2 pe4 = unpack2(pe_s[4 * 32 + j]);
            {
                float tix = pw0[0] * pe0.x + pw0[1] * pe1.x + pw0[2] * pe2.x
                          + pw0[3] * pe3.x + pw0[4] * pe4.x;
                float tiy = pw0[0] * pe0.y + pw0[1] * pe1.y + pw0[2] * pe2.y
                          + pw0[3] * pe3.y + pw0[4] * pe4.y;
                float2 t = unpack2(th0[j]);
                float dx = t.x - tix, dy = t.y - tiy;
                str0 += dx * dx + dy * dy;
                nth0 += t.x * t.x + t.y * t.y;
                nti0 += tix * tix + tiy * tiy;
                rd0  += t.x * tix + t.y * tiy;
                float px = tix - pv.x, py = tiy - pv.y;
                f20 += px * px + py * py;
            }
            {
                float tix = pw1[0] * pe0.x + pw1[1] * pe1.x + pw1[2] * pe2.x
                          + pw1[3] * pe3.x + pw1[4] * pe4.x;
                float tiy = pw1[0] * pe0.y + pw1[1] * pe1.y + pw1[2] * pe2.y
                          + pw1[3] * pe3.y + pw1[4] * pe4.y;
                float2 t = unpack2(th1[j]);
                float dx = t.x - tix, dy = t.y - tiy;
                str1 += dx * dx + dy * dy;
                nth1 += t.x * t.x + t.y * t.y;
                nti1 += tix * tix + tiy * tiy;
                rd1  += t.x * tix + t.y * tiy;
                float px = tix - pv.x, py = tiy - pv.y;
                f21 += px * px + py * py;
            }
        }
        {
            float it0 = __fdividef(1.f, sqrtf(nth0) + EPSV);
            float ii0 = __fdividef(1.f, sqrtf(nti0) + EPSV);
            out_rs[r0] = __fdividef(rd0 * it0 * ii0,
                                    fmaxf(sqrtf(nth0) * it0 * sqrtf(nti0) * ii0, EPSV));
            float fr0 = sqrtf(f20);
            out_om[r0] = ftanh(fr0 * fwv + fbv) * (1.0f + 0.1f * __sinf(fr0));
            float it1 = __fdividef(1.f, sqrtf(nth1) + EPSV);
            float ii1 = __fdividef(1.f, sqrtf(nti1) + EPSV);
            out_rs[r1] = __fdividef(rd1 * it1 * ii1,
                                    fmaxf(sqrtf(nth1) * it1 * sqrtf(nti1) * ii1, EPSV));
            float fr1 = sqrtf(f21);
            out_om[r1] = ftanh(fr1 * fwv + fbv) * (1.0f + 0.1f * __sinf(fr1));
        }
        stress_total = str0 + str1;
    }

    float ws = wsum(stress_total);
    if (lane == 0) s_part[wrp] = ws;
    __syncthreads();
    if (tid == 0) {
        g_part[blockIdx.x] = (s_part[0] + s_part[1]) + (s_part[2] + s_part[3]);
    }
}

// ---------------- kB2a: emotion MLP -> out_e = relu(..) + 0.001*stress ----------------
#define B2A_W1  0        // 4096 ull
#define B2A_W2  8192     // 4096 ull
#define B2A_B1  16384    // 128
#define B2A_B2  16512    // 64
#define B2A_STC 16576    // 1
#define SMEM_B2A_BYTES (16580 * 4)

__global__ __launch_bounds__(128, 3)
void kB2a(const float* __restrict__ theta,
          const float* __restrict__ emo_w1, const float* __restrict__ emo_b1,
          const float* __restrict__ emo_w2, const float* __restrict__ emo_b2,
          float* __restrict__ out) {
    extern __shared__ float smem[];
    const int tid = threadIdx.x, lane = tid & 31, wrp = tid >> 5;
    ull* w1i = (ull*)(smem + B2A_W1);
    ull* w2i = (ull*)(smem + B2A_W2);
    float* s_b1 = smem + B2A_B1;
    float* s_b2 = smem + B2A_B2;
    float* s_stc = smem + B2A_STC;

    for (int idx = tid; idx < 4096; idx += 128) {
        int oi = idx & 7, j = (idx >> 3) & 31, og = idx >> 8;
        int o = og * 8 + oi;
        w1i[idx] = pack2(emo_w1[o * 64 + j], emo_w1[o * 64 + j + 32]);
    }
    for (int idx = tid; idx < 4096; idx += 128) {
        int di = idx & 31, kh = idx >> 5;
        w2i[idx] = pack2(emo_w2[di * 128 + kh], emo_w2[(di + 32) * 128 + kh]);
    }
    if (tid < 128) s_b1[tid] = emo_b1[tid];
    if (tid < 64) s_b2[tid] = emo_b2[tid];
    if (tid == 0) {
        float s = 0.f;
        for (int b = 0; b < NPART; b++) s += g_part[b];
        s_stc[0] = 0.001f * s;
    }
    __syncthreads();
    const float stc = s_stc[0];

    float* out_e = out + (size_t)3 * B_N * 64;

#pragma unroll 1
    for (int u = blockIdx.x * 4 + wrp; u < 2048; u += 444 * 4) {
        const int r = u * 32 + lane;
        const size_t ro = (size_t)r * 64;

        ull th_p[32];
        load_row_pairs(theta + ro, th_p);

        ull e_acc[32];
#pragma unroll
        for (int di = 0; di < 32; di++) e_acc[di] = pack2(s_b2[di], s_b2[di + 32]);
#pragma unroll 1
        for (int og = 0; og < 16; og++) {
            const ulonglong2* w1v = (const ulonglong2*)(w1i + og * 256);
            ull a0 = 0, a1 = 0, a2 = 0, a3 = 0, a4 = 0, a5 = 0, a6 = 0, a7 = 0;
#pragma unroll
            for (int j = 0; j < 32; j++) {
                ulonglong2 p0 = w1v[j * 4 + 0], p1 = w1v[j * 4 + 1];
                ulonglong2 p2 = w1v[j * 4 + 2], p3 = w1v[j * 4 + 3];
                ull t = th_p[j];
                fma2(a0, p0.x, t); fma2(a1, p0.y, t);
                fma2(a2, p1.x, t); fma2(a3, p1.y, t);
                fma2(a4, p2.x, t); fma2(a5, p2.y, t);
                fma2(a6, p3.x, t); fma2(a7, p3.y, t);
            }
            float t8[8];
            t8[0] = ftanh(hadd2(a0) + s_b1[og * 8 + 0]);
            t8[1] = ftanh(hadd2(a1) + s_b1[og * 8 + 1]);
            t8[2] = ftanh(hadd2(a2) + s_b1[og * 8 + 2]);
            t8[3] = ftanh(hadd2(a3) + s_b1[og * 8 + 3]);
            t8[4] = ftanh(hadd2(a4) + s_b1[og * 8 + 4]);
            t8[5] = ftanh(hadd2(a5) + s_b1[og * 8 + 5]);
            t8[6] = ftanh(hadd2(a6) + s_b1[og * 8 + 6]);
            t8[7] = ftanh(hadd2(a7) + s_b1[og * 8 + 7]);
#pragma unroll
            for (int k = 0; k < 8; k++) {
                ull tt = pack2(t8[k], t8[k]);
                const ulonglong2* w2v = (const ulonglong2*)(w2i + (og * 8 + k) * 32);
#pragma unroll
                for (int di2 = 0; di2 < 16; di2++) {
                    ulonglong2 q = w2v[di2];
                    fma2(e_acc[di2 * 2 + 0], q.x, tt);
                    fma2(e_acc[di2 * 2 + 1], q.y, tt);
                }
            }
        }
        float4* ep = (float4*)(out_e + ro);
#pragma unroll
        for (int k = 0; k < 8; k++) {
            float2 v0 = unpack2(e_acc[k * 4 + 0]);
            float2 v1 = unpack2(e_acc[k * 4 + 1]);
            float2 v2 = unpack2(e_acc[k * 4 + 2]);
            float2 v3 = unpack2(e_acc[k * 4 + 3]);
            ep[k]     = make_float4(fmaxf(v0.x, 0.f) + stc, fmaxf(v1.x, 0.f) + stc,
                                    fmaxf(v2.x, 0.f) + stc, fmaxf(v3.x, 0.f) + stc);
            ep[8 + k] = make_float4(fmaxf(v0.y, 0.f) + stc, fmaxf(v1.y, 0.f) + stc,
                                    fmaxf(v2.y, 0.f) + stc, fmaxf(v3.y, 0.f) + stc);
        }
    }
}

// ---------------- kDF: fused GRU, half-warp K-split, split epilogue ----------------
#define DF_W   0         // 12288 ull = 24576 f
#define DF_CST 24576     // 192
#define DF_RES 24768     // 192
#define DF_OM  24960     // 192
#define DF_BHH 25152     // 192
#define SMEM_DF_BYTES (25344 * 4)

__global__ __launch_bounds__(256, 2)
void kDF(const float* __restrict__ wih_f, const float* __restrict__ whh_f,
         const float* __restrict__ bhh_f,
         const float* __restrict__ wih_r, const float* __restrict__ whh_r,
         const float* __restrict__ bhh_r,
         const float* __restrict__ h_prev, const float* __restrict__ theta,
         float* __restrict__ out) {
    extern __shared__ float smem[];
    const int tid = threadIdx.x, lane = tid & 31, wrp = tid >> 5;
    const int dir = blockIdx.x & 1, ublk = blockIdx.x >> 1;
    const int kh = lane >> 4, ln = lane & 15;

    ull* wEH = (ull*)(smem + DF_W);
    float* scst = smem + DF_CST;
    float* sres = smem + DF_RES;
    float* som  = smem + DF_OM;
    float* sbhh = smem + DF_BHH;

    const float* wih = dir ? wih_r : wih_f;
    const float* whh = dir ? whh_r : whh_f;
    const float* bhh = dir ? bhh_r : bhh_f;

    for (int idx = tid; idx < 12288; idx += 256) {
        int s = idx % 12, t = idx / 12;
        int j = t & 31, d = t >> 5;
        int g = (s >= 6) ? s - 6 : s;
        int o = (g >> 1) * 64 + (g & 1) * 32 + d;
        wEH[idx] = (s < 6) ? pack2(wih[o * 130 + 64 + j], wih[o * 130 + 96 + j])
                           : pack2(whh[o * 64 + j], whh[o * 64 + 32 + j]);
    }
    for (int i = tid; i < 192; i += 256) {
        scst[i] = dir ? g_const_r[i] : g_const_f[i];
        sres[i] = wih[i * 130 + 128];
        som[i]  = wih[i * 130 + 129];
        sbhh[i] = bhh[i];
    }
    __syncthreads();

    const float* hpd = h_prev + (size_t)dir * B_N * 64;
    const float* out_e = out + (size_t)3 * B_N * 64;
    const float* out_rs = out + (size_t)4 * B_N * 64;
    const float* out_om = out_rs + B_N;
    float* out_t = out;
    float* out_h = out + (size_t)(1 + dir) * B_N * 64;

#pragma unroll 1
    for (int u = ublk; u < 512; u += 296) {
        const int r = u * 128 + wrp * 16 + ln;
        const size_t ro = (size_t)r * 64;

        ull e_p[16], h_p[16];
        load_half_pairs(out_e + ro, kh, e_p);
        load_half_pairs(hpd + ro, kh, h_p);
        const float res = out_rs[r], om = out_om[r];

#pragma unroll 1
        for (int d = 0; d < 32; d++) {
            const ulonglong2* w = (const ulonglong2*)(wEH + (size_t)(d * 32 + kh * 16) * 12);
            ull A0 = 0, A1 = 0, A2 = 0, A3 = 0, A4 = 0, A5 = 0;
            ull B0 = 0, B1 = 0, B2 = 0, B3 = 0, B4 = 0, B5 = 0;
#pragma unroll
            for (int jj = 0; jj < 16; jj++) {
                ulonglong2 q0 = w[jj * 6 + 0], q1 = w[jj * 6 + 1], q2 = w[jj * 6 + 2];
                ulonglong2 q3 = w[jj * 6 + 3], q4 = w[jj * 6 + 4], q5 = w[jj * 6 + 5];
                ull e = e_p[jj], h = h_p[jj];
                fma2(A0, q0.x, e); fma2(A1, q0.y, e);
                fma2(A2, q1.x, e); fma2(A3, q1.y, e);
                fma2(A4, q2.x, e); fma2(A5, q2.y, e);
                fma2(B0, q3.x, h); fma2(B1, q3.y, h);
                fma2(B2, q4.x, h); fma2(B3, q4.y, h);
                fma2(B4, q5.x, h); fma2(B5, q5.y, h);
            }
            // cross-half combine — after shfl BOTH halves hold complete sums
            float a0 = hadd2(A0); a0 += __shfl_xor_sync(0xffffffffu, a0, 16);
            float a1 = hadd2(A1); a1 += __shfl_xor_sync(0xffffffffu, a1, 16);
            float a2 = hadd2(A2); a2 += __shfl_xor_sync(0xffffffffu, a2, 16);
            float a3 = hadd2(A3); a3 += __shfl_xor_sync(0xffffffffu, a3, 16);
            float a4 = hadd2(A4); a4 += __shfl_xor_sync(0xffffffffu, a4, 16);
            float a5 = hadd2(A5); a5 += __shfl_xor_sync(0xffffffffu, a5, 16);
            float b0 = hadd2(B0); b0 += __shfl_xor_sync(0xffffffffu, b0, 16);
            float b1 = hadd2(B1); b1 += __shfl_xor_sync(0xffffffffu, b1, 16);
            float b2 = hadd2(B2); b2 += __shfl_xor_sync(0xffffffffu, b2, 16);
            float b3 = hadd2(B3); b3 += __shfl_xor_sync(0xffffffffu, b3, 16);
            float b4 = hadd2(B4); b4 += __shfl_xor_sync(0xffffffffu, b4, 16);
            float b5 = hadd2(B5); b5 += __shfl_xor_sync(0xffffffffu, b5, 16);

            // split epilogue: kh=0 -> output d (lo), kh=1 -> output d+32 (hi)
            const int hb = kh << 5;
            float sa_r = kh ? a1 : a0;
            float sa_z = kh ? a3 : a2;
            float sa_n = kh ? a5 : a4;
            float sb_r = kh ? b1 : b0;
            float sb_z = kh ? b3 : b2;
            float sb_n = kh ? b5 : b4;
            const int i_r = hb + d, i_z = 64 + hb + d, i_n = 128 + hb + d;
            float ir  = sa_r + scst[i_r] + res * sres[i_r] + om * som[i_r];
            float iz  = sa_z + scst[i_z] + res * sres[i_z] + om * som[i_z];
            float inx = sa_n + scst[i_n] + res * sres[i_n] + om * som[i_n];
            float hr = sb_r + sbhh[i_r];
            float hz = sb_z + sbhh[i_z];
            float hn = sb_n + sbhh[i_n];
            float hv = hpd[ro + hb + d];
            float rg = sigm(ir + hr), zg = sigm(iz + hz);
            float ng = ftanh(inx + rg * hn);
            float o = (1.f - zg) * ng + zg * hv;
            out_h[ro + hb + d] = o;
            if (dir == 0) {
                out_t[ro + hb + d] = 0.3f * theta[ro + hb + d] + 0.7f * o;
            }
        }
    }
}

extern "C" void kernel_launch(void* const* d_in, const int* in_sizes, int n_in,
                              void* d_out, int out_size) {
    const float* theta   = (const float*)d_in[0];
    const float* context = (const float*)d_in[1];
    const float* h_prev  = (const float*)d_in[2];
    const float* memory  = (const float*)d_in[3];
    const float* tw      = (const float*)d_in[4];
    const float* ipw     = (const float*)d_in[5];
    const float* ipb     = (const float*)d_in[6];
    const float* ow      = (const float*)d_in[7];
    const float* ob      = (const float*)d_in[8];
    const float* emo_w1  = (const float*)d_in[9];
    const float* emo_b1  = (const float*)d_in[10];
    const float* emo_w2  = (const float*)d_in[11];
    const float* emo_b2  = (const float*)d_in[12];
    const float* pe      = (const float*)d_in[13];
    const float* ctx_w   = (const float*)d_in[14];
    const float* ctx_b   = (const float*)d_in[15];
    const float* ideal_w = (const float*)d_in[16];
    const float* ideal_b = (const float*)d_in[17];
    const float* wih_f   = (const float*)d_in[18];
    const float* whh_f   = (const float*)d_in[19];
    const float* bih_f   = (const float*)d_in[20];
    const float* bhh_f   = (const float*)d_in[21];
    const float* wih_r   = (const float*)d_in[22];
    const float* whh_r   = (const float*)d_in[23];
    const float* bih_r   = (const float*)d_in[24];
    const float* bhh_r   = (const float*)d_in[25];
    const float* freq_w  = (const float*)d_in[26];
    const float* freq_b  = (const float*)d_in[27];
    const float* prev_i  = (const float*)d_in[28];
    float* out = (float*)d_out;

    static bool attr_set = false;
    if (!attr_set) {
        cudaFuncSetAttribute(kB1, cudaFuncAttributeMaxDynamicSharedMemorySize, SMEM_B1_BYTES);
        cudaFuncSetAttribute(kB2a, cudaFuncAttributeMaxDynamicSharedMemorySize, SMEM_B2A_BYTES);
        cudaFuncSetAttribute(kDF, cudaFuncAttributeMaxDynamicSharedMemorySize, SMEM_DF_BYTES);
        attr_set = true;
    }

    kA<<<1, 192>>>(memory, tw, ipw, ipb, ow, ob, wih_f, bih_f, wih_r, bih_r);
    kM<<<15, 128>>>(ideal_w, ideal_b, ctx_w, ctx_b);
    kB1<<<296, 128, SMEM_B1_BYTES>>>(theta, context, ideal_w,
                                     pe, prev_i, freq_w, freq_b, out);
    kB2a<<<444, 128, SMEM_B2A_BYTES>>>(theta, emo_w1, emo_b1, emo_w2, emo_b2, out);
    kDF<<<592, 256, SMEM_DF_BYTES>>>(wih_f, whh_f, bhh_f, wih_r, whh_r, bhh_r,
                                     h_prev, theta, out);
}